// round 2
// baseline (speedup 1.0000x reference)
#include <cuda_runtime.h>
#include <cstdint>

#define NB 4
#define NN 1024
#define AIN 8
#define AOUT 16
#define XIN 64
#define XOUT 64

// ---------------- scratch (device globals; no allocation) ----------------
__device__ float g_moc[NB*NN*AIN];
__device__ float g_dp [NB*NN*AIN];
__device__ float g_mdp[NB*AIN];
__device__ float g_mall[NB*AIN];
__device__ float g_mX [NB*XIN];
__device__ float g_C  [NB*AOUT];
__device__ float g_R  [NB*NN*AOUT];
__device__ float g_X1t[NB*NN*XOUT];
__device__ float g_X2t[NB*NN*XOUT];
__device__ float g_T  [NB*AOUT*XOUT];
__device__ float g_K  [NB*XOUT];
__device__ float g_OWH[AIN*XOUT*XOUT];
__device__ float g_H  [NB*NN*AIN*XOUT];   // per-node H (4096 x 512)

#define FMA2(d,a,b) asm("fma.rn.f32x2 %0, %1, %2, %0;" : "+l"(d) : "l"(a), "l"(b))
#define PACK2(d,x)  asm("mov.b64 %0, {%1, %1};" : "=l"(d) : "f"(x))
#define UNPACK2(lo,hi,d) asm("mov.b64 {%0, %1}, %2;" : "=f"(lo), "=f"(hi) : "l"(d))

// ---------------- K1: row reductions over A -> moc, dp -------------------
__global__ void __launch_bounds__(256) k_reduce(const float* __restrict__ A)
{
    int bx = blockIdx.x;            // bx = n*1024 + i
    int n = bx >> 10, i = bx & 1023;
    int w = threadIdx.x >> 5, l = threadIdx.x & 31;   // warp w handles channel a=w
    size_t row = ((size_t)(n*AIN + w) << 20) + ((size_t)i << 10);
    const float4* p = (const float4*)(A + row);
    float s = 0.f;
#pragma unroll
    for (int k = 0; k < 8; ++k) {
        float4 v = p[k*32 + l];
        s += v.x + v.y + v.z + v.w;
    }
#pragma unroll
    for (int o = 16; o; o >>= 1) s += __shfl_xor_sync(0xffffffffu, s, o);
    if (l == 0) {
        g_moc[(bx << 3) + w] = s * (1.f/1024.f);
        g_dp [(bx << 3) + w] = A[row + i];
    }
}

// ---------------- K2a: per-n means, C, and OWH ---------------------------
__global__ void __launch_bounds__(256) k_pre_n(
    const float* __restrict__ X,  const float* __restrict__ AW1,
    const float* __restrict__ AW2, const float* __restrict__ AW4,
    const float* __restrict__ AW7, const float* __restrict__ Abias,
    const float* __restrict__ OW)
{
    int n = blockIdx.x, tid = threadIdx.x;
    __shared__ float smx[XIN], smdp[AIN], smal[AIN];
    if (tid < 64) {
        float s = 0.f;
        const float* xp = X + ((size_t)n << 10) * XIN + tid;
        for (int i = 0; i < NN; ++i) s += xp[(size_t)i * XIN];
        smx[tid] = s * (1.f/1024.f);
        g_mX[n*XIN + tid] = smx[tid];
    } else if (tid < 72) {
        int a = tid - 64; float s = 0.f;
        const float* dpp = g_dp + ((size_t)n << 10) * AIN + a;
        for (int i = 0; i < NN; ++i) s += dpp[i*AIN];
        smdp[a] = s * (1.f/1024.f); g_mdp[n*AIN + a] = smdp[a];
    } else if (tid < 80) {
        int a = tid - 72; float s = 0.f;
        const float* mp = g_moc + ((size_t)n << 10) * AIN + a;
        for (int i = 0; i < NN; ++i) s += mp[i*AIN];
        smal[a] = s * (1.f/1024.f); g_mall[n*AIN + a] = smal[a];
    }
    __syncthreads();
    if (tid < AOUT) {
        int s16 = tid; float c = Abias[s16];
        for (int a = 0; a < AIN; ++a)
            c = fmaf(smal[a], AW2[a*AOUT+s16], fmaf(smdp[a], AW4[a*AOUT+s16], c));
        for (int k = 0; k < XIN; ++k) c = fmaf(smx[k], AW7[k*AOUT+s16], c);
        g_C[n*AOUT + s16] = c;
    }
    // OWH[a,u,t] = sum_s W1[a,s] * OW[(s*64+u)*64+t]; block n does a = 2n, 2n+1
    for (int a2 = 0; a2 < 2; ++a2) {
        int a = 2*n + a2;
        for (int idx = tid; idx < 4096; idx += 256) {
            int u = idx >> 6, t = idx & 63;
            float s = 0.f;
            for (int ss = 0; ss < AOUT; ++ss)
                s = fmaf(AW1[a*AOUT+ss], OW[((ss<<6)+u)*64 + t], s);
            g_OWH[((a<<6)+u)*64 + t] = s;
        }
    }
}

// ---------------- K2b: per-node R, X1t, X2t ------------------------------
__global__ void __launch_bounds__(64) k_node(
    const float* __restrict__ X,
    const float* __restrict__ AW3, const float* __restrict__ AW5, const float* __restrict__ AW6,
    const float* __restrict__ X1W1, const float* __restrict__ X1W2, const float* __restrict__ X1W3,
    const float* __restrict__ X1W4, const float* __restrict__ X1W5, const float* __restrict__ X1W6,
    const float* __restrict__ X1b,
    const float* __restrict__ X2W1, const float* __restrict__ X2W2, const float* __restrict__ X2W3,
    const float* __restrict__ X2W4, const float* __restrict__ X2W5, const float* __restrict__ X2W6,
    const float* __restrict__ X2b)
{
    int bx = blockIdx.x;            // node = n*1024+i
    int n = bx >> 10;
    int t = threadIdx.x;
    __shared__ float sx[XIN], smx[XIN], smoc[AIN], sdp[AIN], smdp[AIN], smal[AIN];
    sx[t]  = X[(size_t)bx * XIN + t];
    smx[t] = g_mX[n*XIN + t];
    if (t < AIN) {
        smoc[t] = g_moc[bx*AIN + t];
        sdp [t] = g_dp [bx*AIN + t];
        smdp[t] = g_mdp[n*AIN + t];
        smal[t] = g_mall[n*AIN + t];
    }
    __syncthreads();
    float x1 = X1b[t], x2 = X2b[t];
    for (int k = 0; k < XIN; ++k) {
        x1 = fmaf(sx[k],  X1W1[k*64+t], x1);  x2 = fmaf(sx[k],  X2W1[k*64+t], x2);
        x1 = fmaf(smx[k], X1W2[k*64+t], x1);  x2 = fmaf(smx[k], X2W2[k*64+t], x2);
    }
#pragma unroll
    for (int a = 0; a < AIN; ++a) {
        x1 = fmaf(smoc[a], X1W3[a*64+t], x1); x2 = fmaf(smoc[a], X2W3[a*64+t], x2);
        x1 = fmaf(sdp[a],  X1W4[a*64+t], x1); x2 = fmaf(sdp[a],  X2W4[a*64+t], x2);
        x1 = fmaf(smdp[a], X1W5[a*64+t], x1); x2 = fmaf(smdp[a], X2W5[a*64+t], x2);
        x1 = fmaf(smal[a], X1W6[a*64+t], x1); x2 = fmaf(smal[a], X2W6[a*64+t], x2);
    }
    g_X1t[(size_t)bx*XOUT + t] = x1;
    g_X2t[(size_t)bx*XOUT + t] = x2;
    if (t < AOUT) {
        float r = 0.f;
#pragma unroll
        for (int a = 0; a < AIN; ++a) {
            r = fmaf(smoc[a], AW3[a*AOUT+t], r);
            r = fmaf(sdp[a],  AW5[a*AOUT+t], r);
        }
        for (int k = 0; k < XIN; ++k) r = fmaf(sx[k], AW6[k*AOUT+t], r);
        g_R[(size_t)bx*AOUT + t] = r;
    }
}

// ---------------- K2c: per-n SX2, Q, T, K ---------------------------------
__global__ void __launch_bounds__(1024) k_pre2(
    const float* __restrict__ OW, const float* __restrict__ outb)
{
    int n = blockIdx.x, tid = threadIdx.x;
    __shared__ float sx2[XOUT];
    __shared__ float sq[AOUT*XOUT];
    __shared__ float st_[AOUT*XOUT];
    if (tid < 64) {
        float s = 0.f;
        const float* p = g_X2t + ((size_t)n << 10) * XOUT + tid;
        for (int j = 0; j < NN; ++j) s += p[(size_t)j * XOUT];
        sx2[tid] = s;
    }
    {   // Q[s,t] = sum_j R[n,j,s] * X2t[n,j,t]
        int s16 = tid >> 6, t = tid & 63;
        const float* rp = g_R   + ((size_t)n << 10) * AOUT;
        const float* xp = g_X2t + ((size_t)n << 10) * XOUT;
        float q = 0.f;
        for (int j = 0; j < NN; ++j)
            q = fmaf(rp[j*AOUT + s16], xp[(size_t)j*XOUT + t], q);
        sq[tid] = q;
    }
    __syncthreads();
    {   // T[s,t] = sum_u SX2[u] * OW[(s*64+u)*64+t]
        int s16 = tid >> 6, t = tid & 63;
        float v = 0.f;
        for (int u = 0; u < 64; ++u)
            v = fmaf(sx2[u], OW[((s16<<6)+u)*64 + t], v);
        st_[tid] = v;
        g_T[n*1024 + tid] = v;
    }
    __syncthreads();
    if (tid < 64) {
        int t = tid;
        float qo = 0.f;
        for (int idx = 0; idx < 1024; ++idx)
            qo = fmaf(sq[idx], OW[idx*64 + t], qo);
        float ct = 0.f;
#pragma unroll
        for (int s16 = 0; s16 < AOUT; ++s16)
            ct = fmaf(g_C[n*AOUT + s16], st_[(s16<<6) + t], ct);
        g_K[n*XOUT + t] = (ct + qo) * (1.f/1024.f) + outb[t];
    }
}

// ---------------- K3: main — At construction + H GEMM --------------------
__global__ void __launch_bounds__(256) k_main(
    const float* __restrict__ A, const float* __restrict__ AW1,
    float* __restrict__ outAt)
{
    int bx = blockIdx.x;                 // n*1024 + i
    int n = bx >> 10, i = bx & 1023;
    int tid = threadIdx.x, w = tid >> 5, l = tid & 31;

    __shared__ __align__(16) float sA[AIN][1028];   // padded: (4a+j)%32 distinct
    __shared__ __align__(16) float sW1[AIN][AOUT];
    __shared__ __align__(16) float sC16[AOUT];
    __shared__ float sRi[AOUT];

    // stage 8 A rows (coalesced float4)
    {
        const float4* A4 = (const float4*)A;
#pragma unroll
        for (int a = 0; a < AIN; ++a) {
            size_t ridx = ((size_t)(n*AIN + a) << 20) + ((size_t)i << 10);
            float4 v = A4[(ridx >> 2) + tid];
            *((float4*)&sA[a][tid*4]) = v;
        }
    }
    if (tid < 128) sW1[tid >> 4][tid & 15] = AW1[tid];
    if (tid < AOUT) {
        float r = g_R[(size_t)bx*AOUT + tid];
        sRi[tid] = r;
        sC16[tid] = r + g_C[n*AOUT + tid];
    }
    __syncthreads();

    // ---- Phase A: At[n,i,j,s] -> out[(n*16+s), i, j]  (f32x2 G) ----
    {
        const unsigned long long* cpair = (const unsigned long long*)sC16;
#pragma unroll 1
        for (int step = 0; step < 4; ++step) {
            int j = (step << 8) + tid;
            unsigned long long acc[8];
#pragma unroll
            for (int p = 0; p < 8; ++p) acc[p] = cpair[p];
#pragma unroll
            for (int a = 0; a < AIN; ++a) {
                float av = sA[a][j];
                unsigned long long bA; PACK2(bA, av);
                const unsigned long long* wp = (const unsigned long long*)sW1[a];
#pragma unroll
                for (int p = 0; p < 8; ++p) FMA2(acc[p], bA, wp[p]);
            }
            float v[16];
#pragma unroll
            for (int p = 0; p < 8; ++p) UNPACK2(v[2*p], v[2*p+1], acc[p]);
            const float4* rj = (const float4*)(g_R + (((size_t)((n<<10) | j)) << 4));
#pragma unroll
            for (int q = 0; q < 4; ++q) {
                float4 r = rj[q];
                v[4*q]   += r.x; v[4*q+1] += r.y; v[4*q+2] += r.z; v[4*q+3] += r.w;
            }
            size_t ob0 = ((size_t)(n*AOUT) << 20) + ((size_t)i << 10) + j;
#pragma unroll
            for (int s = 0; s < AOUT; ++s)
                outAt[ob0 + ((size_t)s << 20)] = v[s];
        }
    }

    // ---- Phase H: H[a,t] = sum_j sA[a][j] * X2t[n,j,t]  (warp-split j) ----
    unsigned long long h[8];
#pragma unroll
    for (int p = 0; p < 8; ++p) h[p] = 0ull;
    {
        int a = l >> 2, t0 = (l & 3) << 4;
        const float* x2b = g_X2t + ((size_t)n << 10) * XOUT + t0;
        int j0 = w << 7;
#pragma unroll 2
        for (int jj = 0; jj < 128; ++jj) {
            int j = j0 + jj;
            float av = sA[a][j];
            unsigned long long bA; PACK2(bA, av);
            const float* xr = x2b + ((size_t)j << 6);
            unsigned long long x0,x1,x2,x3,x4,x5,x6,x7;
            asm("ld.global.v2.b64 {%0,%1},[%2];" : "=l"(x0),"=l"(x1) : "l"(xr));
            asm("ld.global.v2.b64 {%0,%1},[%2];" : "=l"(x2),"=l"(x3) : "l"(xr+4));
            asm("ld.global.v2.b64 {%0,%1},[%2];" : "=l"(x4),"=l"(x5) : "l"(xr+8));
            asm("ld.global.v2.b64 {%0,%1},[%2];" : "=l"(x6),"=l"(x7) : "l"(xr+12));
            FMA2(h[0],bA,x0); FMA2(h[1],bA,x1); FMA2(h[2],bA,x2); FMA2(h[3],bA,x3);
            FMA2(h[4],bA,x4); FMA2(h[5],bA,x5); FMA2(h[6],bA,x6); FMA2(h[7],bA,x7);
        }
    }
    __syncthreads();
    // dump per-warp partials into sA storage, reduce across warps -> g_H
    {
        float* sd = &sA[0][0];
        int a = l >> 2, t0 = (l & 3) << 4;
#pragma unroll
        for (int p = 0; p < 8; ++p) {
            float lo, hi; UNPACK2(lo, hi, h[p]);
            sd[(w<<9) + (a<<6) + t0 + 2*p]     = lo;
            sd[(w<<9) + (a<<6) + t0 + 2*p + 1] = hi;
        }
        __syncthreads();
        for (int idx = tid; idx < 512; idx += 256) {
            float s = 0.f;
#pragma unroll
            for (int w2 = 0; w2 < 8; ++w2) s += sd[(w2<<9) + idx];
            g_H[((size_t)bx << 9) + idx] = s;
        }
    }
}

// ---------------- K4: out = H*OWH/n + R*T/n + K + X1t ---------------------
__global__ void __launch_bounds__(256) k_out(float* __restrict__ out2)
{
    int bx = blockIdx.x;                 // 256 blocks x 16 nodes
    int n = bx >> 6;
    int tid = threadIdx.x;
    __shared__ float sH[16][514];
    {
        const float4* hp = (const float4*)(g_H + ((size_t)bx << 13));
#pragma unroll
        for (int k = 0; k < 8; ++k) {
            int idx = (k << 8) + tid;          // 2048 float4 total
            float4 v = hp[idx];
            int row = idx >> 7, col = (idx & 127) << 2;
            sH[row][col] = v.x; sH[row][col+1] = v.y;
            sH[row][col+2] = v.z; sH[row][col+3] = v.w;
        }
    }
    __syncthreads();
    int r = tid >> 4, q = tid & 15, t0 = q << 2;
    int node = (bx << 4) + r;
    float a0=0.f, a1=0.f, a2=0.f, a3=0.f;
    for (int au = 0; au < 512; ++au) {
        float hv = sH[r][au];
        float4 wv = *(const float4*)(g_OWH + (au << 6) + t0);
        a0 = fmaf(hv, wv.x, a0); a1 = fmaf(hv, wv.y, a1);
        a2 = fmaf(hv, wv.z, a2); a3 = fmaf(hv, wv.w, a3);
    }
    const float* Tn = g_T + (n << 10);
    const float* Rn = g_R + ((size_t)node << 4);
#pragma unroll
    for (int s = 0; s < AOUT; ++s) {
        float rv = Rn[s];
        float4 tv = *(const float4*)(Tn + (s << 6) + t0);
        a0 = fmaf(rv, tv.x, a0); a1 = fmaf(rv, tv.y, a1);
        a2 = fmaf(rv, tv.z, a2); a3 = fmaf(rv, tv.w, a3);
    }
    const float sc = 1.f/1024.f;
    size_t ob = ((size_t)node << 6) + t0;
    float4 kv  = *(const float4*)(g_K + (n << 6) + t0);
    float4 x1v = *(const float4*)(g_X1t + ob);
    float4 o;
    o.x = a0*sc + kv.x + x1v.x;  o.y = a1*sc + kv.y + x1v.y;
    o.z = a2*sc + kv.z + x1v.z;  o.w = a3*sc + kv.w + x1v.w;
    *(float4*)(out2 + ob) = o;
}

// ---------------- launch ---------------------------------------------------
extern "C" void kernel_launch(void* const* d_in, const int* in_sizes, int n_in,
                              void* d_out, int out_size)
{
    const float* A     = (const float*)d_in[0];
    const float* X     = (const float*)d_in[1];
    const float* AW1   = (const float*)d_in[2];
    const float* AW2   = (const float*)d_in[3];
    const float* AW3   = (const float*)d_in[4];
    const float* AW4   = (const float*)d_in[5];
    const float* AW5   = (const float*)d_in[6];
    const float* AW6   = (const float*)d_in[7];
    const float* AW7   = (const float*)d_in[8];
    const float* Abias = (const float*)d_in[9];
    const float* X1W1  = (const float*)d_in[10];
    const float* X1W2  = (const float*)d_in[11];
    const float* X1W3  = (const float*)d_in[12];
    const float* X1W4  = (const float*)d_in[13];
    const float* X1W5  = (const float*)d_in[14];
    const float* X1W6  = (const float*)d_in[15];
    const float* X1b   = (const float*)d_in[16];
    const float* X2W1  = (const float*)d_in[17];
    const float* X2W2  = (const float*)d_in[18];
    const float* X2W3  = (const float*)d_in[19];
    const float* X2W4  = (const float*)d_in[20];
    const float* X2W5  = (const float*)d_in[21];
    const float* X2W6  = (const float*)d_in[22];
    const float* X2b   = (const float*)d_in[23];
    const float* OW    = (const float*)d_in[24];
    const float* outb  = (const float*)d_in[25];

    float* outAt = (float*)d_out;
    float* out2  = outAt + (size_t)NB * AOUT * NN * NN;

    k_reduce<<<NB*NN, 256>>>(A);
    k_pre_n <<<NB, 256>>>(X, AW1, AW2, AW4, AW7, Abias, OW);
    k_node  <<<NB*NN, 64>>>(X, AW3, AW5, AW6,
                            X1W1, X1W2, X1W3, X1W4, X1W5, X1W6, X1b,
                            X2W1, X2W2, X2W3, X2W4, X2W5, X2W6, X2b);
    k_pre2  <<<NB, 1024>>>(OW, outb);
    k_main  <<<NB*NN, 256>>>(A, AW1, outAt);
    k_out   <<<NB*NN/16, 256>>>(out2);
}

// round 3
// speedup vs baseline: 1.0927x; 1.0927x over previous
#include <cuda_runtime.h>
#include <cstdint>

#define NB 4
#define NN 1024
#define AIN 8
#define AOUT 16
#define XIN 64
#define XOUT 64

// ---------------- scratch (device globals; no allocation) ----------------
__device__ float g_moc[NB*NN*AIN];
__device__ float g_dp [NB*NN*AIN];
__device__ float g_mdp[NB*AIN];
__device__ float g_mall[NB*AIN];
__device__ float g_mX [NB*XIN];
__device__ float g_C  [NB*AOUT];
__device__ float g_R  [NB*NN*AOUT];
__device__ float g_X1t[NB*NN*XOUT];
__device__ float g_X2t[NB*NN*XOUT];
__device__ float g_T  [NB*AOUT*XOUT];
__device__ float g_K  [NB*XOUT];
__device__ float g_OWH[AIN*XOUT*XOUT];
__device__ float g_H  [NB*NN*AIN*XOUT];        // per-node H (4096 x 512)
__device__ float g_Qpart[NB*16*AOUT*XOUT];     // 64 seg-partials of Q
__device__ float g_SX2part[NB*16*XOUT];        // 64 seg-partials of SX2

#define FMA2(d,a,b) asm("fma.rn.f32x2 %0, %1, %2, %0;" : "+l"(d) : "l"(a), "l"(b))
#define PACK2(d,x)  asm("mov.b64 %0, {%1, %1};" : "=l"(d) : "f"(x))
#define UNPACK2(lo,hi,d) asm("mov.b64 {%0, %1}, %2;" : "=f"(lo), "=f"(hi) : "l"(d))

// ---------------- K1: row reductions over A -> moc, dp -------------------
__global__ void __launch_bounds__(256) k_reduce(const float* __restrict__ A)
{
    int bx = blockIdx.x;            // bx = n*1024 + i
    int n = bx >> 10, i = bx & 1023;
    int w = threadIdx.x >> 5, l = threadIdx.x & 31;   // warp w handles channel a=w
    size_t row = ((size_t)(n*AIN + w) << 20) + ((size_t)i << 10);
    const float4* p = (const float4*)(A + row);
    float s = 0.f;
#pragma unroll
    for (int k = 0; k < 8; ++k) {
        float4 v = p[k*32 + l];
        s += v.x + v.y + v.z + v.w;
    }
#pragma unroll
    for (int o = 16; o; o >>= 1) s += __shfl_xor_sync(0xffffffffu, s, o);
    if (l == 0) {
        g_moc[(bx << 3) + w] = s * (1.f/1024.f);
        g_dp [(bx << 3) + w] = A[row + i];
    }
}

// ---------------- K_owh: OWH[a,u,t] = sum_s W1[a,s]*OW[(s*64+u)*64+t] ----
__global__ void __launch_bounds__(256) k_owh(
    const float* __restrict__ AW1, const float* __restrict__ OW)
{
    int a = blockIdx.x, tid = threadIdx.x;
    __shared__ float sw[AOUT];
    if (tid < AOUT) sw[tid] = AW1[a*AOUT + tid];
    __syncthreads();
    for (int idx = tid; idx < 4096; idx += 256) {
        int u = idx >> 6, t = idx & 63;
        float s = 0.f;
#pragma unroll
        for (int ss = 0; ss < AOUT; ++ss)
            s = fmaf(sw[ss], OW[((ss<<6)+u)*64 + t], s);
        g_OWH[((a<<6)+u)*64 + t] = s;
    }
}

// ---------------- K2a: per-n means + C (grid-parallel within block) ------
__global__ void __launch_bounds__(1024) k_pre_n(
    const float* __restrict__ X,
    const float* __restrict__ AW2, const float* __restrict__ AW4,
    const float* __restrict__ AW7, const float* __restrict__ Abias)
{
    int n = blockIdx.x, tid = threadIdx.x;
    __shared__ float spart[16][64];     // X col partials
    __shared__ float sdpp[128][8];
    __shared__ float salp[128][8];
    __shared__ float smx[XIN], smdp[AIN], smal[AIN];

    {   // X: 16 segs x 64 cols; seg covers 64 rows
        int col = tid & 63, seg = tid >> 6;
        const float* xp = X + ((size_t)n << 16) + (size_t)(seg << 6) * XIN + col;
        float s = 0.f;
#pragma unroll 4
        for (int r = 0; r < 64; ++r) s += xp[(size_t)r * XIN];
        spart[seg][col] = s;
    }
    {   // dp/moc: 128 segs x 8 ch; seg covers 8 rows
        int a = tid & 7, seg = tid >> 3;
        const float* dpp = g_dp  + (n << 13) + (seg << 6) + a;
        const float* mcp = g_moc + (n << 13) + (seg << 6) + a;
        float s1 = 0.f, s2 = 0.f;
#pragma unroll
        for (int r = 0; r < 8; ++r) { s1 += dpp[r*8]; s2 += mcp[r*8]; }
        sdpp[seg][a] = s1; salp[seg][a] = s2;
    }
    __syncthreads();
    if (tid < 64) {
        float s = 0.f;
#pragma unroll
        for (int k = 0; k < 16; ++k) s += spart[k][tid];
        smx[tid] = s * (1.f/1024.f);
        g_mX[n*XIN + tid] = smx[tid];
    } else if (tid >= 64 && tid < 72) {
        int a = tid - 64; float s = 0.f;
        for (int k = 0; k < 128; ++k) s += sdpp[k][a];
        smdp[a] = s * (1.f/1024.f); g_mdp[n*AIN + a] = smdp[a];
    } else if (tid >= 72 && tid < 80) {
        int a = tid - 72; float s = 0.f;
        for (int k = 0; k < 128; ++k) s += salp[k][a];
        smal[a] = s * (1.f/1024.f); g_mall[n*AIN + a] = smal[a];
    }
    __syncthreads();
    if (tid < AOUT) {
        int s16 = tid; float c = Abias[s16];
#pragma unroll
        for (int a = 0; a < AIN; ++a)
            c = fmaf(smal[a], AW2[a*AOUT+s16], fmaf(smdp[a], AW4[a*AOUT+s16], c));
        for (int k = 0; k < XIN; ++k) c = fmaf(smx[k], AW7[k*AOUT+s16], c);
        g_C[n*AOUT + s16] = c;
    }
}

// ---------------- K2b: per-node R, X1t, X2t ------------------------------
__global__ void __launch_bounds__(64) k_node(
    const float* __restrict__ X,
    const float* __restrict__ AW3, const float* __restrict__ AW5, const float* __restrict__ AW6,
    const float* __restrict__ X1W1, const float* __restrict__ X1W2, const float* __restrict__ X1W3,
    const float* __restrict__ X1W4, const float* __restrict__ X1W5, const float* __restrict__ X1W6,
    const float* __restrict__ X1b,
    const float* __restrict__ X2W1, const float* __restrict__ X2W2, const float* __restrict__ X2W3,
    const float* __restrict__ X2W4, const float* __restrict__ X2W5, const float* __restrict__ X2W6,
    const float* __restrict__ X2b)
{
    int bx = blockIdx.x;            // node = n*1024+i
    int n = bx >> 10;
    int t = threadIdx.x;
    __shared__ float sx[XIN], smx[XIN], smoc[AIN], sdp[AIN], smdp[AIN], smal[AIN];
    sx[t]  = X[(size_t)bx * XIN + t];
    smx[t] = g_mX[n*XIN + t];
    if (t < AIN) {
        smoc[t] = g_moc[bx*AIN + t];
        sdp [t] = g_dp [bx*AIN + t];
        smdp[t] = g_mdp[n*AIN + t];
        smal[t] = g_mall[n*AIN + t];
    }
    __syncthreads();
    float x1 = X1b[t], x2 = X2b[t];
    for (int k = 0; k < XIN; ++k) {
        x1 = fmaf(sx[k],  X1W1[k*64+t], x1);  x2 = fmaf(sx[k],  X2W1[k*64+t], x2);
        x1 = fmaf(smx[k], X1W2[k*64+t], x1);  x2 = fmaf(smx[k], X2W2[k*64+t], x2);
    }
#pragma unroll
    for (int a = 0; a < AIN; ++a) {
        x1 = fmaf(smoc[a], X1W3[a*64+t], x1); x2 = fmaf(smoc[a], X2W3[a*64+t], x2);
        x1 = fmaf(sdp[a],  X1W4[a*64+t], x1); x2 = fmaf(sdp[a],  X2W4[a*64+t], x2);
        x1 = fmaf(smdp[a], X1W5[a*64+t], x1); x2 = fmaf(smdp[a], X2W5[a*64+t], x2);
        x1 = fmaf(smal[a], X1W6[a*64+t], x1); x2 = fmaf(smal[a], X2W6[a*64+t], x2);
    }
    g_X1t[(size_t)bx*XOUT + t] = x1;
    g_X2t[(size_t)bx*XOUT + t] = x2;
    if (t < AOUT) {
        float r = 0.f;
#pragma unroll
        for (int a = 0; a < AIN; ++a) {
            r = fmaf(smoc[a], AW3[a*AOUT+t], r);
            r = fmaf(sdp[a],  AW5[a*AOUT+t], r);
        }
        for (int k = 0; k < XIN; ++k) r = fmaf(sx[k], AW6[k*AOUT+t], r);
        g_R[(size_t)bx*AOUT + t] = r;
    }
}

// ---------------- K_q: Q and SX2 partials over 64-j segments -------------
__global__ void __launch_bounds__(1024) k_q()
{
    int bx = blockIdx.x;               // n*16 + seg
    int n = bx >> 4, seg = bx & 15;
    int tid = threadIdx.x;
    int s16 = tid >> 6, t = tid & 63;
    const float* rp = g_R   + ((size_t)n << 10) * AOUT + (size_t)(seg << 6) * AOUT;
    const float* xp = g_X2t + ((size_t)n << 10) * XOUT + (size_t)(seg << 6) * XOUT;
    float q = 0.f;
#pragma unroll 4
    for (int jj = 0; jj < 64; ++jj)
        q = fmaf(rp[jj*AOUT + s16], xp[jj*XOUT + t], q);
    g_Qpart[(size_t)bx * 1024 + tid] = q;
    if (tid < 64) {
        float s = 0.f;
#pragma unroll 4
        for (int jj = 0; jj < 64; ++jj) s += xp[jj*XOUT + tid];
        g_SX2part[bx*64 + tid] = s;
    }
}

// ---------------- K_fin: T, K --------------------------------------------
__global__ void __launch_bounds__(1024) k_fin(
    const float* __restrict__ OW, const float* __restrict__ outb)
{
    int n = blockIdx.x, tid = threadIdx.x;
    __shared__ float sx2[XOUT];
    __shared__ float sq[AOUT*XOUT];
    __shared__ float st_[AOUT*XOUT];
    __shared__ float sp[AOUT*XOUT];
    {   // reduce Q partials
        float q = 0.f;
#pragma unroll
        for (int seg = 0; seg < 16; ++seg)
            q += g_Qpart[(size_t)((n<<4)|seg) * 1024 + tid];
        sq[tid] = q;
    }
    if (tid < 64) {
        float s = 0.f;
#pragma unroll
        for (int seg = 0; seg < 16; ++seg) s += g_SX2part[((n<<4)|seg)*64 + tid];
        sx2[tid] = s;
    }
    __syncthreads();
    int s16 = tid >> 6, t = tid & 63;
    {   // T[s,t] = sum_u SX2[u] * OW[(s*64+u)*64+t]
        float v = 0.f;
#pragma unroll 4
        for (int u = 0; u < 64; ++u)
            v = fmaf(sx2[u], OW[((s16<<6)+u)*64 + t], v);
        st_[tid] = v;
        g_T[n*1024 + tid] = v;
    }
    {   // qo partials: thread (s,t) sums u of sq[s*64+u]*OW[((s*64+u)*64)+t]
        float p = 0.f;
#pragma unroll 4
        for (int u = 0; u < 64; ++u)
            p = fmaf(sq[(s16<<6)+u], OW[(((s16<<6)+u)<<6) + t], p);
        sp[tid] = p;
    }
    __syncthreads();
    if (tid < 64) {
        int tt = tid;
        float qo = 0.f, ct = 0.f;
#pragma unroll
        for (int s = 0; s < AOUT; ++s) {
            qo += sp[(s<<6) + tt];
            ct = fmaf(g_C[n*AOUT + s], st_[(s<<6) + tt], ct);
        }
        g_K[n*XOUT + tt] = (ct + qo) * (1.f/1024.f) + outb[tt];
    }
}

// ---------------- K3: main — At construction + H GEMM --------------------
__global__ void __launch_bounds__(256) k_main(
    const float* __restrict__ A, const float* __restrict__ AW1,
    float* __restrict__ outAt)
{
    int bx = blockIdx.x;                 // n*1024 + i
    int n = bx >> 10, i = bx & 1023;
    int tid = threadIdx.x, w = tid >> 5, l = tid & 31;

    __shared__ __align__(16) float sA[AIN][1028];   // padded
    __shared__ __align__(16) float sW1[AIN][AOUT];
    __shared__ __align__(16) float sC16[AOUT];

    {
        const float4* A4 = (const float4*)A;
#pragma unroll
        for (int a = 0; a < AIN; ++a) {
            size_t ridx = ((size_t)(n*AIN + a) << 20) + ((size_t)i << 10);
            float4 v = A4[(ridx >> 2) + tid];
            *((float4*)&sA[a][tid*4]) = v;
        }
    }
    if (tid < 128) sW1[tid >> 4][tid & 15] = AW1[tid];
    if (tid < AOUT) {
        float r = g_R[(size_t)bx*AOUT + tid];
        sC16[tid] = r + g_C[n*AOUT + tid];
    }
    __syncthreads();

    // ---- Phase A: At[n,i,j,s] -> out[(n*16+s), i, j]  (f32x2 G) ----
    {
        const unsigned long long* cpair = (const unsigned long long*)sC16;
#pragma unroll 1
        for (int step = 0; step < 4; ++step) {
            int j = (step << 8) + tid;
            unsigned long long acc[8];
#pragma unroll
            for (int p = 0; p < 8; ++p) acc[p] = cpair[p];
#pragma unroll
            for (int a = 0; a < AIN; ++a) {
                float av = sA[a][j];
                unsigned long long bA; PACK2(bA, av);
                const unsigned long long* wp = (const unsigned long long*)sW1[a];
#pragma unroll
                for (int p = 0; p < 8; ++p) FMA2(acc[p], bA, wp[p]);
            }
            float v[16];
#pragma unroll
            for (int p = 0; p < 8; ++p) UNPACK2(v[2*p], v[2*p+1], acc[p]);
            const float4* rj = (const float4*)(g_R + (((size_t)((n<<10) | j)) << 4));
#pragma unroll
            for (int q = 0; q < 4; ++q) {
                float4 r = rj[q];
                v[4*q]   += r.x; v[4*q+1] += r.y; v[4*q+2] += r.z; v[4*q+3] += r.w;
            }
            size_t ob0 = ((size_t)(n*AOUT) << 20) + ((size_t)i << 10) + j;
#pragma unroll
            for (int s = 0; s < AOUT; ++s)
                outAt[ob0 + ((size_t)s << 20)] = v[s];
        }
    }

    // ---- Phase H: H[a,t] = sum_j sA[a][j] * X2t[n,j,t]  (warp-split j) ----
    unsigned long long h[8];
#pragma unroll
    for (int p = 0; p < 8; ++p) h[p] = 0ull;
    {
        int a = l >> 2, t0 = (l & 3) << 4;
        const float* x2b = g_X2t + ((size_t)n << 10) * XOUT + t0;
        int j0 = w << 7;
#pragma unroll 2
        for (int jj = 0; jj < 128; ++jj) {
            int j = j0 + jj;
            float av = sA[a][j];
            unsigned long long bA; PACK2(bA, av);
            const float* xr = x2b + ((size_t)j << 6);
            unsigned long long x0,x1,x2,x3,x4,x5,x6,x7;
            asm("ld.global.v2.b64 {%0,%1},[%2];" : "=l"(x0),"=l"(x1) : "l"(xr));
            asm("ld.global.v2.b64 {%0,%1},[%2];" : "=l"(x2),"=l"(x3) : "l"(xr+4));
            asm("ld.global.v2.b64 {%0,%1},[%2];" : "=l"(x4),"=l"(x5) : "l"(xr+8));
            asm("ld.global.v2.b64 {%0,%1},[%2];" : "=l"(x6),"=l"(x7) : "l"(xr+12));
            FMA2(h[0],bA,x0); FMA2(h[1],bA,x1); FMA2(h[2],bA,x2); FMA2(h[3],bA,x3);
            FMA2(h[4],bA,x4); FMA2(h[5],bA,x5); FMA2(h[6],bA,x6); FMA2(h[7],bA,x7);
        }
    }
    __syncthreads();
    {
        float* sd = &sA[0][0];
        int a = l >> 2, t0 = (l & 3) << 4;
#pragma unroll
        for (int p = 0; p < 8; ++p) {
            float lo, hi; UNPACK2(lo, hi, h[p]);
            sd[(w<<9) + (a<<6) + t0 + 2*p]     = lo;
            sd[(w<<9) + (a<<6) + t0 + 2*p + 1] = hi;
        }
        __syncthreads();
        for (int idx = tid; idx < 512; idx += 256) {
            float s = 0.f;
#pragma unroll
            for (int w2 = 0; w2 < 8; ++w2) s += sd[(w2<<9) + idx];
            g_H[((size_t)bx << 9) + idx] = s;
        }
    }
}

// ---------------- K4: out = H*OWH/n + R*T/n + K + X1t ---------------------
__global__ void __launch_bounds__(256) k_out(float* __restrict__ out2)
{
    int bx = blockIdx.x;                 // 256 blocks x 16 nodes
    int n = bx >> 6;
    int tid = threadIdx.x;
    __shared__ float sH[16][514];
    {
        const float4* hp = (const float4*)(g_H + ((size_t)bx << 13));
#pragma unroll
        for (int k = 0; k < 8; ++k) {
            int idx = (k << 8) + tid;
            float4 v = hp[idx];
            int row = idx >> 7, col = (idx & 127) << 2;
            sH[row][col] = v.x; sH[row][col+1] = v.y;
            sH[row][col+2] = v.z; sH[row][col+3] = v.w;
        }
    }
    __syncthreads();
    int r = tid >> 4, q = tid & 15, t0 = q << 2;
    int node = (bx << 4) + r;
    float a0=0.f, a1=0.f, a2=0.f, a3=0.f;
    for (int au = 0; au < 512; ++au) {
        float hv = sH[r][au];
        float4 wv = *(const float4*)(g_OWH + (au << 6) + t0);
        a0 = fmaf(hv, wv.x, a0); a1 = fmaf(hv, wv.y, a1);
        a2 = fmaf(hv, wv.z, a2); a3 = fmaf(hv, wv.w, a3);
    }
    const float* Tn = g_T + (n << 10);
    const float* Rn = g_R + ((size_t)node << 4);
#pragma unroll
    for (int s = 0; s < AOUT; ++s) {
        float rv = Rn[s];
        float4 tv = *(const float4*)(Tn + (s << 6) + t0);
        a0 = fmaf(rv, tv.x, a0); a1 = fmaf(rv, tv.y, a1);
        a2 = fmaf(rv, tv.z, a2); a3 = fmaf(rv, tv.w, a3);
    }
    const float sc = 1.f/1024.f;
    size_t ob = ((size_t)node << 6) + t0;
    float4 kv  = *(const float4*)(g_K + (n << 6) + t0);
    float4 x1v = *(const float4*)(g_X1t + ob);
    float4 o;
    o.x = a0*sc + kv.x + x1v.x;  o.y = a1*sc + kv.y + x1v.y;
    o.z = a2*sc + kv.z + x1v.z;  o.w = a3*sc + kv.w + x1v.w;
    *(float4*)(out2 + ob) = o;
}

// ---------------- launch ---------------------------------------------------
extern "C" void kernel_launch(void* const* d_in, const int* in_sizes, int n_in,
                              void* d_out, int out_size)
{
    const float* A     = (const float*)d_in[0];
    const float* X     = (const float*)d_in[1];
    const float* AW1   = (const float*)d_in[2];
    const float* AW2   = (const float*)d_in[3];
    const float* AW3   = (const float*)d_in[4];
    const float* AW4   = (const float*)d_in[5];
    const float* AW5   = (const float*)d_in[6];
    const float* AW6   = (const float*)d_in[7];
    const float* AW7   = (const float*)d_in[8];
    const float* Abias = (const float*)d_in[9];
    const float* X1W1  = (const float*)d_in[10];
    const float* X1W2  = (const float*)d_in[11];
    const float* X1W3  = (const float*)d_in[12];
    const float* X1W4  = (const float*)d_in[13];
    const float* X1W5  = (const float*)d_in[14];
    const float* X1W6  = (const float*)d_in[15];
    const float* X1b   = (const float*)d_in[16];
    const float* X2W1  = (const float*)d_in[17];
    const float* X2W2  = (const float*)d_in[18];
    const float* X2W3  = (const float*)d_in[19];
    const float* X2W4  = (const float*)d_in[20];
    const float* X2W5  = (const float*)d_in[21];
    const float* X2W6  = (const float*)d_in[22];
    const float* X2b   = (const float*)d_in[23];
    const float* OW    = (const float*)d_in[24];
    const float* outb  = (const float*)d_in[25];

    float* outAt = (float*)d_out;
    float* out2  = outAt + (size_t)NB * AOUT * NN * NN;

    k_owh   <<<AIN, 256>>>(AW1, OW);
    k_reduce<<<NB*NN, 256>>>(A);
    k_pre_n <<<NB, 1024>>>(X, AW2, AW4, AW7, Abias);
    k_node  <<<NB*NN, 64>>>(X, AW3, AW5, AW6,
                            X1W1, X1W2, X1W3, X1W4, X1W5, X1W6, X1b,
                            X2W1, X2W2, X2W3, X2W4, X2W5, X2W6, X2b);
    k_q     <<<NB*16, 1024>>>();
    k_fin   <<<NB, 1024>>>(OW, outb);
    k_main  <<<NB*NN, 256>>>(A, AW1, outAt);
    k_out   <<<NB*NN/16, 256>>>(out2);
}

// round 4
// speedup vs baseline: 2.3493x; 2.1500x over previous
#include <cuda_runtime.h>
#include <cstdint>

#define NB 4
#define NN 1024
#define AIN 8
#define AOUT 16
#define XIN 64
#define XOUT 64

// ---------------- scratch (device globals; no allocation) ----------------
__device__ float g_moc[NB*NN*AIN];
__device__ float g_dp [NB*NN*AIN];
__device__ float g_mdp[NB*AIN];
__device__ float g_mall[NB*AIN];
__device__ float g_mX [NB*XIN];
__device__ float g_C  [NB*AOUT];
__device__ float g_R  [NB*NN*AOUT];
__device__ float g_X1t[NB*NN*XOUT];
__device__ float g_X2t[NB*NN*XOUT];
__device__ float g_T  [NB*AOUT*XOUT];
__device__ float g_K  [NB*XOUT];
__device__ float g_OWH[AIN*XOUT*XOUT];
__device__ float g_H  [NB*NN*AIN*XOUT];        // per-node H (4096 x 512)
__device__ float g_Qpart[NB*16*AOUT*XOUT];
__device__ float g_SX2part[NB*16*XOUT];

#define FMA2(d,a,b) asm("fma.rn.f32x2 %0, %1, %2, %0;" : "+l"(d) : "l"(a), "l"(b))
#define PACK2(d,x)  asm("mov.b64 %0, {%1, %1};" : "=l"(d) : "f"(x))
#define UNPACK2(lo,hi,d) asm("mov.b64 {%0, %1}, %2;" : "=f"(lo), "=f"(hi) : "l"(d))

// ---------------- K1: row reductions over A -> moc, dp -------------------
__global__ void __launch_bounds__(256) k_reduce(const float* __restrict__ A)
{
    int bx = blockIdx.x;            // bx = n*1024 + i
    int n = bx >> 10, i = bx & 1023;
    int w = threadIdx.x >> 5, l = threadIdx.x & 31;
    size_t row = ((size_t)(n*AIN + w) << 20) + ((size_t)i << 10);
    const float4* p = (const float4*)(A + row);
    float s = 0.f;
#pragma unroll
    for (int k = 0; k < 8; ++k) {
        float4 v = p[k*32 + l];
        s += v.x + v.y + v.z + v.w;
    }
#pragma unroll
    for (int o = 16; o; o >>= 1) s += __shfl_xor_sync(0xffffffffu, s, o);
    if (l == 0) {
        g_moc[(bx << 3) + w] = s * (1.f/1024.f);
        g_dp [(bx << 3) + w] = A[row + i];
    }
}

// ---------------- K_owh: OWH[a,u,t] = sum_s W1[a,s]*OW[(s*64+u)*64+t] ----
__global__ void __launch_bounds__(256) k_owh(
    const float* __restrict__ AW1, const float* __restrict__ OW)
{
    int a = blockIdx.x, tid = threadIdx.x;
    __shared__ float sw[AOUT];
    if (tid < AOUT) sw[tid] = AW1[a*AOUT + tid];
    __syncthreads();
    for (int idx = tid; idx < 4096; idx += 256) {
        int u = idx >> 6, t = idx & 63;
        float s = 0.f;
#pragma unroll
        for (int ss = 0; ss < AOUT; ++ss)
            s = fmaf(sw[ss], OW[((ss<<6)+u)*64 + t], s);
        g_OWH[((a<<6)+u)*64 + t] = s;
    }
}

// ---------------- K2a: per-n means + C -----------------------------------
__global__ void __launch_bounds__(1024) k_pre_n(
    const float* __restrict__ X,
    const float* __restrict__ AW2, const float* __restrict__ AW4,
    const float* __restrict__ AW7, const float* __restrict__ Abias)
{
    int n = blockIdx.x, tid = threadIdx.x;
    __shared__ float spart[16][64];
    __shared__ float sdpp[128][8];
    __shared__ float salp[128][8];
    __shared__ float smx[XIN], smdp[AIN], smal[AIN];

    {
        int col = tid & 63, seg = tid >> 6;
        const float* xp = X + ((size_t)n << 16) + (size_t)(seg << 6) * XIN + col;
        float s = 0.f;
#pragma unroll 4
        for (int r = 0; r < 64; ++r) s += xp[(size_t)r * XIN];
        spart[seg][col] = s;
    }
    {
        int a = tid & 7, seg = tid >> 3;
        const float* dpp = g_dp  + (n << 13) + (seg << 6) + a;
        const float* mcp = g_moc + (n << 13) + (seg << 6) + a;
        float s1 = 0.f, s2 = 0.f;
#pragma unroll
        for (int r = 0; r < 8; ++r) { s1 += dpp[r*8]; s2 += mcp[r*8]; }
        sdpp[seg][a] = s1; salp[seg][a] = s2;
    }
    __syncthreads();
    if (tid < 64) {
        float s = 0.f;
#pragma unroll
        for (int k = 0; k < 16; ++k) s += spart[k][tid];
        smx[tid] = s * (1.f/1024.f);
        g_mX[n*XIN + tid] = smx[tid];
    } else if (tid >= 64 && tid < 72) {
        int a = tid - 64; float s = 0.f;
        for (int k = 0; k < 128; ++k) s += sdpp[k][a];
        smdp[a] = s * (1.f/1024.f); g_mdp[n*AIN + a] = smdp[a];
    } else if (tid >= 72 && tid < 80) {
        int a = tid - 72; float s = 0.f;
        for (int k = 0; k < 128; ++k) s += salp[k][a];
        smal[a] = s * (1.f/1024.f); g_mall[n*AIN + a] = smal[a];
    }
    __syncthreads();
    if (tid < AOUT) {
        int s16 = tid; float c = Abias[s16];
#pragma unroll
        for (int a = 0; a < AIN; ++a)
            c = fmaf(smal[a], AW2[a*AOUT+s16], fmaf(smdp[a], AW4[a*AOUT+s16], c));
        for (int k = 0; k < XIN; ++k) c = fmaf(smx[k], AW7[k*AOUT+s16], c);
        g_C[n*AOUT + s16] = c;
    }
}

// ---------------- K2b: per-node R, X1t, X2t (4 nodes / block) ------------
__global__ void __launch_bounds__(256) k_node(
    const float* __restrict__ X,
    const float* __restrict__ AW3, const float* __restrict__ AW5, const float* __restrict__ AW6,
    const float* __restrict__ X1W1, const float* __restrict__ X1W2, const float* __restrict__ X1W3,
    const float* __restrict__ X1W4, const float* __restrict__ X1W5, const float* __restrict__ X1W6,
    const float* __restrict__ X1b,
    const float* __restrict__ X2W1, const float* __restrict__ X2W2, const float* __restrict__ X2W3,
    const float* __restrict__ X2W4, const float* __restrict__ X2W5, const float* __restrict__ X2W6,
    const float* __restrict__ X2b)
{
    int bx = blockIdx.x;                 // 1024 blocks, 4 nodes each
    int nl = threadIdx.x >> 6, t = threadIdx.x & 63;
    int node = (bx << 2) + nl, n = node >> 10;
    __shared__ float sx[4][64], smx[64];
    __shared__ float smoc[4][8], sdpv[4][8], smdp[8], smal[8];
    sx[nl][t] = X[(size_t)node * XIN + t];
    if (nl == 0) smx[t] = g_mX[(n<<6) + t];
    if (t < 8) {
        smoc[nl][t] = g_moc[(node<<3) + t];
        sdpv[nl][t] = g_dp [(node<<3) + t];
        if (nl == 0) { smdp[t] = g_mdp[(n<<3)+t]; smal[t] = g_mall[(n<<3)+t]; }
    }
    __syncthreads();
    float x1 = X1b[t], x2 = X2b[t];
    for (int k = 0; k < XIN; ++k) {
        float xk = sx[nl][k], mk = smx[k];
        x1 = fmaf(xk, X1W1[(k<<6)+t], x1);  x2 = fmaf(xk, X2W1[(k<<6)+t], x2);
        x1 = fmaf(mk, X1W2[(k<<6)+t], x1);  x2 = fmaf(mk, X2W2[(k<<6)+t], x2);
    }
#pragma unroll
    for (int a = 0; a < AIN; ++a) {
        x1 = fmaf(smoc[nl][a], X1W3[(a<<6)+t], x1); x2 = fmaf(smoc[nl][a], X2W3[(a<<6)+t], x2);
        x1 = fmaf(sdpv[nl][a], X1W4[(a<<6)+t], x1); x2 = fmaf(sdpv[nl][a], X2W4[(a<<6)+t], x2);
        x1 = fmaf(smdp[a],     X1W5[(a<<6)+t], x1); x2 = fmaf(smdp[a],     X2W5[(a<<6)+t], x2);
        x1 = fmaf(smal[a],     X1W6[(a<<6)+t], x1); x2 = fmaf(smal[a],     X2W6[(a<<6)+t], x2);
    }
    g_X1t[(size_t)node*XOUT + t] = x1;
    g_X2t[(size_t)node*XOUT + t] = x2;
    if (t < AOUT) {
        float r = 0.f;
#pragma unroll
        for (int a = 0; a < AIN; ++a) {
            r = fmaf(smoc[nl][a], AW3[a*AOUT+t], r);
            r = fmaf(sdpv[nl][a], AW5[a*AOUT+t], r);
        }
        for (int k = 0; k < XIN; ++k) r = fmaf(sx[nl][k], AW6[k*AOUT+t], r);
        g_R[(size_t)node*AOUT + t] = r;
    }
}

// ---------------- K_q: Q and SX2 partials ---------------------------------
__global__ void __launch_bounds__(1024) k_q()
{
    int bx = blockIdx.x;               // n*16 + seg
    int n = bx >> 4, seg = bx & 15;
    int tid = threadIdx.x;
    int s16 = tid >> 6, t = tid & 63;
    const float* rp = g_R   + ((size_t)n << 10) * AOUT + (size_t)(seg << 6) * AOUT;
    const float* xp = g_X2t + ((size_t)n << 10) * XOUT + (size_t)(seg << 6) * XOUT;
    float q = 0.f;
#pragma unroll 4
    for (int jj = 0; jj < 64; ++jj)
        q = fmaf(rp[jj*AOUT + s16], xp[jj*XOUT + t], q);
    g_Qpart[(size_t)bx * 1024 + tid] = q;
    if (tid < 64) {
        float s = 0.f;
#pragma unroll 4
        for (int jj = 0; jj < 64; ++jj) s += xp[jj*XOUT + tid];
        g_SX2part[bx*64 + tid] = s;
    }
}

// ---------------- K_fin: T, K ---------------------------------------------
__global__ void __launch_bounds__(1024) k_fin(
    const float* __restrict__ OW, const float* __restrict__ outb)
{
    int n = blockIdx.x, tid = threadIdx.x;
    __shared__ float sx2[XOUT];
    __shared__ float sq[AOUT*XOUT];
    __shared__ float st_[AOUT*XOUT];
    __shared__ float sp[AOUT*XOUT];
    {
        float q = 0.f;
#pragma unroll
        for (int seg = 0; seg < 16; ++seg)
            q += g_Qpart[(size_t)((n<<4)|seg) * 1024 + tid];
        sq[tid] = q;
    }
    if (tid < 64) {
        float s = 0.f;
#pragma unroll
        for (int seg = 0; seg < 16; ++seg) s += g_SX2part[((n<<4)|seg)*64 + tid];
        sx2[tid] = s;
    }
    __syncthreads();
    int s16 = tid >> 6, t = tid & 63;
    {
        float v = 0.f;
#pragma unroll 4
        for (int u = 0; u < 64; ++u)
            v = fmaf(sx2[u], OW[((s16<<6)+u)*64 + t], v);
        st_[tid] = v;
        g_T[n*1024 + tid] = v;
    }
    {
        float p = 0.f;
#pragma unroll 4
        for (int u = 0; u < 64; ++u)
            p = fmaf(sq[(s16<<6)+u], OW[(((s16<<6)+u)<<6) + t], p);
        sp[tid] = p;
    }
    __syncthreads();
    if (tid < 64) {
        int tt = tid;
        float qo = 0.f, ct = 0.f;
#pragma unroll
        for (int s = 0; s < AOUT; ++s) {
            qo += sp[(s<<6) + tt];
            ct = fmaf(g_C[n*AOUT + s], st_[(s<<6) + tt], ct);
        }
        g_K[n*XOUT + tt] = (ct + qo) * (1.f/1024.f) + outb[tt];
    }
}

// ---------------- K3: main — At construction + H GEMM --------------------
// dyn smem: sA [8][1028] | sAT [1024][8] (reused as dump[16][512]) | sW1[8][16] | sC16[16]
#define SMEM_MAIN ((8*1028 + 1024*8 + 128 + 16) * 4)

__global__ void __launch_bounds__(256) k_main(
    const float* __restrict__ A, const float* __restrict__ AW1,
    float* __restrict__ outAt)
{
    extern __shared__ float dyn[];
    float* sA   = dyn;                    // 8224 floats
    float* sAT  = dyn + 8224;             // 8192 floats (reused as dump)
    float* sW1  = dyn + 8224 + 8192;      // 128
    float* sC16 = sW1 + 128;              // 16

    int bx = blockIdx.x;                  // n*1024 + i
    int n = bx >> 10, i = bx & 1023;
    int tid = threadIdx.x, w = tid >> 5, l = tid & 31;

    // stage 8 A rows (coalesced float4)
    {
        const float4* A4 = (const float4*)A;
#pragma unroll
        for (int a = 0; a < AIN; ++a) {
            size_t ridx = ((size_t)((n<<3) + a) << 20) + ((size_t)i << 10);
            float4 v = A4[(ridx >> 2) + tid];
            *(float4*)(sA + a*1028 + (tid<<2)) = v;
        }
    }
    if (tid < 128) sW1[tid] = AW1[tid];   // [a][s] row-major, same layout
    if (tid < AOUT)
        sC16[tid] = g_R[((size_t)bx << 4) + tid] + g_C[(n<<4) + tid];
    __syncthreads();

    // conflict-free transpose sA -> sAT[j][a]
    {
        int a = tid & 7, jb = tid >> 3;
#pragma unroll
        for (int it = 0; it < 32; ++it) {
            int j = jb + (it << 5);
            sAT[(j << 3) + a] = sA[a*1028 + j];
        }
    }
    __syncthreads();

    // ---- Phase A: At[n,i,j,s] -> out[(n*16+s), i, j] ----
    {
        int j0 = tid << 2;
        unsigned long long apk[8][2];
#pragma unroll
        for (int a = 0; a < AIN; ++a) {
            const unsigned long long* rp = (const unsigned long long*)(sA + a*1028 + j0);
            apk[a][0] = rp[0]; apk[a][1] = rp[1];
        }
        size_t obase = (((size_t)(n<<4)) << 20) + ((size_t)i << 10) + j0;
        const float* Rb = g_R + (((size_t)(n<<10)) << 4);
#pragma unroll
        for (int sg = 0; sg < 4; ++sg) {
            float4 c4 = *(const float4*)(sC16 + (sg<<2));
            unsigned long long a0a,a0b,a1a,a1b,a2a,a2b,a3a,a3b;
            PACK2(a0a, c4.x); a0b = a0a;
            PACK2(a1a, c4.y); a1b = a1a;
            PACK2(a2a, c4.z); a2b = a2a;
            PACK2(a3a, c4.w); a3b = a3a;
#pragma unroll
            for (int a = 0; a < AIN; ++a) {
                float4 w4 = *(const float4*)(sW1 + (a<<4) + (sg<<2));
                unsigned long long ws;
                PACK2(ws, w4.x); FMA2(a0a, apk[a][0], ws); FMA2(a0b, apk[a][1], ws);
                PACK2(ws, w4.y); FMA2(a1a, apk[a][0], ws); FMA2(a1b, apk[a][1], ws);
                PACK2(ws, w4.z); FMA2(a2a, apk[a][0], ws); FMA2(a2b, apk[a][1], ws);
                PACK2(ws, w4.w); FMA2(a3a, apk[a][0], ws); FMA2(a3b, apk[a][1], ws);
            }
            float4 r0 = *(const float4*)(Rb + ((size_t)(j0+0)<<4) + (sg<<2));
            float4 r1 = *(const float4*)(Rb + ((size_t)(j0+1)<<4) + (sg<<2));
            float4 r2 = *(const float4*)(Rb + ((size_t)(j0+2)<<4) + (sg<<2));
            float4 r3 = *(const float4*)(Rb + ((size_t)(j0+3)<<4) + (sg<<2));
            float v0,v1,v2,v3; float4 o;
            UNPACK2(v0,v1,a0a); UNPACK2(v2,v3,a0b);
            o.x=v0+r0.x; o.y=v1+r1.x; o.z=v2+r2.x; o.w=v3+r3.x;
            *(float4*)(outAt + obase + (((size_t)((sg<<2)+0)) << 20)) = o;
            UNPACK2(v0,v1,a1a); UNPACK2(v2,v3,a1b);
            o.x=v0+r0.y; o.y=v1+r1.y; o.z=v2+r2.y; o.w=v3+r3.y;
            *(float4*)(outAt + obase + (((size_t)((sg<<2)+1)) << 20)) = o;
            UNPACK2(v0,v1,a2a); UNPACK2(v2,v3,a2b);
            o.x=v0+r0.z; o.y=v1+r1.z; o.z=v2+r2.z; o.w=v3+r3.z;
            *(float4*)(outAt + obase + (((size_t)((sg<<2)+2)) << 20)) = o;
            UNPACK2(v0,v1,a3a); UNPACK2(v2,v3,a3b);
            o.x=v0+r0.w; o.y=v1+r1.w; o.z=v2+r2.w; o.w=v3+r3.w;
            *(float4*)(outAt + obase + (((size_t)((sg<<2)+3)) << 20)) = o;
        }
    }

    // ---- Phase H: H[a,t] = sum_j A[a][j] * X2t[n,j,t] ----
    // lane: half = l>>4 (row parity), t0 = (l&15)*4 (4 t-cols); warp w: rows [w*128, w*128+128)
    {
        int half = l >> 4, t0 = (l & 15) << 2;
        const float* X2 = g_X2t + (((size_t)n) << 16);
        unsigned long long hac[4][4];
#pragma unroll
        for (int p = 0; p < 4; ++p)
#pragma unroll
            for (int q = 0; q < 4; ++q) hac[p][q] = 0ull;
        int jb = (w << 7) + half;
#pragma unroll 4
        for (int s2 = 0; s2 < 64; ++s2) {
            int j = jb + (s2 << 1);
            float4 x4 = *(const float4*)(X2 + ((size_t)j << 6) + t0);
            const unsigned long long* ar = (const unsigned long long*)(sAT + (j << 3));
            unsigned long long ap0 = ar[0], ap1 = ar[1], ap2 = ar[2], ap3 = ar[3];
            unsigned long long xs;
            PACK2(xs, x4.x);
            FMA2(hac[0][0], ap0, xs); FMA2(hac[1][0], ap1, xs);
            FMA2(hac[2][0], ap2, xs); FMA2(hac[3][0], ap3, xs);
            PACK2(xs, x4.y);
            FMA2(hac[0][1], ap0, xs); FMA2(hac[1][1], ap1, xs);
            FMA2(hac[2][1], ap2, xs); FMA2(hac[3][1], ap3, xs);
            PACK2(xs, x4.z);
            FMA2(hac[0][2], ap0, xs); FMA2(hac[1][2], ap1, xs);
            FMA2(hac[2][2], ap2, xs); FMA2(hac[3][2], ap3, xs);
            PACK2(xs, x4.w);
            FMA2(hac[0][3], ap0, xs); FMA2(hac[1][3], ap1, xs);
            FMA2(hac[2][3], ap2, xs); FMA2(hac[3][3], ap3, xs);
        }
        __syncthreads();                    // all sAT reads done
        float* dump = sAT;                  // reuse as [16][512]
        int rb = (((w << 1) + half) << 9) + t0;
#pragma unroll
        for (int ap = 0; ap < 4; ++ap) {
            float4 fe, fo;
            UNPACK2(fe.x, fo.x, hac[ap][0]);
            UNPACK2(fe.y, fo.y, hac[ap][1]);
            UNPACK2(fe.z, fo.z, hac[ap][2]);
            UNPACK2(fe.w, fo.w, hac[ap][3]);
            *(float4*)(dump + rb + ((ap<<1)<<6))     = fe;
            *(float4*)(dump + rb + (((ap<<1)|1)<<6)) = fo;
        }
        __syncthreads();
#pragma unroll
        for (int k = 0; k < 2; ++k) {
            int idx = tid + (k << 8);
            float s = 0.f;
#pragma unroll
            for (int r = 0; r < 16; ++r) s += dump[(r << 9) + idx];
            g_H[((size_t)bx << 9) + idx] = s;
        }
    }
}

// ---------------- K4: out = H*OWH/n + R*T/n + K + X1t ---------------------
// dyn smem: sOWH [512][64] | sH [16][512]
#define SMEM_OUT ((512*64 + 16*512) * 4)

__global__ void __launch_bounds__(256) k_out(float* __restrict__ out2)
{
    extern __shared__ float dyn[];
    float* sOWH = dyn;            // 32768 floats
    float* sH   = dyn + 32768;    // 8192 floats
    int bx = blockIdx.x;          // 256 blocks x 16 nodes
    int n = bx >> 6, tid = threadIdx.x;
    {
        const float4* s4 = (const float4*)g_OWH;
        float4* d4 = (float4*)sOWH;
#pragma unroll
        for (int k = 0; k < 32; ++k) d4[(k<<8)+tid] = s4[(k<<8)+tid];
        const float4* h4 = (const float4*)(g_H + ((size_t)bx << 13));
        float4* dh = (float4*)sH;
#pragma unroll
        for (int k = 0; k < 8; ++k) dh[(k<<8)+tid] = h4[(k<<8)+tid];
    }
    __syncthreads();
    int r = tid >> 4, q = tid & 15, t0 = q << 2;
    int node = (bx << 4) + r;
    unsigned long long acc01 = 0ull, acc23 = 0ull;
    const float* hrow = sH + (r << 9);
#pragma unroll 4
    for (int au = 0; au < 512; ++au) {
        unsigned long long hs; PACK2(hs, hrow[au]);
        const unsigned long long* wr = (const unsigned long long*)(sOWH + (au << 6) + t0);
        FMA2(acc01, hs, wr[0]); FMA2(acc23, hs, wr[1]);
    }
    float a0,a1,a2,a3;
    UNPACK2(a0,a1,acc01); UNPACK2(a2,a3,acc23);
    const float* Tn = g_T + (n << 10);
    const float* Rn = g_R + ((size_t)node << 4);
#pragma unroll
    for (int s = 0; s < AOUT; ++s) {
        float rv = Rn[s];
        float4 tv = *(const float4*)(Tn + (s << 6) + t0);
        a0 = fmaf(rv, tv.x, a0); a1 = fmaf(rv, tv.y, a1);
        a2 = fmaf(rv, tv.z, a2); a3 = fmaf(rv, tv.w, a3);
    }
    const float sc = 1.f/1024.f;
    size_t ob = ((size_t)node << 6) + t0;
    float4 kv  = *(const float4*)(g_K + (n << 6) + t0);
    float4 x1v = *(const float4*)(g_X1t + ob);
    float4 o;
    o.x = a0*sc + kv.x + x1v.x;  o.y = a1*sc + kv.y + x1v.y;
    o.z = a2*sc + kv.z + x1v.z;  o.w = a3*sc + kv.w + x1v.w;
    *(float4*)(out2 + ob) = o;
}

// ---------------- launch ---------------------------------------------------
extern "C" void kernel_launch(void* const* d_in, const int* in_sizes, int n_in,
                              void* d_out, int out_size)
{
    const float* A     = (const float*)d_in[0];
    const float* X     = (const float*)d_in[1];
    const float* AW1   = (const float*)d_in[2];
    const float* AW2   = (const float*)d_in[3];
    const float* AW3   = (const float*)d_in[4];
    const float* AW4   = (const float*)d_in[5];
    const float* AW5   = (const float*)d_in[6];
    const float* AW6   = (const float*)d_in[7];
    const float* AW7   = (const float*)d_in[8];
    const float* Abias = (const float*)d_in[9];
    const float* X1W1  = (const float*)d_in[10];
    const float* X1W2  = (const float*)d_in[11];
    const float* X1W3  = (const float*)d_in[12];
    const float* X1W4  = (const float*)d_in[13];
    const float* X1W5  = (const float*)d_in[14];
    const float* X1W6  = (const float*)d_in[15];
    const float* X1b   = (const float*)d_in[16];
    const float* X2W1  = (const float*)d_in[17];
    const float* X2W2  = (const float*)d_in[18];
    const float* X2W3  = (const float*)d_in[19];
    const float* X2W4  = (const float*)d_in[20];
    const float* X2W5  = (const float*)d_in[21];
    const float* X2W6  = (const float*)d_in[22];
    const float* X2b   = (const float*)d_in[23];
    const float* OW    = (const float*)d_in[24];
    const float* outb  = (const float*)d_in[25];

    float* outAt = (float*)d_out;
    float* out2  = outAt + (size_t)NB * AOUT * NN * NN;

    cudaFuncSetAttribute(k_main, cudaFuncAttributeMaxDynamicSharedMemorySize, SMEM_MAIN);
    cudaFuncSetAttribute(k_out,  cudaFuncAttributeMaxDynamicSharedMemorySize, SMEM_OUT);

    k_owh   <<<AIN, 256>>>(AW1, OW);
    k_reduce<<<NB*NN, 256>>>(A);
    k_pre_n <<<NB, 1024>>>(X, AW2, AW4, AW7, Abias);
    k_node  <<<NB*NN/4, 256>>>(X, AW3, AW5, AW6,
                            X1W1, X1W2, X1W3, X1W4, X1W5, X1W6, X1b,
                            X2W1, X2W2, X2W3, X2W4, X2W5, X2W6, X2b);
    k_q     <<<NB*16, 1024>>>();
    k_fin   <<<NB, 1024>>>(OW, outb);
    k_main  <<<NB*NN, 256, SMEM_MAIN>>>(A, AW1, outAt);
    k_out   <<<NB*NN/16, 256, SMEM_OUT>>>(out2);
}

// round 5
// speedup vs baseline: 2.3677x; 1.0078x over previous
#include <cuda_runtime.h>
#include <cstdint>

#define NB 4
#define NN 1024
#define AIN 8
#define AOUT 16
#define XIN 64
#define XOUT 64

typedef unsigned long long ULL;

// ---------------- scratch (device globals; no allocation) ----------------
__device__ float g_moc[NB*NN*AIN];
__device__ float g_dp [NB*NN*AIN];
__device__ float g_mdp[NB*AIN];
__device__ float g_mall[NB*AIN];
__device__ float g_mX [NB*XIN];
__device__ float g_C  [NB*AOUT];
__device__ float g_R  [NB*NN*AOUT];
__device__ float g_X1t[NB*NN*XOUT];
__device__ float g_X2t[NB*NN*XOUT];
__device__ float g_T  [NB*AOUT*XOUT];
__device__ float g_K  [NB*XOUT];
__device__ float g_OWH[AIN*XOUT*XOUT];
__device__ float g_H  [NB*NN*AIN*XOUT];
__device__ float g_Qpart[NB*16*AOUT*XOUT];
__device__ float g_SX2part[NB*16*XOUT];

#define FMA2(d,a,b) asm("fma.rn.f32x2 %0, %1, %2, %0;" : "+l"(d) : "l"(a), "l"(b))
#define PACK2(d,x)  asm("mov.b64 %0, {%1, %1};" : "=l"(d) : "f"(x))
#define PACKXY(d,x,y) asm("mov.b64 %0, {%1, %2};" : "=l"(d) : "f"(x), "f"(y))
#define UNPACK2(lo,hi,d) asm("mov.b64 {%0, %1}, %2;" : "=f"(lo), "=f"(hi) : "l"(d))

// ---------------- K1: row reductions over A -> moc, dp -------------------
__global__ void __launch_bounds__(256) k_reduce(const float* __restrict__ A)
{
    int bx = blockIdx.x;            // bx = n*1024 + i
    int n = bx >> 10, i = bx & 1023;
    int w = threadIdx.x >> 5, l = threadIdx.x & 31;
    size_t row = ((size_t)(n*AIN + w) << 20) + ((size_t)i << 10);
    const float4* p = (const float4*)(A + row);
    float s = 0.f;
#pragma unroll
    for (int k = 0; k < 8; ++k) {
        float4 v = p[k*32 + l];
        s += v.x + v.y + v.z + v.w;
    }
#pragma unroll
    for (int o = 16; o; o >>= 1) s += __shfl_xor_sync(0xffffffffu, s, o);
    if (l == 0) {
        g_moc[(bx << 3) + w] = s * (1.f/1024.f);
        g_dp [(bx << 3) + w] = A[row + i];
    }
}

// ---------------- K_owh -----------------------------------------------------
__global__ void __launch_bounds__(256) k_owh(
    const float* __restrict__ AW1, const float* __restrict__ OW)
{
    int a = blockIdx.x, tid = threadIdx.x;
    __shared__ float sw[AOUT];
    if (tid < AOUT) sw[tid] = AW1[a*AOUT + tid];
    __syncthreads();
    for (int idx = tid; idx < 4096; idx += 256) {
        int u = idx >> 6, t = idx & 63;
        float s = 0.f;
#pragma unroll
        for (int ss = 0; ss < AOUT; ++ss)
            s = fmaf(sw[ss], OW[((ss<<6)+u)*64 + t], s);
        g_OWH[((a<<6)+u)*64 + t] = s;
    }
}

// ---------------- K2a: per-n means + C -----------------------------------
__global__ void __launch_bounds__(1024) k_pre_n(
    const float* __restrict__ X,
    const float* __restrict__ AW2, const float* __restrict__ AW4,
    const float* __restrict__ AW7, const float* __restrict__ Abias)
{
    int n = blockIdx.x, tid = threadIdx.x;
    __shared__ float spart[16][64];
    __shared__ float sdpp[128][8];
    __shared__ float salp[128][8];
    __shared__ float smx[XIN], smdp[AIN], smal[AIN];

    {
        int col = tid & 63, seg = tid >> 6;
        const float* xp = X + ((size_t)n << 16) + (size_t)(seg << 6) * XIN + col;
        float s = 0.f;
#pragma unroll 4
        for (int r = 0; r < 64; ++r) s += xp[(size_t)r * XIN];
        spart[seg][col] = s;
    }
    {
        int a = tid & 7, seg = tid >> 3;
        const float* dpp = g_dp  + (n << 13) + (seg << 6) + a;
        const float* mcp = g_moc + (n << 13) + (seg << 6) + a;
        float s1 = 0.f, s2 = 0.f;
#pragma unroll
        for (int r = 0; r < 8; ++r) { s1 += dpp[r*8]; s2 += mcp[r*8]; }
        sdpp[seg][a] = s1; salp[seg][a] = s2;
    }
    __syncthreads();
    if (tid < 64) {
        float s = 0.f;
#pragma unroll
        for (int k = 0; k < 16; ++k) s += spart[k][tid];
        smx[tid] = s * (1.f/1024.f);
        g_mX[n*XIN + tid] = smx[tid];
    } else if (tid >= 64 && tid < 72) {
        int a = tid - 64; float s = 0.f;
        for (int k = 0; k < 128; ++k) s += sdpp[k][a];
        smdp[a] = s * (1.f/1024.f); g_mdp[n*AIN + a] = smdp[a];
    } else if (tid >= 72 && tid < 80) {
        int a = tid - 72; float s = 0.f;
        for (int k = 0; k < 128; ++k) s += salp[k][a];
        smal[a] = s * (1.f/1024.f); g_mall[n*AIN + a] = smal[a];
    }
    __syncthreads();
    if (tid < AOUT) {
        int s16 = tid; float c = Abias[s16];
#pragma unroll
        for (int a = 0; a < AIN; ++a)
            c = fmaf(smal[a], AW2[a*AOUT+s16], fmaf(smdp[a], AW4[a*AOUT+s16], c));
        for (int k = 0; k < XIN; ++k) c = fmaf(smx[k], AW7[k*AOUT+s16], c);
        g_C[n*AOUT + s16] = c;
    }
}

// ---------------- K2b: per-node R, X1t, X2t (16 nodes/block, 4t/lane) ----
__global__ void __launch_bounds__(256) k_node(
    const float* __restrict__ X,
    const float* __restrict__ AW3, const float* __restrict__ AW5, const float* __restrict__ AW6,
    const float* __restrict__ X1W1, const float* __restrict__ X1W2, const float* __restrict__ X1W3,
    const float* __restrict__ X1W4, const float* __restrict__ X1W5, const float* __restrict__ X1W6,
    const float* __restrict__ X1b,
    const float* __restrict__ X2W1, const float* __restrict__ X2W2, const float* __restrict__ X2W3,
    const float* __restrict__ X2W4, const float* __restrict__ X2W5, const float* __restrict__ X2W6,
    const float* __restrict__ X2b)
{
    int bx = blockIdx.x;                 // 256 blocks x 16 nodes
    int tid = threadIdx.x;
    int nl = tid >> 4, q = tid & 15, t0 = q << 2;
    int node0 = bx << 4;
    int n = node0 >> 10;
    int node = node0 + nl;

    __shared__ float sx[16][64];
    __shared__ float smoc[16][8], sdpv[16][8];
    __shared__ float smx[64], smdp[8], smal[8];

    {   // stage X: 1024 floats coalesced
        const float4* xp = (const float4*)(X + ((size_t)node0 << 6));
        ((float4*)&sx[0][0])[tid] = xp[tid];
    }
    if (tid < 128) {
        ((float*)smoc)[tid] = g_moc[(node0<<3) + tid];
        ((float*)sdpv)[tid] = g_dp [(node0<<3) + tid];
    }
    if (tid >= 128 && tid < 192) smx[tid-128] = g_mX[(n<<6) + tid-128];
    if (tid >= 192 && tid < 200) smdp[tid-192] = g_mdp[(n<<3) + tid-192];
    if (tid >= 200 && tid < 208) smal[tid-200] = g_mall[(n<<3) + tid-200];
    __syncthreads();

    float4 b1 = *(const float4*)(X1b + t0);
    float4 b2 = *(const float4*)(X2b + t0);
    ULL x1a, x1b4, x2a, x2b4;
    PACKXY(x1a, b1.x, b1.y); PACKXY(x1b4, b1.z, b1.w);
    PACKXY(x2a, b2.x, b2.y); PACKXY(x2b4, b2.z, b2.w);

#pragma unroll 4
    for (int k = 0; k < XIN; ++k) {
        float xk = sx[nl][k], mk = smx[k];
        ULL xkp, mkp; PACK2(xkp, xk); PACK2(mkp, mk);
        float4 w; ULL wlo, whi;
        w = *(const float4*)(X1W1 + (k<<6) + t0);
        PACKXY(wlo, w.x, w.y); PACKXY(whi, w.z, w.w);
        FMA2(x1a, xkp, wlo); FMA2(x1b4, xkp, whi);
        w = *(const float4*)(X2W1 + (k<<6) + t0);
        PACKXY(wlo, w.x, w.y); PACKXY(whi, w.z, w.w);
        FMA2(x2a, xkp, wlo); FMA2(x2b4, xkp, whi);
        w = *(const float4*)(X1W2 + (k<<6) + t0);
        PACKXY(wlo, w.x, w.y); PACKXY(whi, w.z, w.w);
        FMA2(x1a, mkp, wlo); FMA2(x1b4, mkp, whi);
        w = *(const float4*)(X2W2 + (k<<6) + t0);
        PACKXY(wlo, w.x, w.y); PACKXY(whi, w.z, w.w);
        FMA2(x2a, mkp, wlo); FMA2(x2b4, mkp, whi);
    }
#pragma unroll
    for (int a = 0; a < AIN; ++a) {
        ULL v1, v2, v3, v4;
        PACK2(v1, smoc[nl][a]); PACK2(v2, sdpv[nl][a]);
        PACK2(v3, smdp[a]);     PACK2(v4, smal[a]);
        float4 w; ULL wlo, whi;
        w = *(const float4*)(X1W3 + (a<<6) + t0);
        PACKXY(wlo, w.x, w.y); PACKXY(whi, w.z, w.w);
        FMA2(x1a, v1, wlo); FMA2(x1b4, v1, whi);
        w = *(const float4*)(X2W3 + (a<<6) + t0);
        PACKXY(wlo, w.x, w.y); PACKXY(whi, w.z, w.w);
        FMA2(x2a, v1, wlo); FMA2(x2b4, v1, whi);
        w = *(const float4*)(X1W4 + (a<<6) + t0);
        PACKXY(wlo, w.x, w.y); PACKXY(whi, w.z, w.w);
        FMA2(x1a, v2, wlo); FMA2(x1b4, v2, whi);
        w = *(const float4*)(X2W4 + (a<<6) + t0);
        PACKXY(wlo, w.x, w.y); PACKXY(whi, w.z, w.w);
        FMA2(x2a, v2, wlo); FMA2(x2b4, v2, whi);
        w = *(const float4*)(X1W5 + (a<<6) + t0);
        PACKXY(wlo, w.x, w.y); PACKXY(whi, w.z, w.w);
        FMA2(x1a, v3, wlo); FMA2(x1b4, v3, whi);
        w = *(const float4*)(X2W5 + (a<<6) + t0);
        PACKXY(wlo, w.x, w.y); PACKXY(whi, w.z, w.w);
        FMA2(x2a, v3, wlo); FMA2(x2b4, v3, whi);
        w = *(const float4*)(X1W6 + (a<<6) + t0);
        PACKXY(wlo, w.x, w.y); PACKXY(whi, w.z, w.w);
        FMA2(x1a, v4, wlo); FMA2(x1b4, v4, whi);
        w = *(const float4*)(X2W6 + (a<<6) + t0);
        PACKXY(wlo, w.x, w.y); PACKXY(whi, w.z, w.w);
        FMA2(x2a, v4, wlo); FMA2(x2b4, v4, whi);
    }
    {
        float4 o1, o2;
        UNPACK2(o1.x, o1.y, x1a); UNPACK2(o1.z, o1.w, x1b4);
        UNPACK2(o2.x, o2.y, x2a); UNPACK2(o2.z, o2.w, x2b4);
        *(float4*)(g_X1t + ((size_t)node << 6) + t0) = o1;
        *(float4*)(g_X2t + ((size_t)node << 6) + t0) = o2;
    }
    {   // R: lane q computes s = q for its node
        float r = 0.f;
#pragma unroll
        for (int a = 0; a < AIN; ++a) {
            r = fmaf(smoc[nl][a], AW3[a*AOUT+q], r);
            r = fmaf(sdpv[nl][a], AW5[a*AOUT+q], r);
        }
#pragma unroll 4
        for (int k = 0; k < XIN; ++k) r = fmaf(sx[nl][k], AW6[k*AOUT+q], r);
        g_R[((size_t)node << 4) + q] = r;
    }
}

// ---------------- K_q: Q and SX2 partials ---------------------------------
__global__ void __launch_bounds__(1024) k_q()
{
    int bx = blockIdx.x;               // n*16 + seg
    int n = bx >> 4, seg = bx & 15;
    int tid = threadIdx.x;
    int s16 = tid >> 6, t = tid & 63;
    const float* rp = g_R   + ((size_t)n << 10) * AOUT + (size_t)(seg << 6) * AOUT;
    const float* xp = g_X2t + ((size_t)n << 10) * XOUT + (size_t)(seg << 6) * XOUT;
    float q = 0.f;
#pragma unroll 4
    for (int jj = 0; jj < 64; ++jj)
        q = fmaf(rp[jj*AOUT + s16], xp[jj*XOUT + t], q);
    g_Qpart[(size_t)bx * 1024 + tid] = q;
    if (tid < 64) {
        float s = 0.f;
#pragma unroll 4
        for (int jj = 0; jj < 64; ++jj) s += xp[jj*XOUT + tid];
        g_SX2part[bx*64 + tid] = s;
    }
}

// ---------------- K_fin: T, K ---------------------------------------------
__global__ void __launch_bounds__(1024) k_fin(
    const float* __restrict__ OW, const float* __restrict__ outb)
{
    int n = blockIdx.x, tid = threadIdx.x;
    __shared__ float sx2[XOUT];
    __shared__ float sq[AOUT*XOUT];
    __shared__ float st_[AOUT*XOUT];
    __shared__ float sp[AOUT*XOUT];
    {
        float q = 0.f;
#pragma unroll
        for (int seg = 0; seg < 16; ++seg)
            q += g_Qpart[(size_t)((n<<4)|seg) * 1024 + tid];
        sq[tid] = q;
    }
    if (tid < 64) {
        float s = 0.f;
#pragma unroll
        for (int seg = 0; seg < 16; ++seg) s += g_SX2part[((n<<4)|seg)*64 + tid];
        sx2[tid] = s;
    }
    __syncthreads();
    int s16 = tid >> 6, t = tid & 63;
    {
        float v = 0.f;
#pragma unroll 4
        for (int u = 0; u < 64; ++u)
            v = fmaf(sx2[u], OW[((s16<<6)+u)*64 + t], v);
        st_[tid] = v;
        g_T[n*1024 + tid] = v;
    }
    {
        float p = 0.f;
#pragma unroll 4
        for (int u = 0; u < 64; ++u)
            p = fmaf(sq[(s16<<6)+u], OW[(((s16<<6)+u)<<6) + t], p);
        sp[tid] = p;
    }
    __syncthreads();
    if (tid < 64) {
        int tt = tid;
        float qo = 0.f, ct = 0.f;
#pragma unroll
        for (int s = 0; s < AOUT; ++s) {
            qo += sp[(s<<6) + tt];
            ct = fmaf(g_C[n*AOUT + s], st_[(s<<6) + tt], ct);
        }
        g_K[n*XOUT + tt] = (ct + qo) * (1.f/1024.f) + outb[tt];
    }
}

// ---------------- K3: main — 2 nodes per block ----------------------------
// dyn smem: sA [8][1028] (scratch/dump) | sAT0 [1024][8] | sAT1 [1024][8] | sW1 | sC0 | sC1
#define SMEM_MAIN ((8224 + 8192 + 8192 + 128 + 32) * 4)

__global__ void __launch_bounds__(256, 2) k_main(
    const float* __restrict__ A, const float* __restrict__ AW1,
    float* __restrict__ outAt)
{
    extern __shared__ float dyn[];
    float* sA   = dyn;                    // 8224 (staging scratch, later dump)
    float* sAT0 = dyn + 8224;             // 8192
    float* sAT1 = sAT0 + 8192;            // 8192
    float* sW1  = sAT1 + 8192;            // 128
    float* sC0  = sW1 + 128;              // 16
    float* sC1  = sC0 + 16;               // 16

    int bx = blockIdx.x;                  // 2048: n = bx>>9, i-pair
    int n = bx >> 9, i0 = (bx & 511) << 1;
    int tid = threadIdx.x, w = tid >> 5, l = tid & 31;

    if (tid < 128) sW1[tid] = AW1[tid];
    if (tid < AOUT) {
        float c = g_C[(n<<4) + tid];
        sC0[tid] = g_R[((size_t)((n<<10)|i0)     << 4) + tid] + c;
        sC1[tid] = g_R[((size_t)((n<<10)|(i0+1)) << 4) + tid] + c;
    }

#pragma unroll
    for (int ii = 0; ii < 2; ++ii) {
        int i = i0 + ii;
        // stage 8 A rows (coalesced float4)
        {
            const float4* A4 = (const float4*)A;
#pragma unroll
            for (int a = 0; a < AIN; ++a) {
                size_t ridx = ((size_t)((n<<3) + a) << 20) + ((size_t)i << 10);
                float4 v = A4[(ridx >> 2) + tid];
                *(float4*)(sA + a*1028 + (tid<<2)) = v;
            }
        }
        __syncthreads();
        // conflict-free transpose sA -> sAT[j][a]
        float* sAT = ii ? sAT1 : sAT0;
        {
            int a = tid & 7, jb = tid >> 3;
#pragma unroll
            for (int it = 0; it < 32; ++it) {
                int j = jb + (it << 5);
                sAT[(j << 3) + a] = sA[a*1028 + j];
            }
        }
        // ---- Phase A for node i (reads sA row-major) ----
        {
            const float* sC = ii ? sC1 : sC0;
            int j0 = tid << 2;
            ULL apk[8][2];
#pragma unroll
            for (int a = 0; a < AIN; ++a) {
                const ULL* rp = (const ULL*)(sA + a*1028 + j0);
                apk[a][0] = rp[0]; apk[a][1] = rp[1];
            }
            size_t obase = (((size_t)(n<<4)) << 20) + ((size_t)i << 10) + j0;
            const float* Rb = g_R + (((size_t)(n<<10)) << 4);
#pragma unroll
            for (int sg = 0; sg < 4; ++sg) {
                float4 c4 = *(const float4*)(sC + (sg<<2));
                ULL a0a,a0b,a1a,a1b,a2a,a2b,a3a,a3b;
                PACK2(a0a, c4.x); a0b = a0a;
                PACK2(a1a, c4.y); a1b = a1a;
                PACK2(a2a, c4.z); a2b = a2a;
                PACK2(a3a, c4.w); a3b = a3a;
#pragma unroll
                for (int a = 0; a < AIN; ++a) {
                    float4 w4 = *(const float4*)(sW1 + (a<<4) + (sg<<2));
                    ULL ws;
                    PACK2(ws, w4.x); FMA2(a0a, apk[a][0], ws); FMA2(a0b, apk[a][1], ws);
                    PACK2(ws, w4.y); FMA2(a1a, apk[a][0], ws); FMA2(a1b, apk[a][1], ws);
                    PACK2(ws, w4.z); FMA2(a2a, apk[a][0], ws); FMA2(a2b, apk[a][1], ws);
                    PACK2(ws, w4.w); FMA2(a3a, apk[a][0], ws); FMA2(a3b, apk[a][1], ws);
                }
                float4 r0 = *(const float4*)(Rb + ((size_t)(j0+0)<<4) + (sg<<2));
                float4 r1 = *(const float4*)(Rb + ((size_t)(j0+1)<<4) + (sg<<2));
                float4 r2 = *(const float4*)(Rb + ((size_t)(j0+2)<<4) + (sg<<2));
                float4 r3 = *(const float4*)(Rb + ((size_t)(j0+3)<<4) + (sg<<2));
                float v0,v1,v2,v3; float4 o;
                UNPACK2(v0,v1,a0a); UNPACK2(v2,v3,a0b);
                o.x=v0+r0.x; o.y=v1+r1.x; o.z=v2+r2.x; o.w=v3+r3.x;
                *(float4*)(outAt + obase + (((size_t)((sg<<2)+0)) << 20)) = o;
                UNPACK2(v0,v1,a1a); UNPACK2(v2,v3,a1b);
                o.x=v0+r0.y; o.y=v1+r1.y; o.z=v2+r2.y; o.w=v3+r3.y;
                *(float4*)(outAt + obase + (((size_t)((sg<<2)+1)) << 20)) = o;
                UNPACK2(v0,v1,a2a); UNPACK2(v2,v3,a2b);
                o.x=v0+r0.z; o.y=v1+r1.z; o.z=v2+r2.z; o.w=v3+r3.z;
                *(float4*)(outAt + obase + (((size_t)((sg<<2)+2)) << 20)) = o;
                UNPACK2(v0,v1,a3a); UNPACK2(v2,v3,a3b);
                o.x=v0+r0.w; o.y=v1+r1.w; o.z=v2+r2.w; o.w=v3+r3.w;
                *(float4*)(outAt + obase + (((size_t)((sg<<2)+3)) << 20)) = o;
            }
        }
        __syncthreads();   // all sA reads done before restage / dump reuse
    }

    // ---- Phase H: both nodes share X2t loads ----
    {
        int half = l >> 4, t0 = (l & 15) << 2;
        const float* X2 = g_X2t + (((size_t)n) << 16);
        ULL h0[4][4], h1[4][4];
#pragma unroll
        for (int p = 0; p < 4; ++p)
#pragma unroll
            for (int q = 0; q < 4; ++q) { h0[p][q] = 0ull; h1[p][q] = 0ull; }
        int jb = (w << 7) + half;
#pragma unroll 2
        for (int s2 = 0; s2 < 64; ++s2) {
            int j = jb + (s2 << 1);
            float4 x4 = *(const float4*)(X2 + ((size_t)j << 6) + t0);
            const ULL* ar0 = (const ULL*)(sAT0 + (j << 3));
            const ULL* ar1 = (const ULL*)(sAT1 + (j << 3));
            ULL b00 = ar0[0], b01 = ar0[1], b02 = ar0[2], b03 = ar0[3];
            ULL b10 = ar1[0], b11 = ar1[1], b12 = ar1[2], b13 = ar1[3];
            ULL xs;
            PACK2(xs, x4.x);
            FMA2(h0[0][0], b00, xs); FMA2(h0[1][0], b01, xs);
            FMA2(h0[2][0], b02, xs); FMA2(h0[3][0], b03, xs);
            FMA2(h1[0][0], b10, xs); FMA2(h1[1][0], b11, xs);
            FMA2(h1[2][0], b12, xs); FMA2(h1[3][0], b13, xs);
            PACK2(xs, x4.y);
            FMA2(h0[0][1], b00, xs); FMA2(h0[1][1], b01, xs);
            FMA2(h0[2][1], b02, xs); FMA2(h0[3][1], b03, xs);
            FMA2(h1[0][1], b10, xs); FMA2(h1[1][1], b11, xs);
            FMA2(h1[2][1], b12, xs); FMA2(h1[3][1], b13, xs);
            PACK2(xs, x4.z);
            FMA2(h0[0][2], b00, xs); FMA2(h0[1][2], b01, xs);
            FMA2(h0[2][2], b02, xs); FMA2(h0[3][2], b03, xs);
            FMA2(h1[0][2], b10, xs); FMA2(h1[1][2], b11, xs);
            FMA2(h1[2][2], b12, xs); FMA2(h1[3][2], b13, xs);
            PACK2(xs, x4.w);
            FMA2(h0[0][3], b00, xs); FMA2(h0[1][3], b01, xs);
            FMA2(h0[2][3], b02, xs); FMA2(h0[3][3], b03, xs);
            FMA2(h1[0][3], b10, xs); FMA2(h1[1][3], b11, xs);
            FMA2(h1[2][3], b12, xs); FMA2(h1[3][3], b13, xs);
        }
        // dump + reduce, node by node (reuse sA as [16][512])
        float* dump = sA;
        int rb = (((w << 1) + half) << 9) + t0;
#pragma unroll
        for (int ap = 0; ap < 4; ++ap) {
            float4 fe, fo;
            UNPACK2(fe.x, fo.x, h0[ap][0]);
            UNPACK2(fe.y, fo.y, h0[ap][1]);
            UNPACK2(fe.z, fo.z, h0[ap][2]);
            UNPACK2(fe.w, fo.w, h0[ap][3]);
            *(float4*)(dump + rb + ((ap<<1)<<6))     = fe;
            *(float4*)(dump + rb + (((ap<<1)|1)<<6)) = fo;
        }
        __syncthreads();
        size_t node0 = ((size_t)n << 10) | (size_t)i0;
#pragma unroll
        for (int k = 0; k < 2; ++k) {
            int idx = tid + (k << 8);
            float s = 0.f;
#pragma unroll
            for (int r = 0; r < 16; ++r) s += dump[(r << 9) + idx];
            g_H[(node0 << 9) + idx] = s;
        }
        __syncthreads();
#pragma unroll
        for (int ap = 0; ap < 4; ++ap) {
            float4 fe, fo;
            UNPACK2(fe.x, fo.x, h1[ap][0]);
            UNPACK2(fe.y, fo.y, h1[ap][1]);
            UNPACK2(fe.z, fo.z, h1[ap][2]);
            UNPACK2(fe.w, fo.w, h1[ap][3]);
            *(float4*)(dump + rb + ((ap<<1)<<6))     = fe;
            *(float4*)(dump + rb + (((ap<<1)|1)<<6)) = fo;
        }
        __syncthreads();
#pragma unroll
        for (int k = 0; k < 2; ++k) {
            int idx = tid + (k << 8);
            float s = 0.f;
#pragma unroll
            for (int r = 0; r < 16; ++r) s += dump[(r << 9) + idx];
            g_H[((node0 + 1) << 9) + idx] = s;
        }
    }
}

// ---------------- K4: out = H*OWH/n + R*T/n + K + X1t ---------------------
#define SMEM_OUT ((512*64 + 16*512) * 4)

__global__ void __launch_bounds__(256) k_out(float* __restrict__ out2)
{
    extern __shared__ float dyn[];
    float* sOWH = dyn;            // 32768 floats
    float* sH   = dyn + 32768;    // 8192 floats
    int bx = blockIdx.x;          // 256 blocks x 16 nodes
    int n = bx >> 6, tid = threadIdx.x;
    {
        const float4* s4 = (const float4*)g_OWH;
        float4* d4 = (float4*)sOWH;
#pragma unroll
        for (int k = 0; k < 32; ++k) d4[(k<<8)+tid] = s4[(k<<8)+tid];
        const float4* h4 = (const float4*)(g_H + ((size_t)bx << 13));
        float4* dh = (float4*)sH;
#pragma unroll
        for (int k = 0; k < 8; ++k) dh[(k<<8)+tid] = h4[(k<<8)+tid];
    }
    __syncthreads();
    int r = tid >> 4, q = tid & 15, t0 = q << 2;
    int node = (bx << 4) + r;
    ULL acc01 = 0ull, acc23 = 0ull;
    const float* hrow = sH + (r << 9);
#pragma unroll 4
    for (int au = 0; au < 512; ++au) {
        ULL hs; PACK2(hs, hrow[au]);
        const ULL* wr = (const ULL*)(sOWH + (au << 6) + t0);
        FMA2(acc01, hs, wr[0]); FMA2(acc23, hs, wr[1]);
    }
    float a0,a1,a2,a3;
    UNPACK2(a0,a1,acc01); UNPACK2(a2,a3,acc23);
    const float* Tn = g_T + (n << 10);
    const float* Rn = g_R + ((size_t)node << 4);
#pragma unroll
    for (int s = 0; s < AOUT; ++s) {
        float rv = Rn[s];
        float4 tv = *(const float4*)(Tn + (s << 6) + t0);
        a0 = fmaf(rv, tv.x, a0); a1 = fmaf(rv, tv.y, a1);
        a2 = fmaf(rv, tv.z, a2); a3 = fmaf(rv, tv.w, a3);
    }
    const float sc = 1.f/1024.f;
    size_t ob = ((size_t)node << 6) + t0;
    float4 kv  = *(const float4*)(g_K + (n << 6) + t0);
    float4 x1v = *(const float4*)(g_X1t + ob);
    float4 o;
    o.x = a0*sc + kv.x + x1v.x;  o.y = a1*sc + kv.y + x1v.y;
    o.z = a2*sc + kv.z + x1v.z;  o.w = a3*sc + kv.w + x1v.w;
    *(float4*)(out2 + ob) = o;
}

// ---------------- launch ---------------------------------------------------
extern "C" void kernel_launch(void* const* d_in, const int* in_sizes, int n_in,
                              void* d_out, int out_size)
{
    const float* A     = (const float*)d_in[0];
    const float* X     = (const float*)d_in[1];
    const float* AW1   = (const float*)d_in[2];
    const float* AW2   = (const float*)d_in[3];
    const float* AW3   = (const float*)d_in[4];
    const float* AW4   = (const float*)d_in[5];
    const float* AW5   = (const float*)d_in[6];
    const float* AW6   = (const float*)d_in[7];
    const float* AW7   = (const float*)d_in[8];
    const float* Abias = (const float*)d_in[9];
    const float* X1W1  = (const float*)d_in[10];
    const float* X1W2  = (const float*)d_in[11];
    const float* X1W3  = (const float*)d_in[12];
    const float* X1W4  = (const float*)d_in[13];
    const float* X1W5  = (const float*)d_in[14];
    const float* X1W6  = (const float*)d_in[15];
    const float* X1b   = (const float*)d_in[16];
    const float* X2W1  = (const float*)d_in[17];
    const float* X2W2  = (const float*)d_in[18];
    const float* X2W3  = (const float*)d_in[19];
    const float* X2W4  = (const float*)d_in[20];
    const float* X2W5  = (const float*)d_in[21];
    const float* X2W6  = (const float*)d_in[22];
    const float* X2b   = (const float*)d_in[23];
    const float* OW    = (const float*)d_in[24];
    const float* outb  = (const float*)d_in[25];

    float* outAt = (float*)d_out;
    float* out2  = outAt + (size_t)NB * AOUT * NN * NN;

    cudaFuncSetAttribute(k_main, cudaFuncAttributeMaxDynamicSharedMemorySize, SMEM_MAIN);
    cudaFuncSetAttribute(k_out,  cudaFuncAttributeMaxDynamicSharedMemorySize, SMEM_OUT);

    k_owh   <<<AIN, 256>>>(AW1, OW);
    k_reduce<<<NB*NN, 256>>>(A);
    k_pre_n <<<NB, 1024>>>(X, AW2, AW4, AW7, Abias);
    k_node  <<<NB*NN/16, 256>>>(X, AW3, AW5, AW6,
                            X1W1, X1W2, X1W3, X1W4, X1W5, X1W6, X1b,
                            X2W1, X2W2, X2W3, X2W4, X2W5, X2W6, X2b);
    k_q     <<<NB*16, 1024>>>();
    k_fin   <<<NB, 1024>>>(OW, outb);
    k_main  <<<NB*NN/2, 256, SMEM_MAIN>>>(A, AW1, outAt);
    k_out   <<<NB*NN/16, 256, SMEM_OUT>>>(out2);
}

// round 6
// speedup vs baseline: 2.4928x; 1.0528x over previous
#include <cuda_runtime.h>
#include <cstdint>

#define NB 4
#define NN 1024
#define AIN 8
#define AOUT 16
#define XIN 64
#define XOUT 64

typedef unsigned long long ULL;

// ---------------- scratch (device globals; no allocation) ----------------
__device__ float g_moc[NB*NN*AIN];
__device__ float g_dp [NB*NN*AIN];
__device__ float g_mdp[NB*AIN];
__device__ float g_mall[NB*AIN];
__device__ float g_mX [NB*XIN];
__device__ float g_C  [NB*AOUT];
__device__ float g_R  [NB*NN*AOUT];
__device__ float g_X1t[NB*NN*XOUT];
__device__ float g_X2t[NB*NN*XOUT];
__device__ float g_T  [NB*AOUT*XOUT];
__device__ float g_K  [NB*XOUT];
__device__ float g_OWH[AIN*XOUT*XOUT];
__device__ float g_H  [NB*NN*AIN*XOUT];
__device__ float g_Qpart[NB*16*AOUT*XOUT];
__device__ float g_SX2part[NB*16*XOUT];

#define FMA2(d,a,b) asm("fma.rn.f32x2 %0, %1, %2, %0;" : "+l"(d) : "l"(a), "l"(b))
#define PACK2(d,x)  asm("mov.b64 %0, {%1, %1};" : "=l"(d) : "f"(x))
#define PACKXY(d,x,y) asm("mov.b64 %0, {%1, %2};" : "=l"(d) : "f"(x), "f"(y))
#define UNPACK2(lo,hi,d) asm("mov.b64 {%0, %1}, %2;" : "=f"(lo), "=f"(hi) : "l"(d))

// ---------------- K1: row reductions over A -> moc, dp -------------------
__global__ void __launch_bounds__(256) k_reduce(const float* __restrict__ A)
{
    int bx = blockIdx.x;            // bx = n*1024 + i
    int n = bx >> 10, i = bx & 1023;
    int w = threadIdx.x >> 5, l = threadIdx.x & 31;
    size_t row = ((size_t)(n*AIN + w) << 20) + ((size_t)i << 10);
    const float4* p = (const float4*)(A + row);
    float s = 0.f;
#pragma unroll
    for (int k = 0; k < 8; ++k) {
        float4 v = p[k*32 + l];
        s += v.x + v.y + v.z + v.w;
    }
#pragma unroll
    for (int o = 16; o; o >>= 1) s += __shfl_xor_sync(0xffffffffu, s, o);
    if (l == 0) {
        g_moc[(bx << 3) + w] = s * (1.f/1024.f);
        g_dp [(bx << 3) + w] = A[row + i];
    }
}

// ---------------- K_owh -----------------------------------------------------
__global__ void __launch_bounds__(256) k_owh(
    const float* __restrict__ AW1, const float* __restrict__ OW)
{
    int a = blockIdx.x, tid = threadIdx.x;
    __shared__ float sw[AOUT];
    if (tid < AOUT) sw[tid] = AW1[a*AOUT + tid];
    __syncthreads();
    for (int idx = tid; idx < 4096; idx += 256) {
        int u = idx >> 6, t = idx & 63;
        float s = 0.f;
#pragma unroll
        for (int ss = 0; ss < AOUT; ++ss)
            s = fmaf(sw[ss], OW[((ss<<6)+u)*64 + t], s);
        g_OWH[((a<<6)+u)*64 + t] = s;
    }
}

// ---------------- K2a: per-n means + C -----------------------------------
__global__ void __launch_bounds__(1024) k_pre_n(
    const float* __restrict__ X,
    const float* __restrict__ AW2, const float* __restrict__ AW4,
    const float* __restrict__ AW7, const float* __restrict__ Abias)
{
    int n = blockIdx.x, tid = threadIdx.x;
    __shared__ float spart[16][64];
    __shared__ float sdpp[128][8];
    __shared__ float salp[128][8];
    __shared__ float smx[XIN], smdp[AIN], smal[AIN];

    {
        int col = tid & 63, seg = tid >> 6;
        const float* xp = X + ((size_t)n << 16) + (size_t)(seg << 6) * XIN + col;
        float s = 0.f;
#pragma unroll 4
        for (int r = 0; r < 64; ++r) s += xp[(size_t)r * XIN];
        spart[seg][col] = s;
    }
    {
        int a = tid & 7, seg = tid >> 3;
        const float* dpp = g_dp  + (n << 13) + (seg << 6) + a;
        const float* mcp = g_moc + (n << 13) + (seg << 6) + a;
        float s1 = 0.f, s2 = 0.f;
#pragma unroll
        for (int r = 0; r < 8; ++r) { s1 += dpp[r*8]; s2 += mcp[r*8]; }
        sdpp[seg][a] = s1; salp[seg][a] = s2;
    }
    __syncthreads();
    if (tid < 64) {
        float s = 0.f;
#pragma unroll
        for (int k = 0; k < 16; ++k) s += spart[k][tid];
        smx[tid] = s * (1.f/1024.f);
        g_mX[n*XIN + tid] = smx[tid];
    } else if (tid >= 64 && tid < 72) {
        int a = tid - 64; float s = 0.f;
        for (int k = 0; k < 128; ++k) s += sdpp[k][a];
        smdp[a] = s * (1.f/1024.f); g_mdp[n*AIN + a] = smdp[a];
    } else if (tid >= 72 && tid < 80) {
        int a = tid - 72; float s = 0.f;
        for (int k = 0; k < 128; ++k) s += salp[k][a];
        smal[a] = s * (1.f/1024.f); g_mall[n*AIN + a] = smal[a];
    }
    __syncthreads();
    if (tid < AOUT) {
        int s16 = tid; float c = Abias[s16];
#pragma unroll
        for (int a = 0; a < AIN; ++a)
            c = fmaf(smal[a], AW2[a*AOUT+s16], fmaf(smdp[a], AW4[a*AOUT+s16], c));
        for (int k = 0; k < XIN; ++k) c = fmaf(smx[k], AW7[k*AOUT+s16], c);
        g_C[n*AOUT + s16] = c;
    }
}

// ---------------- K2b: per-node R, X1t, X2t (16 nodes/block, 4t/lane) ----
__global__ void __launch_bounds__(256) k_node(
    const float* __restrict__ X,
    const float* __restrict__ AW3, const float* __restrict__ AW5, const float* __restrict__ AW6,
    const float* __restrict__ X1W1, const float* __restrict__ X1W2, const float* __restrict__ X1W3,
    const float* __restrict__ X1W4, const float* __restrict__ X1W5, const float* __restrict__ X1W6,
    const float* __restrict__ X1b,
    const float* __restrict__ X2W1, const float* __restrict__ X2W2, const float* __restrict__ X2W3,
    const float* __restrict__ X2W4, const float* __restrict__ X2W5, const float* __restrict__ X2W6,
    const float* __restrict__ X2b)
{
    int bx = blockIdx.x;                 // 256 blocks x 16 nodes
    int tid = threadIdx.x;
    int nl = tid >> 4, q = tid & 15, t0 = q << 2;
    int node0 = bx << 4;
    int n = node0 >> 10;
    int node = node0 + nl;

    __shared__ float sx[16][64];
    __shared__ float smoc[16][8], sdpv[16][8];
    __shared__ float smx[64], smdp[8], smal[8];

    {   // stage X: 1024 floats coalesced
        const float4* xp = (const float4*)(X + ((size_t)node0 << 6));
        ((float4*)&sx[0][0])[tid] = xp[tid];
    }
    if (tid < 128) {
        ((float*)smoc)[tid] = g_moc[(node0<<3) + tid];
        ((float*)sdpv)[tid] = g_dp [(node0<<3) + tid];
    }
    if (tid >= 128 && tid < 192) smx[tid-128] = g_mX[(n<<6) + tid-128];
    if (tid >= 192 && tid < 200) smdp[tid-192] = g_mdp[(n<<3) + tid-192];
    if (tid >= 200 && tid < 208) smal[tid-200] = g_mall[(n<<3) + tid-200];
    __syncthreads();

    float4 b1 = *(const float4*)(X1b + t0);
    float4 b2 = *(const float4*)(X2b + t0);
    ULL x1a, x1b4, x2a, x2b4;
    PACKXY(x1a, b1.x, b1.y); PACKXY(x1b4, b1.z, b1.w);
    PACKXY(x2a, b2.x, b2.y); PACKXY(x2b4, b2.z, b2.w);

#pragma unroll 4
    for (int k = 0; k < XIN; ++k) {
        float xk = sx[nl][k], mk = smx[k];
        ULL xkp, mkp; PACK2(xkp, xk); PACK2(mkp, mk);
        float4 w; ULL wlo, whi;
        w = *(const float4*)(X1W1 + (k<<6) + t0);
        PACKXY(wlo, w.x, w.y); PACKXY(whi, w.z, w.w);
        FMA2(x1a, xkp, wlo); FMA2(x1b4, xkp, whi);
        w = *(const float4*)(X2W1 + (k<<6) + t0);
        PACKXY(wlo, w.x, w.y); PACKXY(whi, w.z, w.w);
        FMA2(x2a, xkp, wlo); FMA2(x2b4, xkp, whi);
        w = *(const float4*)(X1W2 + (k<<6) + t0);
        PACKXY(wlo, w.x, w.y); PACKXY(whi, w.z, w.w);
        FMA2(x1a, mkp, wlo); FMA2(x1b4, mkp, whi);
        w = *(const float4*)(X2W2 + (k<<6) + t0);
        PACKXY(wlo, w.x, w.y); PACKXY(whi, w.z, w.w);
        FMA2(x2a, mkp, wlo); FMA2(x2b4, mkp, whi);
    }
#pragma unroll
    for (int a = 0; a < AIN; ++a) {
        ULL v1, v2, v3, v4;
        PACK2(v1, smoc[nl][a]); PACK2(v2, sdpv[nl][a]);
        PACK2(v3, smdp[a]);     PACK2(v4, smal[a]);
        float4 w; ULL wlo, whi;
        w = *(const float4*)(X1W3 + (a<<6) + t0);
        PACKXY(wlo, w.x, w.y); PACKXY(whi, w.z, w.w);
        FMA2(x1a, v1, wlo); FMA2(x1b4, v1, whi);
        w = *(const float4*)(X2W3 + (a<<6) + t0);
        PACKXY(wlo, w.x, w.y); PACKXY(whi, w.z, w.w);
        FMA2(x2a, v1, wlo); FMA2(x2b4, v1, whi);
        w = *(const float4*)(X1W4 + (a<<6) + t0);
        PACKXY(wlo, w.x, w.y); PACKXY(whi, w.z, w.w);
        FMA2(x1a, v2, wlo); FMA2(x1b4, v2, whi);
        w = *(const float4*)(X2W4 + (a<<6) + t0);
        PACKXY(wlo, w.x, w.y); PACKXY(whi, w.z, w.w);
        FMA2(x2a, v2, wlo); FMA2(x2b4, v2, whi);
        w = *(const float4*)(X1W5 + (a<<6) + t0);
        PACKXY(wlo, w.x, w.y); PACKXY(whi, w.z, w.w);
        FMA2(x1a, v3, wlo); FMA2(x1b4, v3, whi);
        w = *(const float4*)(X2W5 + (a<<6) + t0);
        PACKXY(wlo, w.x, w.y); PACKXY(whi, w.z, w.w);
        FMA2(x2a, v3, wlo); FMA2(x2b4, v3, whi);
        w = *(const float4*)(X1W6 + (a<<6) + t0);
        PACKXY(wlo, w.x, w.y); PACKXY(whi, w.z, w.w);
        FMA2(x1a, v4, wlo); FMA2(x1b4, v4, whi);
        w = *(const float4*)(X2W6 + (a<<6) + t0);
        PACKXY(wlo, w.x, w.y); PACKXY(whi, w.z, w.w);
        FMA2(x2a, v4, wlo); FMA2(x2b4, v4, whi);
    }
    {
        float4 o1, o2;
        UNPACK2(o1.x, o1.y, x1a); UNPACK2(o1.z, o1.w, x1b4);
        UNPACK2(o2.x, o2.y, x2a); UNPACK2(o2.z, o2.w, x2b4);
        *(float4*)(g_X1t + ((size_t)node << 6) + t0) = o1;
        *(float4*)(g_X2t + ((size_t)node << 6) + t0) = o2;
    }
    {   // R: lane q computes s = q for its node
        float r = 0.f;
#pragma unroll
        for (int a = 0; a < AIN; ++a) {
            r = fmaf(smoc[nl][a], AW3[a*AOUT+q], r);
            r = fmaf(sdpv[nl][a], AW5[a*AOUT+q], r);
        }
#pragma unroll 4
        for (int k = 0; k < XIN; ++k) r = fmaf(sx[nl][k], AW6[k*AOUT+q], r);
        g_R[((size_t)node << 4) + q] = r;
    }
}

// ---------------- K_q: Q and SX2 partials ---------------------------------
__global__ void __launch_bounds__(1024) k_q()
{
    int bx = blockIdx.x;               // n*16 + seg
    int n = bx >> 4, seg = bx & 15;
    int tid = threadIdx.x;
    int s16 = tid >> 6, t = tid & 63;
    const float* rp = g_R   + ((size_t)n << 10) * AOUT + (size_t)(seg << 6) * AOUT;
    const float* xp = g_X2t + ((size_t)n << 10) * XOUT + (size_t)(seg << 6) * XOUT;
    float q = 0.f;
#pragma unroll 4
    for (int jj = 0; jj < 64; ++jj)
        q = fmaf(rp[jj*AOUT + s16], xp[jj*XOUT + t], q);
    g_Qpart[(size_t)bx * 1024 + tid] = q;
    if (tid < 64) {
        float s = 0.f;
#pragma unroll 4
        for (int jj = 0; jj < 64; ++jj) s += xp[jj*XOUT + tid];
        g_SX2part[bx*64 + tid] = s;
    }
}

// ---------------- K_fin: T, K ---------------------------------------------
__global__ void __launch_bounds__(1024) k_fin(
    const float* __restrict__ OW, const float* __restrict__ outb)
{
    int n = blockIdx.x, tid = threadIdx.x;
    __shared__ float sx2[XOUT];
    __shared__ float sq[AOUT*XOUT];
    __shared__ float st_[AOUT*XOUT];
    __shared__ float sp[AOUT*XOUT];
    {
        float q = 0.f;
#pragma unroll
        for (int seg = 0; seg < 16; ++seg)
            q += g_Qpart[(size_t)((n<<4)|seg) * 1024 + tid];
        sq[tid] = q;
    }
    if (tid < 64) {
        float s = 0.f;
#pragma unroll
        for (int seg = 0; seg < 16; ++seg) s += g_SX2part[((n<<4)|seg)*64 + tid];
        sx2[tid] = s;
    }
    __syncthreads();
    int s16 = tid >> 6, t = tid & 63;
    {
        float v = 0.f;
#pragma unroll 4
        for (int u = 0; u < 64; ++u)
            v = fmaf(sx2[u], OW[((s16<<6)+u)*64 + t], v);
        st_[tid] = v;
        g_T[n*1024 + tid] = v;
    }
    {
        float p = 0.f;
#pragma unroll 4
        for (int u = 0; u < 64; ++u)
            p = fmaf(sq[(s16<<6)+u], OW[(((s16<<6)+u)<<6) + t], p);
        sp[tid] = p;
    }
    __syncthreads();
    if (tid < 64) {
        int tt = tid;
        float qo = 0.f, ct = 0.f;
#pragma unroll
        for (int s = 0; s < AOUT; ++s) {
            qo += sp[(s<<6) + tt];
            ct = fmaf(g_C[n*AOUT + s], st_[(s<<6) + tt], ct);
        }
        g_K[n*XOUT + tt] = (ct + qo) * (1.f/1024.f) + outb[tt];
    }
}

// ---------------- K3: main — 2 nodes per block ----------------------------
#define SMEM_MAIN ((8224 + 8192 + 8192 + 128 + 32) * 4)

__global__ void __launch_bounds__(256, 2) k_main(
    const float* __restrict__ A, const float* __restrict__ AW1,
    float* __restrict__ outAt)
{
    extern __shared__ float dyn[];
    float* sA   = dyn;                    // 8224 (staging scratch, later dump)
    float* sAT0 = dyn + 8224;             // 8192
    float* sAT1 = sAT0 + 8192;            // 8192
    float* sW1  = sAT1 + 8192;            // 128
    float* sC0  = sW1 + 128;              // 16
    float* sC1  = sC0 + 16;               // 16

    int bx = blockIdx.x;                  // 2048: n = bx>>9, i-pair
    int n = bx >> 9, i0 = (bx & 511) << 1;
    int tid = threadIdx.x, w = tid >> 5, l = tid & 31;

    if (tid < 128) sW1[tid] = AW1[tid];
    if (tid < AOUT) {
        float c = g_C[(n<<4) + tid];
        sC0[tid] = g_R[((size_t)((n<<10)|i0)     << 4) + tid] + c;
        sC1[tid] = g_R[((size_t)((n<<10)|(i0+1)) << 4) + tid] + c;
    }

#pragma unroll
    for (int ii = 0; ii < 2; ++ii) {
        int i = i0 + ii;
        // stage 8 A rows (coalesced float4)
        {
            const float4* A4 = (const float4*)A;
#pragma unroll
            for (int a = 0; a < AIN; ++a) {
                size_t ridx = ((size_t)((n<<3) + a) << 20) + ((size_t)i << 10);
                float4 v = A4[(ridx >> 2) + tid];
                *(float4*)(sA + a*1028 + (tid<<2)) = v;
            }
        }
        __syncthreads();
        // conflict-free transpose sA -> sAT[j][a]
        float* sAT = ii ? sAT1 : sAT0;
        {
            int a = tid & 7, jb2 = tid >> 3;
#pragma unroll
            for (int it = 0; it < 32; ++it) {
                int j = jb2 + (it << 5);
                sAT[(j << 3) + a] = sA[a*1028 + j];
            }
        }
        // ---- Phase A for node i (reads sA row-major) ----
        {
            const float* sC = ii ? sC1 : sC0;
            int j0 = tid << 2;
            ULL apk[8][2];
#pragma unroll
            for (int a = 0; a < AIN; ++a) {
                const ULL* rp = (const ULL*)(sA + a*1028 + j0);
                apk[a][0] = rp[0]; apk[a][1] = rp[1];
            }
            size_t obase = (((size_t)(n<<4)) << 20) + ((size_t)i << 10) + j0;
            const float* Rb = g_R + (((size_t)(n<<10)) << 4);
#pragma unroll
            for (int sg = 0; sg < 4; ++sg) {
                float4 c4 = *(const float4*)(sC + (sg<<2));
                ULL a0a,a0b,a1a,a1b,a2a,a2b,a3a,a3b;
                PACK2(a0a, c4.x); a0b = a0a;
                PACK2(a1a, c4.y); a1b = a1a;
                PACK2(a2a, c4.z); a2b = a2a;
                PACK2(a3a, c4.w); a3b = a3a;
#pragma unroll
                for (int a = 0; a < AIN; ++a) {
                    float4 w4 = *(const float4*)(sW1 + (a<<4) + (sg<<2));
                    ULL ws;
                    PACK2(ws, w4.x); FMA2(a0a, apk[a][0], ws); FMA2(a0b, apk[a][1], ws);
                    PACK2(ws, w4.y); FMA2(a1a, apk[a][0], ws); FMA2(a1b, apk[a][1], ws);
                    PACK2(ws, w4.z); FMA2(a2a, apk[a][0], ws); FMA2(a2b, apk[a][1], ws);
                    PACK2(ws, w4.w); FMA2(a3a, apk[a][0], ws); FMA2(a3b, apk[a][1], ws);
                }
                float4 r0 = *(const float4*)(Rb + ((size_t)(j0+0)<<4) + (sg<<2));
                float4 r1 = *(const float4*)(Rb + ((size_t)(j0+1)<<4) + (sg<<2));
                float4 r2 = *(const float4*)(Rb + ((size_t)(j0+2)<<4) + (sg<<2));
                float4 r3 = *(const float4*)(Rb + ((size_t)(j0+3)<<4) + (sg<<2));
                float v0,v1,v2,v3; float4 o;
                UNPACK2(v0,v1,a0a); UNPACK2(v2,v3,a0b);
                o.x=v0+r0.x; o.y=v1+r1.x; o.z=v2+r2.x; o.w=v3+r3.x;
                *(float4*)(outAt + obase + (((size_t)((sg<<2)+0)) << 20)) = o;
                UNPACK2(v0,v1,a1a); UNPACK2(v2,v3,a1b);
                o.x=v0+r0.y; o.y=v1+r1.y; o.z=v2+r2.y; o.w=v3+r3.y;
                *(float4*)(outAt + obase + (((size_t)((sg<<2)+1)) << 20)) = o;
                UNPACK2(v0,v1,a2a); UNPACK2(v2,v3,a2b);
                o.x=v0+r0.z; o.y=v1+r1.z; o.z=v2+r2.z; o.w=v3+r3.z;
                *(float4*)(outAt + obase + (((size_t)((sg<<2)+2)) << 20)) = o;
                UNPACK2(v0,v1,a3a); UNPACK2(v2,v3,a3b);
                o.x=v0+r0.w; o.y=v1+r1.w; o.z=v2+r2.w; o.w=v3+r3.w;
                *(float4*)(outAt + obase + (((size_t)((sg<<2)+3)) << 20)) = o;
            }
        }
        __syncthreads();   // all sA reads done before restage / dump reuse
    }

    // ---- Phase H: both nodes share X2t loads; SW-pipelined LDG (MLP 4-8) ----
    {
        int half = l >> 4, t0 = (l & 15) << 2;
        int jb = (w << 7) + half;
        const float* Xb = g_X2t + (((size_t)n) << 16) + ((size_t)jb << 6) + t0;
        ULL h0[4][4], h1[4][4];
#pragma unroll
        for (int p = 0; p < 4; ++p)
#pragma unroll
            for (int q = 0; q < 4; ++q) { h0[p][q] = 0ull; h1[p][q] = 0ull; }

        float4 xa[4];
#pragma unroll
        for (int u = 0; u < 4; ++u) xa[u] = *(const float4*)(Xb + (u << 7));

#pragma unroll 2
        for (int s4 = 0; s4 < 16; ++s4) {
            int nb = ((s4 + 1) & 15) << 2;       // wrap prefetch (last iter dummy, in-bounds)
            float4 xb[4];
#pragma unroll
            for (int u = 0; u < 4; ++u)
                xb[u] = *(const float4*)(Xb + ((nb + u) << 7));
#pragma unroll
            for (int u = 0; u < 4; ++u) {
                int j = jb + (((s4 << 2) + u) << 1);
                const ULL* ar0 = (const ULL*)(sAT0 + (j << 3));
                const ULL* ar1 = (const ULL*)(sAT1 + (j << 3));
                ULL b00 = ar0[0], b01 = ar0[1], b02 = ar0[2], b03 = ar0[3];
                ULL b10 = ar1[0], b11 = ar1[1], b12 = ar1[2], b13 = ar1[3];
                ULL xs;
                PACK2(xs, xa[u].x);
                FMA2(h0[0][0], b00, xs); FMA2(h0[1][0], b01, xs);
                FMA2(h0[2][0], b02, xs); FMA2(h0[3][0], b03, xs);
                FMA2(h1[0][0], b10, xs); FMA2(h1[1][0], b11, xs);
                FMA2(h1[2][0], b12, xs); FMA2(h1[3][0], b13, xs);
                PACK2(xs, xa[u].y);
                FMA2(h0[0][1], b00, xs); FMA2(h0[1][1], b01, xs);
                FMA2(h0[2][1], b02, xs); FMA2(h0[3][1], b03, xs);
                FMA2(h1[0][1], b10, xs); FMA2(h1[1][1], b11, xs);
                FMA2(h1[2][1], b12, xs); FMA2(h1[3][1], b13, xs);
                PACK2(xs, xa[u].z);
                FMA2(h0[0][2], b00, xs); FMA2(h0[1][2], b01, xs);
                FMA2(h0[2][2], b02, xs); FMA2(h0[3][2], b03, xs);
                FMA2(h1[0][2], b10, xs); FMA2(h1[1][2], b11, xs);
                FMA2(h1[2][2], b12, xs); FMA2(h1[3][2], b13, xs);
                PACK2(xs, xa[u].w);
                FMA2(h0[0][3], b00, xs); FMA2(h0[1][3], b01, xs);
                FMA2(h0[2][3], b02, xs); FMA2(h0[3][3], b03, xs);
                FMA2(h1[0][3], b10, xs); FMA2(h1[1][3], b11, xs);
                FMA2(h1[2][3], b12, xs); FMA2(h1[3][3], b13, xs);
            }
#pragma unroll
            for (int u = 0; u < 4; ++u) xa[u] = xb[u];
        }

        // dump + reduce, node by node (reuse sA as [16][512])
        float* dump = sA;
        int rb = (((w << 1) + half) << 9) + t0;
#pragma unroll
        for (int ap = 0; ap < 4; ++ap) {
            float4 fe, fo;
            UNPACK2(fe.x, fo.x, h0[ap][0]);
            UNPACK2(fe.y, fo.y, h0[ap][1]);
            UNPACK2(fe.z, fo.z, h0[ap][2]);
            UNPACK2(fe.w, fo.w, h0[ap][3]);
            *(float4*)(dump + rb + ((ap<<1)<<6))     = fe;
            *(float4*)(dump + rb + (((ap<<1)|1)<<6)) = fo;
        }
        __syncthreads();
        size_t node0 = ((size_t)n << 10) | (size_t)i0;
#pragma unroll
        for (int k = 0; k < 2; ++k) {
            int idx = tid + (k << 8);
            float s = 0.f;
#pragma unroll
            for (int r = 0; r < 16; ++r) s += dump[(r << 9) + idx];
            g_H[(node0 << 9) + idx] = s;
        }
        __syncthreads();
#pragma unroll
        for (int ap = 0; ap < 4; ++ap) {
            float4 fe, fo;
            UNPACK2(fe.x, fo.x, h1[ap][0]);
            UNPACK2(fe.y, fo.y, h1[ap][1]);
            UNPACK2(fe.z, fo.z, h1[ap][2]);
            UNPACK2(fe.w, fo.w, h1[ap][3]);
            *(float4*)(dump + rb + ((ap<<1)<<6))     = fe;
            *(float4*)(dump + rb + (((ap<<1)|1)<<6)) = fo;
        }
        __syncthreads();
#pragma unroll
        for (int k = 0; k < 2; ++k) {
            int idx = tid + (k << 8);
            float s = 0.f;
#pragma unroll
            for (int r = 0; r < 16; ++r) s += dump[(r << 9) + idx];
            g_H[((node0 + 1) << 9) + idx] = s;
        }
    }
}

// ---------------- K4: out = H*OWH/n + R*T/n + K + X1t ---------------------
#define SMEM_OUT ((512*64 + 16*512) * 4)

__global__ void __launch_bounds__(256) k_out(float* __restrict__ out2)
{
    extern __shared__ float dyn[];
    float* sOWH = dyn;            // 32768 floats
    float* sH   = dyn + 32768;    // 8192 floats
    int bx = blockIdx.x;          // 256 blocks x 16 nodes
    int n = bx >> 6, tid = threadIdx.x;
    {
        const float4* s4 = (const float4*)g_OWH;
        float4* d4 = (float4*)sOWH;
#pragma unroll
        for (int k = 0; k < 32; ++k) d4[(k<<8)+tid] = s4[(k<<8)+tid];
        const float4* h4 = (const float4*)(g_H + ((size_t)bx << 13));
        float4* dh = (float4*)sH;
#pragma unroll
        for (int k = 0; k < 8; ++k) dh[(k<<8)+tid] = h4[(k<<8)+tid];
    }
    __syncthreads();
    int r = tid >> 4, q = tid & 15, t0 = q << 2;
    int node = (bx << 4) + r;
    ULL acc01 = 0ull, acc23 = 0ull;
    const float* hrow = sH + (r << 9);
#pragma unroll 4
    for (int au = 0; au < 512; ++au) {
        ULL hs; PACK2(hs, hrow[au]);
        const ULL* wr = (const ULL*)(sOWH + (au << 6) + t0);
        FMA2(acc01, hs, wr[0]); FMA2(acc23, hs, wr[1]);
    }
    float a0,a1,a2,a3;
    UNPACK2(a0,a1,acc01); UNPACK2(a2,a3,acc23);
    const float* Tn = g_T + (n << 10);
    const float* Rn = g_R + ((size_t)node << 4);
#pragma unroll
    for (int s = 0; s < AOUT; ++s) {
        float rv = Rn[s];
        float4 tv = *(const float4*)(Tn + (s << 6) + t0);
        a0 = fmaf(rv, tv.x, a0); a1 = fmaf(rv, tv.y, a1);
        a2 = fmaf(rv, tv.z, a2); a3 = fmaf(rv, tv.w, a3);
    }
    const float sc = 1.f/1024.f;
    size_t ob = ((size_t)node << 6) + t0;
    float4 kv  = *(const float4*)(g_K + (n << 6) + t0);
    float4 x1v = *(const float4*)(g_X1t + ob);
    float4 o;
    o.x = a0*sc + kv.x + x1v.x;  o.y = a1*sc + kv.y + x1v.y;
    o.z = a2*sc + kv.z + x1v.z;  o.w = a3*sc + kv.w + x1v.w;
    *(float4*)(out2 + ob) = o;
}

// ---------------- launch ---------------------------------------------------
extern "C" void kernel_launch(void* const* d_in, const int* in_sizes, int n_in,
                              void* d_out, int out_size)
{
    const float* A     = (const float*)d_in[0];
    const float* X     = (const float*)d_in[1];
    const float* AW1   = (const float*)d_in[2];
    const float* AW2   = (const float*)d_in[3];
    const float* AW3   = (const float*)d_in[4];
    const float* AW4   = (const float*)d_in[5];
    const float* AW5   = (const float*)d_in[6];
    const float* AW6   = (const float*)d_in[7];
    const float* AW7   = (const float*)d_in[8];
    const float* Abias = (const float*)d_in[9];
    const float* X1W1  = (const float*)d_in[10];
    const float* X1W2  = (const float*)d_in[11];
    const float* X1W3  = (const float*)d_in[12];
    const float* X1W4  = (const float*)d_in[13];
    const float* X1W5  = (const float*)d_in[14];
    const float* X1W6  = (const float*)d_in[15];
    const float* X1b   = (const float*)d_in[16];
    const float* X2W1  = (const float*)d_in[17];
    const float* X2W2  = (const float*)d_in[18];
    const float* X2W3  = (const float*)d_in[19];
    const float* X2W4  = (const float*)d_in[20];
    const float* X2W5  = (const float*)d_in[21];
    const float* X2W6  = (const float*)d_in[22];
    const float* X2b   = (const float*)d_in[23];
    const float* OW    = (const float*)d_in[24];
    const float* outb  = (const float*)d_in[25];

    float* outAt = (float*)d_out;
    float* out2  = outAt + (size_t)NB * AOUT * NN * NN;

    cudaFuncSetAttribute(k_main, cudaFuncAttributeMaxDynamicSharedMemorySize, SMEM_MAIN);
    cudaFuncSetAttribute(k_out,  cudaFuncAttributeMaxDynamicSharedMemorySize, SMEM_OUT);

    // NOTE: ncu captures the 4th launch -> k_main is placed 4th (deps still hold)
    k_reduce<<<NB*NN, 256>>>(A);
    k_pre_n <<<NB, 1024>>>(X, AW2, AW4, AW7, Abias);
    k_node  <<<NB*NN/16, 256>>>(X, AW3, AW5, AW6,
                            X1W1, X1W2, X1W3, X1W4, X1W5, X1W6, X1b,
                            X2W1, X2W2, X2W3, X2W4, X2W5, X2W6, X2b);
    k_main  <<<NB*NN/2, 256, SMEM_MAIN>>>(A, AW1, outAt);
    k_owh   <<<AIN, 256>>>(AW1, OW);
    k_q     <<<NB*16, 1024>>>();
    k_fin   <<<NB, 1024>>>(OW, outb);
    k_out   <<<NB*NN/16, 256, SMEM_OUT>>>(out2);
}

// round 7
// speedup vs baseline: 2.8765x; 1.1539x over previous
#include <cuda_runtime.h>
#include <cstdint>

#define NB 4
#define NN 1024
#define AIN 8
#define AOUT 16
#define XIN 64
#define XOUT 64

typedef unsigned long long ULL;

// ---------------- scratch (device globals; no allocation) ----------------
__device__ float g_moc[NB*NN*AIN];
__device__ float g_dp [NB*NN*AIN];
__device__ float g_mdp[NB*AIN];
__device__ float g_mall[NB*AIN];
__device__ float g_mX [NB*XIN];
__device__ float g_C  [NB*AOUT];
__device__ float g_R  [NB*NN*AOUT];
__device__ float g_Rt [NB*AOUT*NN];      // R transposed: [n][s][j]
__device__ float g_X1t[NB*NN*XOUT];
__device__ float g_X2t[NB*NN*XOUT];
__device__ float g_T  [NB*AOUT*XOUT];
__device__ float g_K  [NB*XOUT];
__device__ float g_OWH[AIN*XOUT*XOUT];
__device__ float g_H  [NB*NN*AIN*XOUT];
__device__ float g_Qpart[NB*16*AOUT*XOUT];
__device__ float g_SX2part[NB*16*XOUT];

#define FMA2(d,a,b) asm("fma.rn.f32x2 %0, %1, %2, %0;" : "+l"(d) : "l"(a), "l"(b))
#define PACK2(d,x)  asm("mov.b64 %0, {%1, %1};" : "=l"(d) : "f"(x))
#define PACKXY(d,x,y) asm("mov.b64 %0, {%1, %2};" : "=l"(d) : "f"(x), "f"(y))
#define UNPACK2(lo,hi,d) asm("mov.b64 {%0, %1}, %2;" : "=f"(lo), "=f"(hi) : "l"(d))

// ---------------- K1: row reductions over A -> moc, dp -------------------
__global__ void __launch_bounds__(256) k_reduce(const float* __restrict__ A)
{
    int bx = blockIdx.x;            // bx = n*1024 + i
    int n = bx >> 10, i = bx & 1023;
    int w = threadIdx.x >> 5, l = threadIdx.x & 31;
    size_t row = ((size_t)(n*AIN + w) << 20) + ((size_t)i << 10);
    const float4* p = (const float4*)(A + row);
    float s = 0.f;
#pragma unroll
    for (int k = 0; k < 8; ++k) {
        float4 v = p[k*32 + l];
        s += v.x + v.y + v.z + v.w;
    }
#pragma unroll
    for (int o = 16; o; o >>= 1) s += __shfl_xor_sync(0xffffffffu, s, o);
    if (l == 0) {
        g_moc[(bx << 3) + w] = s * (1.f/1024.f);
        g_dp [(bx << 3) + w] = A[row + i];
    }
}

// ---------------- K_owh -----------------------------------------------------
__global__ void __launch_bounds__(256) k_owh(
    const float* __restrict__ AW1, const float* __restrict__ OW)
{
    int a = blockIdx.x, tid = threadIdx.x;
    __shared__ float sw[AOUT];
    if (tid < AOUT) sw[tid] = AW1[a*AOUT + tid];
    __syncthreads();
    for (int idx = tid; idx < 4096; idx += 256) {
        int u = idx >> 6, t = idx & 63;
        float s = 0.f;
#pragma unroll
        for (int ss = 0; ss < AOUT; ++ss)
            s = fmaf(sw[ss], OW[((ss<<6)+u)*64 + t], s);
        g_OWH[((a<<6)+u)*64 + t] = s;
    }
}

// ---------------- K2a: per-n means + C -----------------------------------
__global__ void __launch_bounds__(1024) k_pre_n(
    const float* __restrict__ X,
    const float* __restrict__ AW2, const float* __restrict__ AW4,
    const float* __restrict__ AW7, const float* __restrict__ Abias)
{
    int n = blockIdx.x, tid = threadIdx.x;
    __shared__ float spart[16][64];
    __shared__ float sdpp[128][8];
    __shared__ float salp[128][8];
    __shared__ float smx[XIN], smdp[AIN], smal[AIN];

    {
        int col = tid & 63, seg = tid >> 6;
        const float* xp = X + ((size_t)n << 16) + (size_t)(seg << 6) * XIN + col;
        float s = 0.f;
#pragma unroll 4
        for (int r = 0; r < 64; ++r) s += xp[(size_t)r * XIN];
        spart[seg][col] = s;
    }
    {
        int a = tid & 7, seg = tid >> 3;
        const float* dpp = g_dp  + (n << 13) + (seg << 6) + a;
        const float* mcp = g_moc + (n << 13) + (seg << 6) + a;
        float s1 = 0.f, s2 = 0.f;
#pragma unroll
        for (int r = 0; r < 8; ++r) { s1 += dpp[r*8]; s2 += mcp[r*8]; }
        sdpp[seg][a] = s1; salp[seg][a] = s2;
    }
    __syncthreads();
    if (tid < 64) {
        float s = 0.f;
#pragma unroll
        for (int k = 0; k < 16; ++k) s += spart[k][tid];
        smx[tid] = s * (1.f/1024.f);
        g_mX[n*XIN + tid] = smx[tid];
    } else if (tid >= 64 && tid < 72) {
        int a = tid - 64; float s = 0.f;
        for (int k = 0; k < 128; ++k) s += sdpp[k][a];
        smdp[a] = s * (1.f/1024.f); g_mdp[n*AIN + a] = smdp[a];
    } else if (tid >= 72 && tid < 80) {
        int a = tid - 72; float s = 0.f;
        for (int k = 0; k < 128; ++k) s += salp[k][a];
        smal[a] = s * (1.f/1024.f); g_mall[n*AIN + a] = smal[a];
    }
    __syncthreads();
    if (tid < AOUT) {
        int s16 = tid; float c = Abias[s16];
#pragma unroll
        for (int a = 0; a < AIN; ++a)
            c = fmaf(smal[a], AW2[a*AOUT+s16], fmaf(smdp[a], AW4[a*AOUT+s16], c));
        for (int k = 0; k < XIN; ++k) c = fmaf(smx[k], AW7[k*AOUT+s16], c);
        g_C[n*AOUT + s16] = c;
    }
}

// ---------------- K2b: per-node R, X1t, X2t (16 nodes/block, 4t/lane) ----
__global__ void __launch_bounds__(256) k_node(
    const float* __restrict__ X,
    const float* __restrict__ AW3, const float* __restrict__ AW5, const float* __restrict__ AW6,
    const float* __restrict__ X1W1, const float* __restrict__ X1W2, const float* __restrict__ X1W3,
    const float* __restrict__ X1W4, const float* __restrict__ X1W5, const float* __restrict__ X1W6,
    const float* __restrict__ X1b,
    const float* __restrict__ X2W1, const float* __restrict__ X2W2, const float* __restrict__ X2W3,
    const float* __restrict__ X2W4, const float* __restrict__ X2W5, const float* __restrict__ X2W6,
    const float* __restrict__ X2b)
{
    int bx = blockIdx.x;                 // 256 blocks x 16 nodes
    int tid = threadIdx.x;
    int nl = tid >> 4, q = tid & 15, t0 = q << 2;
    int node0 = bx << 4;
    int n = node0 >> 10;
    int node = node0 + nl;

    __shared__ float sx[16][64];
    __shared__ float smoc[16][8], sdpv[16][8];
    __shared__ float smx[64], smdp[8], smal[8];

    {   // stage X: 1024 floats coalesced
        const float4* xp = (const float4*)(X + ((size_t)node0 << 6));
        ((float4*)&sx[0][0])[tid] = xp[tid];
    }
    if (tid < 128) {
        ((float*)smoc)[tid] = g_moc[(node0<<3) + tid];
        ((float*)sdpv)[tid] = g_dp [(node0<<3) + tid];
    }
    if (tid >= 128 && tid < 192) smx[tid-128] = g_mX[(n<<6) + tid-128];
    if (tid >= 192 && tid < 200) smdp[tid-192] = g_mdp[(n<<3) + tid-192];
    if (tid >= 200 && tid < 208) smal[tid-200] = g_mall[(n<<3) + tid-200];
    __syncthreads();

    float4 b1 = *(const float4*)(X1b + t0);
    float4 b2 = *(const float4*)(X2b + t0);
    ULL x1a, x1b4, x2a, x2b4;
    PACKXY(x1a, b1.x, b1.y); PACKXY(x1b4, b1.z, b1.w);
    PACKXY(x2a, b2.x, b2.y); PACKXY(x2b4, b2.z, b2.w);

#pragma unroll 4
    for (int k = 0; k < XIN; ++k) {
        float xk = sx[nl][k], mk = smx[k];
        ULL xkp, mkp; PACK2(xkp, xk); PACK2(mkp, mk);
        float4 w; ULL wlo, whi;
        w = *(const float4*)(X1W1 + (k<<6) + t0);
        PACKXY(wlo, w.x, w.y); PACKXY(whi, w.z, w.w);
        FMA2(x1a, xkp, wlo); FMA2(x1b4, xkp, whi);
        w = *(const float4*)(X2W1 + (k<<6) + t0);
        PACKXY(wlo, w.x, w.y); PACKXY(whi, w.z, w.w);
        FMA2(x2a, xkp, wlo); FMA2(x2b4, xkp, whi);
        w = *(const float4*)(X1W2 + (k<<6) + t0);
        PACKXY(wlo, w.x, w.y); PACKXY(whi, w.z, w.w);
        FMA2(x1a, mkp, wlo); FMA2(x1b4, mkp, whi);
        w = *(const float4*)(X2W2 + (k<<6) + t0);
        PACKXY(wlo, w.x, w.y); PACKXY(whi, w.z, w.w);
        FMA2(x2a, mkp, wlo); FMA2(x2b4, mkp, whi);
    }
#pragma unroll
    for (int a = 0; a < AIN; ++a) {
        ULL v1, v2, v3, v4;
        PACK2(v1, smoc[nl][a]); PACK2(v2, sdpv[nl][a]);
        PACK2(v3, smdp[a]);     PACK2(v4, smal[a]);
        float4 w; ULL wlo, whi;
        w = *(const float4*)(X1W3 + (a<<6) + t0);
        PACKXY(wlo, w.x, w.y); PACKXY(whi, w.z, w.w);
        FMA2(x1a, v1, wlo); FMA2(x1b4, v1, whi);
        w = *(const float4*)(X2W3 + (a<<6) + t0);
        PACKXY(wlo, w.x, w.y); PACKXY(whi, w.z, w.w);
        FMA2(x2a, v1, wlo); FMA2(x2b4, v1, whi);
        w = *(const float4*)(X1W4 + (a<<6) + t0);
        PACKXY(wlo, w.x, w.y); PACKXY(whi, w.z, w.w);
        FMA2(x1a, v2, wlo); FMA2(x1b4, v2, whi);
        w = *(const float4*)(X2W4 + (a<<6) + t0);
        PACKXY(wlo, w.x, w.y); PACKXY(whi, w.z, w.w);
        FMA2(x2a, v2, wlo); FMA2(x2b4, v2, whi);
        w = *(const float4*)(X1W5 + (a<<6) + t0);
        PACKXY(wlo, w.x, w.y); PACKXY(whi, w.z, w.w);
        FMA2(x1a, v3, wlo); FMA2(x1b4, v3, whi);
        w = *(const float4*)(X2W5 + (a<<6) + t0);
        PACKXY(wlo, w.x, w.y); PACKXY(whi, w.z, w.w);
        FMA2(x2a, v3, wlo); FMA2(x2b4, v3, whi);
        w = *(const float4*)(X1W6 + (a<<6) + t0);
        PACKXY(wlo, w.x, w.y); PACKXY(whi, w.z, w.w);
        FMA2(x1a, v4, wlo); FMA2(x1b4, v4, whi);
        w = *(const float4*)(X2W6 + (a<<6) + t0);
        PACKXY(wlo, w.x, w.y); PACKXY(whi, w.z, w.w);
        FMA2(x2a, v4, wlo); FMA2(x2b4, v4, whi);
    }
    {
        float4 o1, o2;
        UNPACK2(o1.x, o1.y, x1a); UNPACK2(o1.z, o1.w, x1b4);
        UNPACK2(o2.x, o2.y, x2a); UNPACK2(o2.z, o2.w, x2b4);
        *(float4*)(g_X1t + ((size_t)node << 6) + t0) = o1;
        *(float4*)(g_X2t + ((size_t)node << 6) + t0) = o2;
    }
    {   // R: lane q computes s = q for its node; also write transposed copy
        float r = 0.f;
#pragma unroll
        for (int a = 0; a < AIN; ++a) {
            r = fmaf(smoc[nl][a], AW3[a*AOUT+q], r);
            r = fmaf(sdpv[nl][a], AW5[a*AOUT+q], r);
        }
#pragma unroll 4
        for (int k = 0; k < XIN; ++k) r = fmaf(sx[nl][k], AW6[k*AOUT+q], r);
        g_R [((size_t)node << 4) + q] = r;
        g_Rt[(n << 14) + (q << 10) + (node & 1023)] = r;
    }
}

// ---------------- K_q: Q and SX2 partials ---------------------------------
__global__ void __launch_bounds__(1024) k_q()
{
    int bx = blockIdx.x;               // n*16 + seg
    int n = bx >> 4, seg = bx & 15;
    int tid = threadIdx.x;
    int s16 = tid >> 6, t = tid & 63;
    const float* rp = g_R   + ((size_t)n << 10) * AOUT + (size_t)(seg << 6) * AOUT;
    const float* xp = g_X2t + ((size_t)n << 10) * XOUT + (size_t)(seg << 6) * XOUT;
    float q = 0.f;
#pragma unroll 4
    for (int jj = 0; jj < 64; ++jj)
        q = fmaf(rp[jj*AOUT + s16], xp[jj*XOUT + t], q);
    g_Qpart[(size_t)bx * 1024 + tid] = q;
    if (tid < 64) {
        float s = 0.f;
#pragma unroll 4
        for (int jj = 0; jj < 64; ++jj) s += xp[jj*XOUT + tid];
        g_SX2part[bx*64 + tid] = s;
    }
}

// ---------------- K_fin: T, K ---------------------------------------------
__global__ void __launch_bounds__(1024) k_fin(
    const float* __restrict__ OW, const float* __restrict__ outb)
{
    int n = blockIdx.x, tid = threadIdx.x;
    __shared__ float sx2[XOUT];
    __shared__ float sq[AOUT*XOUT];
    __shared__ float st_[AOUT*XOUT];
    __shared__ float sp[AOUT*XOUT];
    {
        float q = 0.f;
#pragma unroll
        for (int seg = 0; seg < 16; ++seg)
            q += g_Qpart[(size_t)((n<<4)|seg) * 1024 + tid];
        sq[tid] = q;
    }
    if (tid < 64) {
        float s = 0.f;
#pragma unroll
        for (int seg = 0; seg < 16; ++seg) s += g_SX2part[((n<<4)|seg)*64 + tid];
        sx2[tid] = s;
    }
    __syncthreads();
    int s16 = tid >> 6, t = tid & 63;
    {
        float v = 0.f;
#pragma unroll 4
        for (int u = 0; u < 64; ++u)
            v = fmaf(sx2[u], OW[((s16<<6)+u)*64 + t], v);
        st_[tid] = v;
        g_T[n*1024 + tid] = v;
    }
    {
        float p = 0.f;
#pragma unroll 4
        for (int u = 0; u < 64; ++u)
            p = fmaf(sq[(s16<<6)+u], OW[(((s16<<6)+u)<<6) + t], p);
        sp[tid] = p;
    }
    __syncthreads();
    if (tid < 64) {
        int tt = tid;
        float qo = 0.f, ct = 0.f;
#pragma unroll
        for (int s = 0; s < AOUT; ++s) {
            qo += sp[(s<<6) + tt];
            ct = fmaf(g_C[n*AOUT + s], st_[(s<<6) + tt], ct);
        }
        g_K[n*XOUT + tt] = (ct + qo) * (1.f/1024.f) + outb[tt];
    }
}

// ---------------- K3: main — 2 nodes per block ----------------------------
#define SMEM_MAIN ((8224 + 8192 + 8192 + 128 + 32) * 4)

__global__ void __launch_bounds__(256, 2) k_main(
    const float* __restrict__ A, const float* __restrict__ AW1,
    float* __restrict__ outAt)
{
    extern __shared__ float dyn[];
    float* sA   = dyn;                    // 8224 (staging scratch, later dump)
    float* sAT0 = dyn + 8224;             // 8192
    float* sAT1 = sAT0 + 8192;            // 8192
    float* sW1  = sAT1 + 8192;            // 128
    float* sC0  = sW1 + 128;              // 16
    float* sC1  = sC0 + 16;               // 16

    int bx = blockIdx.x;                  // 2048: n = bx>>9, i-pair
    int n = bx >> 9, i0 = (bx & 511) << 1;
    int tid = threadIdx.x, w = tid >> 5, l = tid & 31;

    if (tid < 128) sW1[tid] = AW1[tid];
    if (tid < AOUT) {
        float c = g_C[(n<<4) + tid];
        sC0[tid] = g_R[((size_t)((n<<10)|i0)     << 4) + tid] + c;
        sC1[tid] = g_R[((size_t)((n<<10)|(i0+1)) << 4) + tid] + c;
    }

#pragma unroll
    for (int ii = 0; ii < 2; ++ii) {
        int i = i0 + ii;
        // stage 8 A rows (coalesced float4)
        {
            const float4* A4 = (const float4*)A;
#pragma unroll
            for (int a = 0; a < AIN; ++a) {
                size_t ridx = ((size_t)((n<<3) + a) << 20) + ((size_t)i << 10);
                float4 v = A4[(ridx >> 2) + tid];
                *(float4*)(sA + a*1028 + (tid<<2)) = v;
            }
        }
        __syncthreads();
        // conflict-free transpose sA -> sAT[j][a]
        float* sAT = ii ? sAT1 : sAT0;
        {
            int a = tid & 7, jb2 = tid >> 3;
#pragma unroll
            for (int it = 0; it < 32; ++it) {
                int j = jb2 + (it << 5);
                sAT[(j << 3) + a] = sA[a*1028 + j];
            }
        }
        // ---- Phase A for node i: G + (R_i+C) + R_j (R_j via coalesced g_Rt) ----
        {
            const float* sC = ii ? sC1 : sC0;
            int j0 = tid << 2;
            ULL apk[8][2];
#pragma unroll
            for (int a = 0; a < AIN; ++a) {
                const ULL* rp = (const ULL*)(sA + a*1028 + j0);
                apk[a][0] = rp[0]; apk[a][1] = rp[1];
            }
            size_t obase = (((size_t)(n<<4)) << 20) + ((size_t)i << 10) + j0;
            const float* Rtb = g_Rt + (n << 14) + j0;
#pragma unroll
            for (int sg = 0; sg < 4; ++sg) {
                float4 c4 = *(const float4*)(sC + (sg<<2));
                ULL a0a,a0b,a1a,a1b,a2a,a2b,a3a,a3b;
                PACK2(a0a, c4.x); a0b = a0a;
                PACK2(a1a, c4.y); a1b = a1a;
                PACK2(a2a, c4.z); a2b = a2a;
                PACK2(a3a, c4.w); a3b = a3a;
#pragma unroll
                for (int a = 0; a < AIN; ++a) {
                    float4 w4 = *(const float4*)(sW1 + (a<<4) + (sg<<2));
                    ULL ws;
                    PACK2(ws, w4.x); FMA2(a0a, apk[a][0], ws); FMA2(a0b, apk[a][1], ws);
                    PACK2(ws, w4.y); FMA2(a1a, apk[a][0], ws); FMA2(a1b, apk[a][1], ws);
                    PACK2(ws, w4.z); FMA2(a2a, apk[a][0], ws); FMA2(a2b, apk[a][1], ws);
                    PACK2(ws, w4.w); FMA2(a3a, apk[a][0], ws); FMA2(a3b, apk[a][1], ws);
                }
                // coalesced R_j rows (one float4 per s, lanes contiguous)
                float4 rt0 = *(const float4*)(Rtb + (((sg<<2)+0) << 10));
                float4 rt1 = *(const float4*)(Rtb + (((sg<<2)+1) << 10));
                float4 rt2 = *(const float4*)(Rtb + (((sg<<2)+2) << 10));
                float4 rt3 = *(const float4*)(Rtb + (((sg<<2)+3) << 10));
                float v0,v1,v2,v3; float4 o;
                UNPACK2(v0,v1,a0a); UNPACK2(v2,v3,a0b);
                o.x=v0+rt0.x; o.y=v1+rt0.y; o.z=v2+rt0.z; o.w=v3+rt0.w;
                *(float4*)(outAt + obase + (((size_t)((sg<<2)+0)) << 20)) = o;
                UNPACK2(v0,v1,a1a); UNPACK2(v2,v3,a1b);
                o.x=v0+rt1.x; o.y=v1+rt1.y; o.z=v2+rt1.z; o.w=v3+rt1.w;
                *(float4*)(outAt + obase + (((size_t)((sg<<2)+1)) << 20)) = o;
                UNPACK2(v0,v1,a2a); UNPACK2(v2,v3,a2b);
                o.x=v0+rt2.x; o.y=v1+rt2.y; o.z=v2+rt2.z; o.w=v3+rt2.w;
                *(float4*)(outAt + obase + (((size_t)((sg<<2)+2)) << 20)) = o;
                UNPACK2(v0,v1,a3a); UNPACK2(v2,v3,a3b);
                o.x=v0+rt3.x; o.y=v1+rt3.y; o.z=v2+rt3.z; o.w=v3+rt3.w;
                *(float4*)(outAt + obase + (((size_t)((sg<<2)+3)) << 20)) = o;
            }
        }
        __syncthreads();   // all sA reads done before restage / dump reuse
    }

    // ---- Phase H: both nodes share X2t loads; SW-pipelined LDG (MLP 4-8) ----
    {
        int half = l >> 4, t0 = (l & 15) << 2;
        int jb = (w << 7) + half;
        const float* Xb = g_X2t + (((size_t)n) << 16) + ((size_t)jb << 6) + t0;
        ULL h0[4][4], h1[4][4];
#pragma unroll
        for (int p = 0; p < 4; ++p)
#pragma unroll
            for (int q = 0; q < 4; ++q) { h0[p][q] = 0ull; h1[p][q] = 0ull; }

        float4 xa[4];
#pragma unroll
        for (int u = 0; u < 4; ++u) xa[u] = *(const float4*)(Xb + (u << 7));

#pragma unroll 2
        for (int s4 = 0; s4 < 16; ++s4) {
            int nb = ((s4 + 1) & 15) << 2;       // wrap prefetch (last iter dummy, in-bounds)
            float4 xb[4];
#pragma unroll
            for (int u = 0; u < 4; ++u)
                xb[u] = *(const float4*)(Xb + ((nb + u) << 7));
#pragma unroll
            for (int u = 0; u < 4; ++u) {
                int j = jb + (((s4 << 2) + u) << 1);
                // 4x LDS.128 instead of 8x LDS.64
                float4 f00 = *(const float4*)(sAT0 + (j << 3));
                float4 f01 = *(const float4*)(sAT0 + (j << 3) + 4);
                float4 f10 = *(const float4*)(sAT1 + (j << 3));
                float4 f11 = *(const float4*)(sAT1 + (j << 3) + 4);
                ULL b00,b01,b02,b03,b10,b11,b12,b13;
                PACKXY(b00, f00.x, f00.y); PACKXY(b01, f00.z, f00.w);
                PACKXY(b02, f01.x, f01.y); PACKXY(b03, f01.z, f01.w);
                PACKXY(b10, f10.x, f10.y); PACKXY(b11, f10.z, f10.w);
                PACKXY(b12, f11.x, f11.y); PACKXY(b13, f11.z, f11.w);
                ULL xs;
                PACK2(xs, xa[u].x);
                FMA2(h0[0][0], b00, xs); FMA2(h0[1][0], b01, xs);
                FMA2(h0[2][0], b02, xs); FMA2(h0[3][0], b03, xs);
                FMA2(h1[0][0], b10, xs); FMA2(h1[1][0], b11, xs);
                FMA2(h1[2][0], b12, xs); FMA2(h1[3][0], b13, xs);
                PACK2(xs, xa[u].y);
                FMA2(h0[0][1], b00, xs); FMA2(h0[1][1], b01, xs);
                FMA2(h0[2][1], b02, xs); FMA2(h0[3][1], b03, xs);
                FMA2(h1[0][1], b10, xs); FMA2(h1[1][1], b11, xs);
                FMA2(h1[2][1], b12, xs); FMA2(h1[3][1], b13, xs);
                PACK2(xs, xa[u].z);
                FMA2(h0[0][2], b00, xs); FMA2(h0[1][2], b01, xs);
                FMA2(h0[2][2], b02, xs); FMA2(h0[3][2], b03, xs);
                FMA2(h1[0][2], b10, xs); FMA2(h1[1][2], b11, xs);
                FMA2(h1[2][2], b12, xs); FMA2(h1[3][2], b13, xs);
                PACK2(xs, xa[u].w);
                FMA2(h0[0][3], b00, xs); FMA2(h0[1][3], b01, xs);
                FMA2(h0[2][3], b02, xs); FMA2(h0[3][3], b03, xs);
                FMA2(h1[0][3], b10, xs); FMA2(h1[1][3], b11, xs);
                FMA2(h1[2][3], b12, xs); FMA2(h1[3][3], b13, xs);
            }
#pragma unroll
            for (int u = 0; u < 4; ++u) xa[u] = xb[u];
        }

        // dump + reduce, node by node (reuse sA as [16][512])
        float* dump = sA;
        int rb = (((w << 1) + half) << 9) + t0;
#pragma unroll
        for (int ap = 0; ap < 4; ++ap) {
            float4 fe, fo;
            UNPACK2(fe.x, fo.x, h0[ap][0]);
            UNPACK2(fe.y, fo.y, h0[ap][1]);
            UNPACK2(fe.z, fo.z, h0[ap][2]);
            UNPACK2(fe.w, fo.w, h0[ap][3]);
            *(float4*)(dump + rb + ((ap<<1)<<6))     = fe;
            *(float4*)(dump + rb + (((ap<<1)|1)<<6)) = fo;
        }
        __syncthreads();
        size_t node0 = ((size_t)n << 10) | (size_t)i0;
#pragma unroll
        for (int k = 0; k < 2; ++k) {
            int idx = tid + (k << 8);
            float s = 0.f;
#pragma unroll
            for (int r = 0; r < 16; ++r) s += dump[(r << 9) + idx];
            g_H[(node0 << 9) + idx] = s;
        }
        __syncthreads();
#pragma unroll
        for (int ap = 0; ap < 4; ++ap) {
            float4 fe, fo;
            UNPACK2(fe.x, fo.x, h1[ap][0]);
            UNPACK2(fe.y, fo.y, h1[ap][1]);
            UNPACK2(fe.z, fo.z, h1[ap][2]);
            UNPACK2(fe.w, fo.w, h1[ap][3]);
            *(float4*)(dump + rb + ((ap<<1)<<6))     = fe;
            *(float4*)(dump + rb + (((ap<<1)|1)<<6)) = fo;
        }
        __syncthreads();
#pragma unroll
        for (int k = 0; k < 2; ++k) {
            int idx = tid + (k << 8);
            float s = 0.f;
#pragma unroll
            for (int r = 0; r < 16; ++r) s += dump[(r << 9) + idx];
            g_H[((node0 + 1) << 9) + idx] = s;
        }
    }
}

// ---------------- K4: out = H*OWH/n + R*T/n + K + X1t ---------------------
#define SMEM_OUT ((512*64 + 16*512) * 4)

__global__ void __launch_bounds__(256) k_out(float* __restrict__ out2)
{
    extern __shared__ float dyn[];
    float* sOWH = dyn;            // 32768 floats
    float* sH   = dyn + 32768;    // 8192 floats
    int bx = blockIdx.x;          // 256 blocks x 16 nodes
    int n = bx >> 6, tid = threadIdx.x;
    {
        const float4* s4 = (const float4*)g_OWH;
        float4* d4 = (float4*)sOWH;
#pragma unroll
        for (int k = 0; k < 32; ++k) d4[(k<<8)+tid] = s4[(k<<8)+tid];
        const float4* h4 = (const float4*)(g_H + ((size_t)bx << 13));
        float4* dh = (float4*)sH;
#pragma unroll
        for (int k = 0; k < 8; ++k) dh[(k<<8)+tid] = h4[(k<<8)+tid];
    }
    __syncthreads();
    int r = tid >> 4, q = tid & 15, t0 = q << 2;
    int node = (bx << 4) + r;
    ULL acc01 = 0ull, acc23 = 0ull;
    const float* hrow = sH + (r << 9);
#pragma unroll 4
    for (int au = 0; au < 512; ++au) {
        ULL hs; PACK2(hs, hrow[au]);
        const ULL* wr = (const ULL*)(sOWH + (au << 6) + t0);
        FMA2(acc01, hs, wr[0]); FMA2(acc23, hs, wr[1]);
    }
    float a0,a1,a2,a3;
    UNPACK2(a0,a1,acc01); UNPACK2(a2,a3,acc23);
    const float* Tn = g_T + (n << 10);
    const float* Rn = g_R + ((size_t)node << 4);
#pragma unroll
    for (int s = 0; s < AOUT; ++s) {
        float rv = Rn[s];
        float4 tv = *(const float4*)(Tn + (s << 6) + t0);
        a0 = fmaf(rv, tv.x, a0); a1 = fmaf(rv, tv.y, a1);
        a2 = fmaf(rv, tv.z, a2); a3 = fmaf(rv, tv.w, a3);
    }
    const float sc = 1.f/1024.f;
    size_t ob = ((size_t)node << 6) + t0;
    float4 kv  = *(const float4*)(g_K + (n << 6) + t0);
    float4 x1v = *(const float4*)(g_X1t + ob);
    float4 o;
    o.x = a0*sc + kv.x + x1v.x;  o.y = a1*sc + kv.y + x1v.y;
    o.z = a2*sc + kv.z + x1v.z;  o.w = a3*sc + kv.w + x1v.w;
    *(float4*)(out2 + ob) = o;
}

// ---------------- launch ---------------------------------------------------
extern "C" void kernel_launch(void* const* d_in, const int* in_sizes, int n_in,
                              void* d_out, int out_size)
{
    const float* A     = (const float*)d_in[0];
    const float* X     = (const float*)d_in[1];
    const float* AW1   = (const float*)d_in[2];
    const float* AW2   = (const float*)d_in[3];
    const float* AW3   = (const float*)d_in[4];
    const float* AW4   = (const float*)d_in[5];
    const float* AW5   = (const float*)d_in[6];
    const float* AW6   = (const float*)d_in[7];
    const float* AW7   = (const float*)d_in[8];
    const float* Abias = (const float*)d_in[9];
    const float* X1W1  = (const float*)d_in[10];
    const float* X1W2  = (const float*)d_in[11];
    const float* X1W3  = (const float*)d_in[12];
    const float* X1W4  = (const float*)d_in[13];
    const float* X1W5  = (const float*)d_in[14];
    const float* X1W6  = (const float*)d_in[15];
    const float* X1b   = (const float*)d_in[16];
    const float* X2W1  = (const float*)d_in[17];
    const float* X2W2  = (const float*)d_in[18];
    const float* X2W3  = (const float*)d_in[19];
    const float* X2W4  = (const float*)d_in[20];
    const float* X2W5  = (const float*)d_in[21];
    const float* X2W6  = (const float*)d_in[22];
    const float* X2b   = (const float*)d_in[23];
    const float* OW    = (const float*)d_in[24];
    const float* outb  = (const float*)d_in[25];

    float* outAt = (float*)d_out;
    float* out2  = outAt + (size_t)NB * AOUT * NN * NN;

    cudaFuncSetAttribute(k_main, cudaFuncAttributeMaxDynamicSharedMemorySize, SMEM_MAIN);
    cudaFuncSetAttribute(k_out,  cudaFuncAttributeMaxDynamicSharedMemorySize, SMEM_OUT);

    // NOTE: ncu captures the 4th launch -> k_main stays 4th
    k_reduce<<<NB*NN, 256>>>(A);
    k_pre_n <<<NB, 1024>>>(X, AW2, AW4, AW7, Abias);
    k_node  <<<NB*NN/16, 256>>>(X, AW3, AW5, AW6,
                            X1W1, X1W2, X1W3, X1W4, X1W5, X1W6, X1b,
                            X2W1, X2W2, X2W3, X2W4, X2W5, X2W6, X2b);
    k_main  <<<NB*NN/2, 256, SMEM_MAIN>>>(A, AW1, outAt);
    k_owh   <<<AIN, 256>>>(AW1, OW);
    k_q     <<<NB*16, 1024>>>();
    k_fin   <<<NB, 1024>>>(OW, outb);
    k_out   <<<NB*NN/16, 256, SMEM_OUT>>>(out2);
}

// round 9
// speedup vs baseline: 3.0026x; 1.0438x over previous
#include <cuda_runtime.h>
#include <cuda_bf16.h>
#include <cstdint>

#define NB 4
#define NN 1024
#define AIN 8
#define AOUT 16
#define XIN 64
#define XOUT 64

typedef unsigned long long ULL;

// ---------------- scratch (device globals; no allocation) ----------------
__device__ float g_moc[NB*NN*AIN];
__device__ float g_dp [NB*NN*AIN];
__device__ float g_mdp[NB*AIN];
__device__ float g_mall[NB*AIN];
__device__ float g_mX [NB*XIN];
__device__ float g_C  [NB*AOUT];
__device__ float g_R  [NB*NN*AOUT];
__device__ float g_Rt [NB*AOUT*NN];      // R transposed: [n][s][j]
__device__ float g_X1t[NB*NN*XOUT];
__device__ float g_X2t[NB*NN*XOUT];
__device__ __align__(16) __nv_bfloat16 g_X2tT_hi[NB*XOUT*NN];   // [n][t][j]
__device__ __align__(16) __nv_bfloat16 g_X2tT_lo[NB*XOUT*NN];   // [n][t][j]
__device__ float g_T  [NB*AOUT*XOUT];
__device__ float g_K  [NB*XOUT];
__device__ float g_OWH[AIN*XOUT*XOUT];
__device__ __align__(16) float g_H[NB*NN*AIN*XOUT];
__device__ float g_Qpart[NB*16*AOUT*XOUT];
__device__ float g_SX2part[NB*16*XOUT];

#define FMA2(d,a,b) asm("fma.rn.f32x2 %0, %1, %2, %0;" : "+l"(d) : "l"(a), "l"(b))
#define PACK2(d,x)  asm("mov.b64 %0, {%1, %1};" : "=l"(d) : "f"(x))
#define PACKXY(d,x,y) asm("mov.b64 %0, {%1, %2};" : "=l"(d) : "f"(x), "f"(y))
#define UNPACK2(lo,hi,d) asm("mov.b64 {%0, %1}, %2;" : "=f"(lo), "=f"(hi) : "l"(d))

#define LDSM_X4(r0,r1,r2,r3,addr) \
    asm volatile("ldmatrix.sync.aligned.m8n8.x4.shared.b16 {%0,%1,%2,%3}, [%4];" \
        : "=r"(r0),"=r"(r1),"=r"(r2),"=r"(r3) : "r"(addr))

#define MMA_BF16(c0,c1,c2,c3,a0,a1,a2,a3,b0,b1) \
    asm volatile("mma.sync.aligned.m16n8k16.row.col.f32.bf16.bf16.f32 " \
        "{%0,%1,%2,%3}, {%4,%5,%6,%7}, {%8,%9}, {%0,%1,%2,%3};" \
        : "+f"(c0),"+f"(c1),"+f"(c2),"+f"(c3) \
        : "r"(a0),"r"(a1),"r"(a2),"r"(a3), "r"(b0),"r"(b1))

__device__ __forceinline__ uint32_t smem_u32(const void* p) {
    uint32_t a;
    asm("{ .reg .u64 t; cvta.to.shared.u64 t, %1; cvt.u32.u64 %0, t; }" : "=r"(a) : "l"(p));
    return a;
}

// ---------------- K1: row reductions over A -> moc, dp -------------------
__global__ void __launch_bounds__(256) k_reduce(const float* __restrict__ A)
{
    int bx = blockIdx.x;            // bx = n*1024 + i
    int n = bx >> 10, i = bx & 1023;
    int w = threadIdx.x >> 5, l = threadIdx.x & 31;
    size_t row = ((size_t)(n*AIN + w) << 20) + ((size_t)i << 10);
    const float4* p = (const float4*)(A + row);
    float s = 0.f;
#pragma unroll
    for (int k = 0; k < 8; ++k) {
        float4 v = p[k*32 + l];
        s += v.x + v.y + v.z + v.w;
    }
#pragma unroll
    for (int o = 16; o; o >>= 1) s += __shfl_xor_sync(0xffffffffu, s, o);
    if (l == 0) {
        g_moc[(bx << 3) + w] = s * (1.f/1024.f);
        g_dp [(bx << 3) + w] = A[row + i];
    }
}

// ---------------- K_owh -----------------------------------------------------
__global__ void __launch_bounds__(256) k_owh(
    const float* __restrict__ AW1, const float* __restrict__ OW)
{
    int a = blockIdx.x, tid = threadIdx.x;
    __shared__ float sw[AOUT];
    if (tid < AOUT) sw[tid] = AW1[a*AOUT + tid];
    __syncthreads();
    for (int idx = tid; idx < 4096; idx += 256) {
        int u = idx >> 6, t = idx & 63;
        float s = 0.f;
#pragma unroll
        for (int ss = 0; ss < AOUT; ++ss)
            s = fmaf(sw[ss], OW[((ss<<6)+u)*64 + t], s);
        g_OWH[((a<<6)+u)*64 + t] = s;
    }
}

// ---------------- K2a: per-n means + C -----------------------------------
__global__ void __launch_bounds__(1024) k_pre_n(
    const float* __restrict__ X,
    const float* __restrict__ AW2, const float* __restrict__ AW4,
    const float* __restrict__ AW7, const float* __restrict__ Abias)
{
    int n = blockIdx.x, tid = threadIdx.x;
    __shared__ float spart[16][64];
    __shared__ float sdpp[128][8];
    __shared__ float salp[128][8];
    __shared__ float smx[XIN], smdp[AIN], smal[AIN];

    {
        int col = tid & 63, seg = tid >> 6;
        const float* xp = X + ((size_t)n << 16) + (size_t)(seg << 6) * XIN + col;
        float s = 0.f;
#pragma unroll 4
        for (int r = 0; r < 64; ++r) s += xp[(size_t)r * XIN];
        spart[seg][col] = s;
    }
    {
        int a = tid & 7, seg = tid >> 3;
        const float* dpp = g_dp  + (n << 13) + (seg << 6) + a;
        const float* mcp = g_moc + (n << 13) + (seg << 6) + a;
        float s1 = 0.f, s2 = 0.f;
#pragma unroll
        for (int r = 0; r < 8; ++r) { s1 += dpp[r*8]; s2 += mcp[r*8]; }
        sdpp[seg][a] = s1; salp[seg][a] = s2;
    }
    __syncthreads();
    if (tid < 64) {
        float s = 0.f;
#pragma unroll
        for (int k = 0; k < 16; ++k) s += spart[k][tid];
        smx[tid] = s * (1.f/1024.f);
        g_mX[n*XIN + tid] = smx[tid];
    } else if (tid >= 64 && tid < 72) {
        int a = tid - 64; float s = 0.f;
        for (int k = 0; k < 128; ++k) s += sdpp[k][a];
        smdp[a] = s * (1.f/1024.f); g_mdp[n*AIN + a] = smdp[a];
    } else if (tid >= 72 && tid < 80) {
        int a = tid - 72; float s = 0.f;
        for (int k = 0; k < 128; ++k) s += salp[k][a];
        smal[a] = s * (1.f/1024.f); g_mall[n*AIN + a] = smal[a];
    }
    __syncthreads();
    if (tid < AOUT) {
        int s16 = tid; float c = Abias[s16];
#pragma unroll
        for (int a = 0; a < AIN; ++a)
            c = fmaf(smal[a], AW2[a*AOUT+s16], fmaf(smdp[a], AW4[a*AOUT+s16], c));
        for (int k = 0; k < XIN; ++k) c = fmaf(smx[k], AW7[k*AOUT+s16], c);
        g_C[n*AOUT + s16] = c;
    }
}

// ---------------- K2b: per-node R, X1t, X2t (16 nodes/block) --------------
__global__ void __launch_bounds__(256) k_node(
    const float* __restrict__ X,
    const float* __restrict__ AW3, const float* __restrict__ AW5, const float* __restrict__ AW6,
    const float* __restrict__ X1W1, const float* __restrict__ X1W2, const float* __restrict__ X1W3,
    const float* __restrict__ X1W4, const float* __restrict__ X1W5, const float* __restrict__ X1W6,
    const float* __restrict__ X1b,
    const float* __restrict__ X2W1, const float* __restrict__ X2W2, const float* __restrict__ X2W3,
    const float* __restrict__ X2W4, const float* __restrict__ X2W5, const float* __restrict__ X2W6,
    const float* __restrict__ X2b)
{
    int bx = blockIdx.x;                 // 256 blocks x 16 nodes
    int tid = threadIdx.x;
    int nl = tid >> 4, q = tid & 15, t0 = q << 2;
    int node0 = bx << 4;
    int n = node0 >> 10;
    int node = node0 + nl;

    __shared__ float sx[16][64];
    __shared__ float smoc[16][8], sdpv[16][8];
    __shared__ float smx[64], smdp[8], smal[8];

    {
        const float4* xp = (const float4*)(X + ((size_t)node0 << 6));
        ((float4*)&sx[0][0])[tid] = xp[tid];
    }
    if (tid < 128) {
        ((float*)smoc)[tid] = g_moc[(node0<<3) + tid];
        ((float*)sdpv)[tid] = g_dp [(node0<<3) + tid];
    }
    if (tid >= 128 && tid < 192) smx[tid-128] = g_mX[(n<<6) + tid-128];
    if (tid >= 192 && tid < 200) smdp[tid-192] = g_mdp[(n<<3) + tid-192];
    if (tid >= 200 && tid < 208) smal[tid-200] = g_mall[(n<<3) + tid-200];
    __syncthreads();

    float4 b1 = *(const float4*)(X1b + t0);
    float4 b2 = *(const float4*)(X2b + t0);
    ULL x1a, x1b4, x2a, x2b4;
    PACKXY(x1a, b1.x, b1.y); PACKXY(x1b4, b1.z, b1.w);
    PACKXY(x2a, b2.x, b2.y); PACKXY(x2b4, b2.z, b2.w);

#pragma unroll 4
    for (int k = 0; k < XIN; ++k) {
        float xk = sx[nl][k], mk = smx[k];
        ULL xkp, mkp; PACK2(xkp, xk); PACK2(mkp, mk);
        float4 w; ULL wlo, whi;
        w = *(const float4*)(X1W1 + (k<<6) + t0);
        PACKXY(wlo, w.x, w.y); PACKXY(whi, w.z, w.w);
        FMA2(x1a, xkp, wlo); FMA2(x1b4, xkp, whi);
        w = *(const float4*)(X2W1 + (k<<6) + t0);
        PACKXY(wlo, w.x, w.y); PACKXY(whi, w.z, w.w);
        FMA2(x2a, xkp, wlo); FMA2(x2b4, xkp, whi);
        w = *(const float4*)(X1W2 + (k<<6) + t0);
        PACKXY(wlo, w.x, w.y); PACKXY(whi, w.z, w.w);
        FMA2(x1a, mkp, wlo); FMA2(x1b4, mkp, whi);
        w = *(const float4*)(X2W2 + (k<<6) + t0);
        PACKXY(wlo, w.x, w.y); PACKXY(whi, w.z, w.w);
        FMA2(x2a, mkp, wlo); FMA2(x2b4, mkp, whi);
    }
#pragma unroll
    for (int a = 0; a < AIN; ++a) {
        ULL v1, v2, v3, v4;
        PACK2(v1, smoc[nl][a]); PACK2(v2, sdpv[nl][a]);
        PACK2(v3, smdp[a]);     PACK2(v4, smal[a]);
        float4 w; ULL wlo, whi;
        w = *(const float4*)(X1W3 + (a<<6) + t0);
        PACKXY(wlo, w.x, w.y); PACKXY(whi, w.z, w.w);
        FMA2(x1a, v1, wlo); FMA2(x1b4, v1, whi);
        w = *(const float4*)(X2W3 + (a<<6) + t0);
        PACKXY(wlo, w.x, w.y); PACKXY(whi, w.z, w.w);
        FMA2(x2a, v1, wlo); FMA2(x2b4, v1, whi);
        w = *(const float4*)(X1W4 + (a<<6) + t0);
        PACKXY(wlo, w.x, w.y); PACKXY(whi, w.z, w.w);
        FMA2(x1a, v2, wlo); FMA2(x1b4, v2, whi);
        w = *(const float4*)(X2W4 + (a<<6) + t0);
        PACKXY(wlo, w.x, w.y); PACKXY(whi, w.z, w.w);
        FMA2(x2a, v2, wlo); FMA2(x2b4, v2, whi);
        w = *(const float4*)(X1W5 + (a<<6) + t0);
        PACKXY(wlo, w.x, w.y); PACKXY(whi, w.z, w.w);
        FMA2(x1a, v3, wlo); FMA2(x1b4, v3, whi);
        w = *(const float4*)(X2W5 + (a<<6) + t0);
        PACKXY(wlo, w.x, w.y); PACKXY(whi, w.z, w.w);
        FMA2(x2a, v3, wlo); FMA2(x2b4, v3, whi);
        w = *(const float4*)(X1W6 + (a<<6) + t0);
        PACKXY(wlo, w.x, w.y); PACKXY(whi, w.z, w.w);
        FMA2(x1a, v4, wlo); FMA2(x1b4, v4, whi);
        w = *(const float4*)(X2W6 + (a<<6) + t0);
        PACKXY(wlo, w.x, w.y); PACKXY(whi, w.z, w.w);
        FMA2(x2a, v4, wlo); FMA2(x2b4, v4, whi);
    }
    {
        float4 o1, o2;
        UNPACK2(o1.x, o1.y, x1a); UNPACK2(o1.z, o1.w, x1b4);
        UNPACK2(o2.x, o2.y, x2a); UNPACK2(o2.z, o2.w, x2b4);
        *(float4*)(g_X1t + ((size_t)node << 6) + t0) = o1;
        *(float4*)(g_X2t + ((size_t)node << 6) + t0) = o2;
        // transposed bf16 split for tensor GEMM
        int jn = node & 1023;
        float v[4] = {o2.x, o2.y, o2.z, o2.w};
#pragma unroll
        for (int d = 0; d < 4; ++d) {
            __nv_bfloat16 h = __float2bfloat16_rn(v[d]);
            __nv_bfloat16 lo = __float2bfloat16_rn(v[d] - __bfloat162float(h));
            g_X2tT_hi[(n<<16) + ((t0+d)<<10) + jn] = h;
            g_X2tT_lo[(n<<16) + ((t0+d)<<10) + jn] = lo;
        }
    }
    {   // R: lane q computes s = q for its node; also transposed copy
        float r = 0.f;
#pragma unroll
        for (int a = 0; a < AIN; ++a) {
            r = fmaf(smoc[nl][a], AW3[a*AOUT+q], r);
            r = fmaf(sdpv[nl][a], AW5[a*AOUT+q], r);
        }
#pragma unroll 4
        for (int k = 0; k < XIN; ++k) r = fmaf(sx[nl][k], AW6[k*AOUT+q], r);
        g_R [((size_t)node << 4) + q] = r;
        g_Rt[(n << 14) + (q << 10) + (node & 1023)] = r;
    }
}

// ---------------- K_q: Q and SX2 partials ---------------------------------
__global__ void __launch_bounds__(1024) k_q()
{
    int bx = blockIdx.x;               // n*16 + seg
    int n = bx >> 4, seg = bx & 15;
    int tid = threadIdx.x;
    int s16 = tid >> 6, t = tid & 63;
    const float* rp = g_R   + ((size_t)n << 10) * AOUT + (size_t)(seg << 6) * AOUT;
    const float* xp = g_X2t + ((size_t)n << 10) * XOUT + (size_t)(seg << 6) * XOUT;
    float q = 0.f;
#pragma unroll 4
    for (int jj = 0; jj < 64; ++jj)
        q = fmaf(rp[jj*AOUT + s16], xp[jj*XOUT + t], q);
    g_Qpart[(size_t)bx * 1024 + tid] = q;
    if (tid < 64) {
        float s = 0.f;
#pragma unroll 4
        for (int jj = 0; jj < 64; ++jj) s += xp[jj*XOUT + tid];
        g_SX2part[bx*64 + tid] = s;
    }
}

// ---------------- K_fin: T, K ---------------------------------------------
__global__ void __launch_bounds__(1024) k_fin(
    const float* __restrict__ OW, const float* __restrict__ outb)
{
    int n = blockIdx.x, tid = threadIdx.x;
    __shared__ float sx2[XOUT];
    __shared__ float sq[AOUT*XOUT];
    __shared__ float st_[AOUT*XOUT];
    __shared__ float sp[AOUT*XOUT];
    {
        float q = 0.f;
#pragma unroll
        for (int seg = 0; seg < 16; ++seg)
            q += g_Qpart[(size_t)((n<<4)|seg) * 1024 + tid];
        sq[tid] = q;
    }
    if (tid < 64) {
        float s = 0.f;
#pragma unroll
        for (int seg = 0; seg < 16; ++seg) s += g_SX2part[((n<<4)|seg)*64 + tid];
        sx2[tid] = s;
    }
    __syncthreads();
    int s16 = tid >> 6, t = tid & 63;
    {
        float v = 0.f;
#pragma unroll 4
        for (int u = 0; u < 64; ++u)
            v = fmaf(sx2[u], OW[((s16<<6)+u)*64 + t], v);
        st_[tid] = v;
        g_T[n*1024 + tid] = v;
    }
    {
        float p = 0.f;
#pragma unroll 4
        for (int u = 0; u < 64; ++u)
            p = fmaf(sq[(s16<<6)+u], OW[(((s16<<6)+u)<<6) + t], p);
        sp[tid] = p;
    }
    __syncthreads();
    if (tid < 64) {
        int tt = tid;
        float qo = 0.f, ct = 0.f;
#pragma unroll
        for (int s = 0; s < AOUT; ++s) {
            qo += sp[(s<<6) + tt];
            ct = fmaf(g_C[n*AOUT + s], st_[(s<<6) + tt], ct);
        }
        g_K[n*XOUT + tt] = (ct + qo) * (1.f/1024.f) + outb[tt];
    }
}

// ---------------- K_h: H GEMM via mma.sync bf16 split-precision ------------
// block = (n, a, mt): C[64 i x 64 t] = A[n,a, mt*64 + i, :] @ X2tT[n, t, :]^T
// 4 warps x 16 rows. smem: A hi/lo [64][72] bf16, B hi/lo [64][72] bf16.
#define AP 72           // row pitch in bf16 (144 B, conflict-free ldmatrix)
__global__ void __launch_bounds__(128) k_h(const float* __restrict__ A)
{
    __shared__ __align__(16) __nv_bfloat16 sAhi[64*AP], sAlo[64*AP];
    __shared__ __align__(16) __nv_bfloat16 sBhi[64*AP], sBlo[64*AP];
    uint32_t bAhi = smem_u32(sAhi), bAlo = smem_u32(sAlo);
    uint32_t bBhi = smem_u32(sBhi), bBlo = smem_u32(sBlo);

    int bx = blockIdx.x;
    int n = bx >> 7, a = (bx >> 4) & 7, mt = bx & 15;
    int tid = threadIdx.x, w = tid >> 5, l = tid & 31;

    const float* Ab = A + ((size_t)((n<<3) + a) << 20) + ((size_t)(mt << 6) << 10);
    const __nv_bfloat16* Bh = g_X2tT_hi + ((size_t)n << 16);
    const __nv_bfloat16* Bl = g_X2tT_lo + ((size_t)n << 16);

    float c[8][4];
#pragma unroll
    for (int q = 0; q < 8; ++q)
#pragma unroll
        for (int d = 0; d < 4; ++d) c[q][d] = 0.f;

    // ldmatrix lane addressing (constant across chunks)
    int blk = l >> 3, r8 = l & 7;
    uint32_t aoff = (uint32_t)((w*16 + ((blk & 1) << 3) + r8) * (AP*2) + ((blk >> 1) << 4));

#pragma unroll 1
    for (int ch = 0; ch < 16; ++ch) {
        // stage A: 64 rows x 64 j fp32 -> bf16 hi/lo
#pragma unroll
        for (int k = 0; k < 8; ++k) {
            int g = tid + (k << 7);
            int row = g >> 4, u = g & 15;
            float4 v = *(const float4*)(Ab + ((size_t)row << 10) + (ch << 6) + (u << 2));
            __nv_bfloat162 h0 = __floats2bfloat162_rn(v.x, v.y);
            __nv_bfloat162 h1 = __floats2bfloat162_rn(v.z, v.w);
            __nv_bfloat162 l0 = __floats2bfloat162_rn(v.x - __bfloat162float(h0.x),
                                                      v.y - __bfloat162float(h0.y));
            __nv_bfloat162 l1 = __floats2bfloat162_rn(v.z - __bfloat162float(h1.x),
                                                      v.w - __bfloat162float(h1.y));
            uint32_t off = row*AP + (u << 2);
            *(__nv_bfloat162*)(sAhi + off)     = h0;
            *(__nv_bfloat162*)(sAhi + off + 2) = h1;
            *(__nv_bfloat162*)(sAlo + off)     = l0;
            *(__nv_bfloat162*)(sAlo + off + 2) = l1;
        }
        // stage B hi/lo: 64 t-rows x 64 j bf16 (16B copies)
#pragma unroll
        for (int k = 0; k < 4; ++k) {
            int g = tid + (k << 7);
            int trow = g >> 3, u = g & 7;
            uint32_t off = trow*AP + (u << 3);
            *(uint4*)(sBhi + off) = *(const uint4*)(Bh + ((size_t)trow << 10) + (ch << 6) + (u << 3));
            *(uint4*)(sBlo + off) = *(const uint4*)(Bl + ((size_t)trow << 10) + (ch << 6) + (u << 3));
        }
        __syncthreads();

#pragma unroll
        for (int kt = 0; kt < 4; ++kt) {
            uint32_t ah0,ah1,ah2,ah3, al0,al1,al2,al3;
            LDSM_X4(ah0,ah1,ah2,ah3, bAhi + aoff + (kt << 5));
            LDSM_X4(al0,al1,al2,al3, bAlo + aoff + (kt << 5));
#pragma unroll
            for (int p = 0; p < 4; ++p) {
                // tiles 2p, 2p+1 ; lane: matrix mi=blk, row n = p*16 + (blk>>1)*8 + r8
                uint32_t boff = (uint32_t)((p*16 + ((blk >> 1) << 3) + r8) * (AP*2)
                                           + ((blk & 1) << 4)) + (kt << 5);
                uint32_t bh0,bh1,bh2,bh3, bl0,bl1,bl2,bl3;
                LDSM_X4(bh0,bh1,bh2,bh3, bBhi + boff);
                LDSM_X4(bl0,bl1,bl2,bl3, bBlo + boff);
                int q0 = 2*p, q1 = 2*p+1;
                MMA_BF16(c[q0][0],c[q0][1],c[q0][2],c[q0][3], ah0,ah1,ah2,ah3, bh0,bh1);
                MMA_BF16(c[q0][0],c[q0][1],c[q0][2],c[q0][3], ah0,ah1,ah2,ah3, bl0,bl1);
                MMA_BF16(c[q0][0],c[q0][1],c[q0][2],c[q0][3], al0,al1,al2,al3, bh0,bh1);
                MMA_BF16(c[q1][0],c[q1][1],c[q1][2],c[q1][3], ah0,ah1,ah2,ah3, bh2,bh3);
                MMA_BF16(c[q1][0],c[q1][1],c[q1][2],c[q1][3], ah0,ah1,ah2,ah3, bl2,bl3);
                MMA_BF16(c[q1][0],c[q1][1],c[q1][2],c[q1][3], al0,al1,al2,al3, bh2,bh3);
            }
        }
        __syncthreads();
    }

    // epilogue: c[q] -> g_H[node][a*64 + t]
    {
        int row0 = (mt << 6) + (w << 4) + (l >> 2);
        size_t nb = ((size_t)n << 10);
        float* H0 = g_H + ((nb + row0)     << 9) + (a << 6);
        float* H1 = g_H + ((nb + row0 + 8) << 9) + (a << 6);
        int tc = (l & 3) << 1;
#pragma unroll
        for (int q = 0; q < 8; ++q) {
            int t = (q << 3) + tc;
            *(float2*)(H0 + t) = make_float2(c[q][0], c[q][1]);
            *(float2*)(H1 + t) = make_float2(c[q][2], c[q][3]);
        }
    }
}

// ---------------- K3: main — Phase A only (1 node/block) -------------------
#define SMEM_MAINA ((8224 + 128 + 16) * 4)

__global__ void __launch_bounds__(256) k_main(
    const float* __restrict__ A, const float* __restrict__ AW1,
    float* __restrict__ outAt)
{
    extern __shared__ float dyn[];
    float* sA   = dyn;                    // 8224
    float* sW1  = dyn + 8224;             // 128
    float* sC16 = sW1 + 128;              // 16

    int bx = blockIdx.x;                  // n*1024 + i
    int n = bx >> 10, i = bx & 1023;
    int tid = threadIdx.x;

    {
        const float4* A4 = (const float4*)A;
#pragma unroll
        for (int a = 0; a < AIN; ++a) {
            size_t ridx = ((size_t)((n<<3) + a) << 20) + ((size_t)i << 10);
            float4 v = A4[(ridx >> 2) + tid];
            *(float4*)(sA + a*1028 + (tid<<2)) = v;
        }
    }
    if (tid < 128) sW1[tid] = AW1[tid];
    if (tid < AOUT)
        sC16[tid] = g_R[((size_t)bx << 4) + tid] + g_C[(n<<4) + tid];
    __syncthreads();

    {
        int j0 = tid << 2;
        ULL apk[8][2];
#pragma unroll
        for (int a = 0; a < AIN; ++a) {
            const ULL* rp = (const ULL*)(sA + a*1028 + j0);
            apk[a][0] = rp[0]; apk[a][1] = rp[1];
        }
        size_t obase = (((size_t)(n<<4)) << 20) + ((size_t)i << 10) + j0;
        const float* Rtb = g_Rt + (n << 14) + j0;
#pragma unroll
        for (int sg = 0; sg < 4; ++sg) {
            float4 c4 = *(const float4*)(sC16 + (sg<<2));
            ULL a0a,a0b,a1a,a1b,a2a,a2b,a3a,a3b;
            PACK2(a0a, c4.x); a0b = a0a;
            PACK2(a1a, c4.y); a1b = a1a;
            PACK2(a2a, c4.z); a2b = a2a;
            PACK2(a3a, c4.w); a3b = a3a;
#pragma unroll
            for (int a = 0; a < AIN; ++a) {
                float4 w4 = *(const float4*)(sW1 + (a<<4) + (sg<<2));
                ULL ws;
                PACK2(ws, w4.x); FMA2(a0a, apk[a][0], ws); FMA2(a0b, apk[a][1], ws);
                PACK2(ws, w4.y); FMA2(a1a, apk[a][0], ws); FMA2(a1b, apk[a][1], ws);
                PACK2(ws, w4.z); FMA2(a2a, apk[a][0], ws); FMA2(a2b, apk[a][1], ws);
                PACK2(ws, w4.w); FMA2(a3a, apk[a][0], ws); FMA2(a3b, apk[a][1], ws);
            }
            float4 rt0 = *(const float4*)(Rtb + (((sg<<2)+0) << 10));
            float4 rt1 = *(const float4*)(Rtb + (((sg<<2)+1) << 10));
            float4 rt2 = *(const float4*)(Rtb + (((sg<<2)+2) << 10));
            float4 rt3 = *(const float4*)(Rtb + (((sg<<2)+3) << 10));
            float v0,v1,v2,v3; float4 o;
            UNPACK2(v0,v1,a0a); UNPACK2(v2,v3,a0b);
            o.x=v0+rt0.x; o.y=v1+rt0.y; o.z=v2+rt0.z; o.w=v3+rt0.w;
            *(float4*)(outAt + obase + (((size_t)((sg<<2)+0)) << 20)) = o;
            UNPACK2(v0,v1,a1a); UNPACK2(v2,v3,a1b);
            o.x=v0+rt1.x; o.y=v1+rt1.y; o.z=v2+rt1.z; o.w=v3+rt1.w;
            *(float4*)(outAt + obase + (((size_t)((sg<<2)+1)) << 20)) = o;
            UNPACK2(v0,v1,a2a); UNPACK2(v2,v3,a2b);
            o.x=v0+rt2.x; o.y=v1+rt2.y; o.z=v2+rt2.z; o.w=v3+rt2.w;
            *(float4*)(outAt + obase + (((size_t)((sg<<2)+2)) << 20)) = o;
            UNPACK2(v0,v1,a3a); UNPACK2(v2,v3,a3b);
            o.x=v0+rt3.x; o.y=v1+rt3.y; o.z=v2+rt3.z; o.w=v3+rt3.w;
            *(float4*)(outAt + obase + (((size_t)((sg<<2)+3)) << 20)) = o;
        }
    }
}

// ---------------- K4: out = H*OWH/n + R*T/n + K + X1t ---------------------
#define SMEM_OUT ((512*64 + 16*512) * 4)

__global__ void __launch_bounds__(256) k_out(float* __restrict__ out2)
{
    extern __shared__ float dyn[];
    float* sOWH = dyn;            // 32768 floats
    float* sH   = dyn + 32768;    // 8192 floats
    int bx = blockIdx.x;          // 256 blocks x 16 nodes
    int n = bx >> 6, tid = threadIdx.x;
    {
        const float4* s4 = (const float4*)g_OWH;
        float4* d4 = (float4*)sOWH;
#pragma unroll
        for (int k = 0; k < 32; ++k) d4[(k<<8)+tid] = s4[(k<<8)+tid];
        const float4* h4 = (const float4*)(g_H + ((size_t)bx << 13));
        float4* dh = (float4*)sH;
#pragma unroll
        for (int k = 0; k < 8; ++k) dh[(k<<8)+tid] = h4[(k<<8)+tid];
    }
    __syncthreads();
    int r = tid >> 4, q = tid & 15, t0 = q << 2;
    int node = (bx << 4) + r;
    ULL acc01 = 0ull, acc23 = 0ull;
    const float* hrow = sH + (r << 9);
#pragma unroll 4
    for (int au = 0; au < 512; ++au) {
        ULL hs; PACK2(hs, hrow[au]);
        const ULL* wr = (const ULL*)(sOWH + (au << 6) + t0);
        FMA2(acc01, hs, wr[0]); FMA2(acc23, hs, wr[1]);
    }
    float a0,a1,a2,a3;
    UNPACK2(a0,a1,acc01); UNPACK2(a2,a3,acc23);
    const float* Tn = g_T + (n << 10);
    const float* Rn = g_R + ((size_t)node << 4);
#pragma unroll
    for (int s = 0; s < AOUT; ++s) {
        float rv = Rn[s];
        float4 tv = *(const float4*)(Tn + (s << 6) + t0);
        a0 = fmaf(rv, tv.x, a0); a1 = fmaf(rv, tv.y, a1);
        a2 = fmaf(rv, tv.z, a2); a3 = fmaf(rv, tv.w, a3);
    }
    const float sc = 1.f/1024.f;
    size_t ob = ((size_t)node << 6) + t0;
    float4 kv  = *(const float4*)(g_K + (n << 6) + t0);
    float4 x1v = *(const float4*)(g_X1t + ob);
    float4 o;
    o.x = a0*sc + kv.x + x1v.x;  o.y = a1*sc + kv.y + x1v.y;
    o.z = a2*sc + kv.z + x1v.z;  o.w = a3*sc + kv.w + x1v.w;
    *(float4*)(out2 + ob) = o;
}

// ---------------- launch ---------------------------------------------------
extern "C" void kernel_launch(void* const* d_in, const int* in_sizes, int n_in,
                              void* d_out, int out_size)
{
    const float* A     = (const float*)d_in[0];
    const float* X     = (const float*)d_in[1];
    const float* AW1   = (const float*)d_in[2];
    const float* AW2   = (const float*)d_in[3];
    const float* AW3   = (const float*)d_in[4];
    const float* AW4   = (const float*)d_in[5];
    const float* AW5   = (const float*)d_in[6];
    const float* AW6   = (const float*)d_in[7];
    const float* AW7   = (const float*)d_in[8];
    const float* Abias = (const float*)d_in[9];
    const float* X1W1  = (const float*)d_in[10];
    const float* X1W2  = (const float*)d_in[11];
    const float* X1W3  = (const float*)d_in[12];
    const float* X1W4  = (const float*)d_in[13];
    const float* X1W5  = (const float*)d_in[14];
    const float* X1W6  = (const float*)d_in[15];
    const float* X1b   = (const float*)d_in[16];
    const float* X2W1  = (const float*)d_in[17];
    const float* X2W2  = (const float*)d_in[18];
    const float* X2W3  = (const float*)d_in[19];
    const float* X2W4  = (const float*)d_in[20];
    const float* X2W5  = (const float*)d_in[21];
    const float* X2W6  = (const float*)d_in[22];
    const float* X2b   = (const float*)d_in[23];
    const float* OW    = (const float*)d_in[24];
    const float* outb  = (const float*)d_in[25];

    float* outAt = (float*)d_out;
    float* out2  = outAt + (size_t)NB * AOUT * NN * NN;

    cudaFuncSetAttribute(k_main, cudaFuncAttributeMaxDynamicSharedMemorySize, SMEM_MAINA);
    cudaFuncSetAttribute(k_out,  cudaFuncAttributeMaxDynamicSharedMemorySize, SMEM_OUT);

    // ncu captures the 4th launch -> k_h (tensor kernel) placed 4th
    k_reduce<<<NB*NN, 256>>>(A);
    k_pre_n <<<NB, 1024>>>(X, AW2, AW4, AW7, Abias);
    k_node  <<<NB*NN/16, 256>>>(X, AW3, AW5, AW6,
                            X1W1, X1W2, X1W3, X1W4, X1W5, X1W6, X1b,
                            X2W1, X2W2, X2W3, X2W4, X2W5, X2W6, X2b);
    k_h     <<<NB*AIN*16, 128>>>(A);
    k_main  <<<NB*NN, 256, SMEM_MAINA>>>(A, AW1, outAt);
    k_owh   <<<AIN, 256>>>(AW1, OW);
    k_q     <<<NB*16, 1024>>>();
    k_fin   <<<NB, 1024>>>(OW, outb);
    k_out   <<<NB*NN/16, 256, SMEM_OUT>>>(out2);
}

// round 10
// speedup vs baseline: 3.0067x; 1.0014x over previous
#include <cuda_runtime.h>
#include <cuda_bf16.h>
#include <cstdint>

#define NB 4
#define NN 1024
#define AIN 8
#define AOUT 16
#define XIN 64
#define XOUT 64

typedef unsigned long long ULL;

// ---------------- scratch (device globals; no allocation) ----------------
__device__ float g_moc[NB*NN*AIN];
__device__ float g_dp [NB*NN*AIN];
__device__ float g_mdp[NB*AIN];
__device__ float g_mall[NB*AIN];
__device__ float g_mX [NB*XIN];
__device__ float g_C  [NB*AOUT];
__device__ float g_R  [NB*NN*AOUT];
__device__ float g_Rt [NB*AOUT*NN];      // R transposed: [n][s][j]
__device__ float g_X1t[NB*NN*XOUT];
__device__ float g_X2t[NB*NN*XOUT];
__device__ __align__(16) __nv_bfloat16 g_X2tT_hi[NB*XOUT*NN];   // [n][t][j]
__device__ __align__(16) __nv_bfloat16 g_X2tT_lo[NB*XOUT*NN];   // [n][t][j]
__device__ float g_T  [NB*AOUT*XOUT];
__device__ float g_K  [NB*XOUT];
__device__ float g_OWH[AIN*XOUT*XOUT];
__device__ __align__(16) float g_H[NB*NN*AIN*XOUT];
__device__ float g_Qpart[NB*16*AOUT*XOUT];
__device__ float g_SX2part[NB*16*XOUT];

#define FMA2(d,a,b) asm("fma.rn.f32x2 %0, %1, %2, %0;" : "+l"(d) : "l"(a), "l"(b))
#define PACK2(d,x)  asm("mov.b64 %0, {%1, %1};" : "=l"(d) : "f"(x))
#define PACKXY(d,x,y) asm("mov.b64 %0, {%1, %2};" : "=l"(d) : "f"(x), "f"(y))
#define UNPACK2(lo,hi,d) asm("mov.b64 {%0, %1}, %2;" : "=f"(lo), "=f"(hi) : "l"(d))

#define LDSM_X4(r0,r1,r2,r3,addr) \
    asm volatile("ldmatrix.sync.aligned.m8n8.x4.shared.b16 {%0,%1,%2,%3}, [%4];" \
        : "=r"(r0),"=r"(r1),"=r"(r2),"=r"(r3) : "r"(addr))

#define MMA_BF16(c0,c1,c2,c3,a0,a1,a2,a3,b0,b1) \
    asm volatile("mma.sync.aligned.m16n8k16.row.col.f32.bf16.bf16.f32 " \
        "{%0,%1,%2,%3}, {%4,%5,%6,%7}, {%8,%9}, {%0,%1,%2,%3};" \
        : "+f"(c0),"+f"(c1),"+f"(c2),"+f"(c3) \
        : "r"(a0),"r"(a1),"r"(a2),"r"(a3), "r"(b0),"r"(b1))

__device__ __forceinline__ uint32_t smem_u32(const void* p) {
    uint32_t a;
    asm("{ .reg .u64 t; cvta.to.shared.u64 t, %1; cvt.u32.u64 %0, t; }" : "=r"(a) : "l"(p));
    return a;
}

// ---------------- K1: row reductions over A -> moc, dp -------------------
__global__ void __launch_bounds__(256) k_reduce(const float* __restrict__ A)
{
    int bx = blockIdx.x;            // bx = n*1024 + i
    int n = bx >> 10, i = bx & 1023;
    int w = threadIdx.x >> 5, l = threadIdx.x & 31;
    size_t row = ((size_t)(n*AIN + w) << 20) + ((size_t)i << 10);
    const float4* p = (const float4*)(A + row);
    float s = 0.f;
#pragma unroll
    for (int k = 0; k < 8; ++k) {
        float4 v = p[k*32 + l];
        s += v.x + v.y + v.z + v.w;
    }
#pragma unroll
    for (int o = 16; o; o >>= 1) s += __shfl_xor_sync(0xffffffffu, s, o);
    if (l == 0) {
        g_moc[(bx << 3) + w] = s * (1.f/1024.f);
        g_dp [(bx << 3) + w] = A[row + i];
    }
}

// ---------------- K_owh -----------------------------------------------------
__global__ void __launch_bounds__(256) k_owh(
    const float* __restrict__ AW1, const float* __restrict__ OW)
{
    int a = blockIdx.x, tid = threadIdx.x;
    __shared__ float sw[AOUT];
    if (tid < AOUT) sw[tid] = AW1[a*AOUT + tid];
    __syncthreads();
    for (int idx = tid; idx < 4096; idx += 256) {
        int u = idx >> 6, t = idx & 63;
        float s = 0.f;
#pragma unroll
        for (int ss = 0; ss < AOUT; ++ss)
            s = fmaf(sw[ss], OW[((ss<<6)+u)*64 + t], s);
        g_OWH[((a<<6)+u)*64 + t] = s;
    }
}

// ---------------- K2a: per-n means + C -----------------------------------
__global__ void __launch_bounds__(1024) k_pre_n(
    const float* __restrict__ X,
    const float* __restrict__ AW2, const float* __restrict__ AW4,
    const float* __restrict__ AW7, const float* __restrict__ Abias)
{
    int n = blockIdx.x, tid = threadIdx.x;
    __shared__ float spart[16][64];
    __shared__ float sdpp[128][8];
    __shared__ float salp[128][8];
    __shared__ float smx[XIN], smdp[AIN], smal[AIN];

    {
        int col = tid & 63, seg = tid >> 6;
        const float* xp = X + ((size_t)n << 16) + (size_t)(seg << 6) * XIN + col;
        float s = 0.f;
#pragma unroll 4
        for (int r = 0; r < 64; ++r) s += xp[(size_t)r * XIN];
        spart[seg][col] = s;
    }
    {
        int a = tid & 7, seg = tid >> 3;
        const float* dpp = g_dp  + (n << 13) + (seg << 6) + a;
        const float* mcp = g_moc + (n << 13) + (seg << 6) + a;
        float s1 = 0.f, s2 = 0.f;
#pragma unroll
        for (int r = 0; r < 8; ++r) { s1 += dpp[r*8]; s2 += mcp[r*8]; }
        sdpp[seg][a] = s1; salp[seg][a] = s2;
    }
    __syncthreads();
    if (tid < 64) {
        float s = 0.f;
#pragma unroll
        for (int k = 0; k < 16; ++k) s += spart[k][tid];
        smx[tid] = s * (1.f/1024.f);
        g_mX[n*XIN + tid] = smx[tid];
    } else if (tid >= 64 && tid < 72) {
        int a = tid - 64; float s = 0.f;
        for (int k = 0; k < 128; ++k) s += sdpp[k][a];
        smdp[a] = s * (1.f/1024.f); g_mdp[n*AIN + a] = smdp[a];
    } else if (tid >= 72 && tid < 80) {
        int a = tid - 72; float s = 0.f;
        for (int k = 0; k < 128; ++k) s += salp[k][a];
        smal[a] = s * (1.f/1024.f); g_mall[n*AIN + a] = smal[a];
    }
    __syncthreads();
    if (tid < AOUT) {
        int s16 = tid; float c = Abias[s16];
#pragma unroll
        for (int a = 0; a < AIN; ++a)
            c = fmaf(smal[a], AW2[a*AOUT+s16], fmaf(smdp[a], AW4[a*AOUT+s16], c));
        for (int k = 0; k < XIN; ++k) c = fmaf(smx[k], AW7[k*AOUT+s16], c);
        g_C[n*AOUT + s16] = c;
    }
}

// ---------------- K2b: per-node R, X1t, X2t (16 nodes/block) --------------
__global__ void __launch_bounds__(256) k_node(
    const float* __restrict__ X,
    const float* __restrict__ AW3, const float* __restrict__ AW5, const float* __restrict__ AW6,
    const float* __restrict__ X1W1, const float* __restrict__ X1W2, const float* __restrict__ X1W3,
    const float* __restrict__ X1W4, const float* __restrict__ X1W5, const float* __restrict__ X1W6,
    const float* __restrict__ X1b,
    const float* __restrict__ X2W1, const float* __restrict__ X2W2, const float* __restrict__ X2W3,
    const float* __restrict__ X2W4, const float* __restrict__ X2W5, const float* __restrict__ X2W6,
    const float* __restrict__ X2b)
{
    int bx = blockIdx.x;                 // 256 blocks x 16 nodes
    int tid = threadIdx.x;
    int nl = tid >> 4, q = tid & 15, t0 = q << 2;
    int node0 = bx << 4;
    int n = node0 >> 10;
    int node = node0 + nl;

    __shared__ float sx[16][64];
    __shared__ float smoc[16][8], sdpv[16][8];
    __shared__ float smx[64], smdp[8], smal[8];

    {
        const float4* xp = (const float4*)(X + ((size_t)node0 << 6));
        ((float4*)&sx[0][0])[tid] = xp[tid];
    }
    if (tid < 128) {
        ((float*)smoc)[tid] = g_moc[(node0<<3) + tid];
        ((float*)sdpv)[tid] = g_dp [(node0<<3) + tid];
    }
    if (tid >= 128 && tid < 192) smx[tid-128] = g_mX[(n<<6) + tid-128];
    if (tid >= 192 && tid < 200) smdp[tid-192] = g_mdp[(n<<3) + tid-192];
    if (tid >= 200 && tid < 208) smal[tid-200] = g_mall[(n<<3) + tid-200];
    __syncthreads();

    float4 b1 = *(const float4*)(X1b + t0);
    float4 b2 = *(const float4*)(X2b + t0);
    ULL x1a, x1b4, x2a, x2b4;
    PACKXY(x1a, b1.x, b1.y); PACKXY(x1b4, b1.z, b1.w);
    PACKXY(x2a, b2.x, b2.y); PACKXY(x2b4, b2.z, b2.w);

#pragma unroll 4
    for (int k = 0; k < XIN; ++k) {
        float xk = sx[nl][k], mk = smx[k];
        ULL xkp, mkp; PACK2(xkp, xk); PACK2(mkp, mk);
        float4 w; ULL wlo, whi;
        w = *(const float4*)(X1W1 + (k<<6) + t0);
        PACKXY(wlo, w.x, w.y); PACKXY(whi, w.z, w.w);
        FMA2(x1a, xkp, wlo); FMA2(x1b4, xkp, whi);
        w = *(const float4*)(X2W1 + (k<<6) + t0);
        PACKXY(wlo, w.x, w.y); PACKXY(whi, w.z, w.w);
        FMA2(x2a, xkp, wlo); FMA2(x2b4, xkp, whi);
        w = *(const float4*)(X1W2 + (k<<6) + t0);
        PACKXY(wlo, w.x, w.y); PACKXY(whi, w.z, w.w);
        FMA2(x1a, mkp, wlo); FMA2(x1b4, mkp, whi);
        w = *(const float4*)(X2W2 + (k<<6) + t0);
        PACKXY(wlo, w.x, w.y); PACKXY(whi, w.z, w.w);
        FMA2(x2a, mkp, wlo); FMA2(x2b4, mkp, whi);
    }
#pragma unroll
    for (int a = 0; a < AIN; ++a) {
        ULL v1, v2, v3, v4;
        PACK2(v1, smoc[nl][a]); PACK2(v2, sdpv[nl][a]);
        PACK2(v3, smdp[a]);     PACK2(v4, smal[a]);
        float4 w; ULL wlo, whi;
        w = *(const float4*)(X1W3 + (a<<6) + t0);
        PACKXY(wlo, w.x, w.y); PACKXY(whi, w.z, w.w);
        FMA2(x1a, v1, wlo); FMA2(x1b4, v1, whi);
        w = *(const float4*)(X2W3 + (a<<6) + t0);
        PACKXY(wlo, w.x, w.y); PACKXY(whi, w.z, w.w);
        FMA2(x2a, v1, wlo); FMA2(x2b4, v1, whi);
        w = *(const float4*)(X1W4 + (a<<6) + t0);
        PACKXY(wlo, w.x, w.y); PACKXY(whi, w.z, w.w);
        FMA2(x1a, v2, wlo); FMA2(x1b4, v2, whi);
        w = *(const float4*)(X2W4 + (a<<6) + t0);
        PACKXY(wlo, w.x, w.y); PACKXY(whi, w.z, w.w);
        FMA2(x2a, v2, wlo); FMA2(x2b4, v2, whi);
        w = *(const float4*)(X1W5 + (a<<6) + t0);
        PACKXY(wlo, w.x, w.y); PACKXY(whi, w.z, w.w);
        FMA2(x1a, v3, wlo); FMA2(x1b4, v3, whi);
        w = *(const float4*)(X2W5 + (a<<6) + t0);
        PACKXY(wlo, w.x, w.y); PACKXY(whi, w.z, w.w);
        FMA2(x2a, v3, wlo); FMA2(x2b4, v3, whi);
        w = *(const float4*)(X1W6 + (a<<6) + t0);
        PACKXY(wlo, w.x, w.y); PACKXY(whi, w.z, w.w);
        FMA2(x1a, v4, wlo); FMA2(x1b4, v4, whi);
        w = *(const float4*)(X2W6 + (a<<6) + t0);
        PACKXY(wlo, w.x, w.y); PACKXY(whi, w.z, w.w);
        FMA2(x2a, v4, wlo); FMA2(x2b4, v4, whi);
    }
    {
        float4 o1, o2;
        UNPACK2(o1.x, o1.y, x1a); UNPACK2(o1.z, o1.w, x1b4);
        UNPACK2(o2.x, o2.y, x2a); UNPACK2(o2.z, o2.w, x2b4);
        *(float4*)(g_X1t + ((size_t)node << 6) + t0) = o1;
        *(float4*)(g_X2t + ((size_t)node << 6) + t0) = o2;
        int jn = node & 1023;
        float v[4] = {o2.x, o2.y, o2.z, o2.w};
#pragma unroll
        for (int d = 0; d < 4; ++d) {
            __nv_bfloat16 h = __float2bfloat16_rn(v[d]);
            __nv_bfloat16 lo = __float2bfloat16_rn(v[d] - __bfloat162float(h));
            g_X2tT_hi[(n<<16) + ((t0+d)<<10) + jn] = h;
            g_X2tT_lo[(n<<16) + ((t0+d)<<10) + jn] = lo;
        }
    }
    {
        float r = 0.f;
#pragma unroll
        for (int a = 0; a < AIN; ++a) {
            r = fmaf(smoc[nl][a], AW3[a*AOUT+q], r);
            r = fmaf(sdpv[nl][a], AW5[a*AOUT+q], r);
        }
#pragma unroll 4
        for (int k = 0; k < XIN; ++k) r = fmaf(sx[nl][k], AW6[k*AOUT+q], r);
        g_R [((size_t)node << 4) + q] = r;
        g_Rt[(n << 14) + (q << 10) + (node & 1023)] = r;
    }
}

// ---------------- K_q: Q and SX2 partials ---------------------------------
__global__ void __launch_bounds__(1024) k_q()
{
    int bx = blockIdx.x;               // n*16 + seg
    int n = bx >> 4, seg = bx & 15;
    int tid = threadIdx.x;
    int s16 = tid >> 6, t = tid & 63;
    const float* rp = g_R   + ((size_t)n << 10) * AOUT + (size_t)(seg << 6) * AOUT;
    const float* xp = g_X2t + ((size_t)n << 10) * XOUT + (size_t)(seg << 6) * XOUT;
    float q = 0.f;
#pragma unroll 4
    for (int jj = 0; jj < 64; ++jj)
        q = fmaf(rp[jj*AOUT + s16], xp[jj*XOUT + t], q);
    g_Qpart[(size_t)bx * 1024 + tid] = q;
    if (tid < 64) {
        float s = 0.f;
#pragma unroll 4
        for (int jj = 0; jj < 64; ++jj) s += xp[jj*XOUT + tid];
        g_SX2part[bx*64 + tid] = s;
    }
}

// ---------------- K_fin: T, K ---------------------------------------------
__global__ void __launch_bounds__(1024) k_fin(
    const float* __restrict__ OW, const float* __restrict__ outb)
{
    int n = blockIdx.x, tid = threadIdx.x;
    __shared__ float sx2[XOUT];
    __shared__ float sq[AOUT*XOUT];
    __shared__ float st_[AOUT*XOUT];
    __shared__ float sp[AOUT*XOUT];
    {
        float q = 0.f;
#pragma unroll
        for (int seg = 0; seg < 16; ++seg)
            q += g_Qpart[(size_t)((n<<4)|seg) * 1024 + tid];
        sq[tid] = q;
    }
    if (tid < 64) {
        float s = 0.f;
#pragma unroll
        for (int seg = 0; seg < 16; ++seg) s += g_SX2part[((n<<4)|seg)*64 + tid];
        sx2[tid] = s;
    }
    __syncthreads();
    int s16 = tid >> 6, t = tid & 63;
    {
        float v = 0.f;
#pragma unroll 4
        for (int u = 0; u < 64; ++u)
            v = fmaf(sx2[u], OW[((s16<<6)+u)*64 + t], v);
        st_[tid] = v;
        g_T[n*1024 + tid] = v;
    }
    {
        float p = 0.f;
#pragma unroll 4
        for (int u = 0; u < 64; ++u)
            p = fmaf(sq[(s16<<6)+u], OW[(((s16<<6)+u)<<6) + t], p);
        sp[tid] = p;
    }
    __syncthreads();
    if (tid < 64) {
        int tt = tid;
        float qo = 0.f, ct = 0.f;
#pragma unroll
        for (int s = 0; s < AOUT; ++s) {
            qo += sp[(s<<6) + tt];
            ct = fmaf(g_C[n*AOUT + s], st_[(s<<6) + tt], ct);
        }
        g_K[n*XOUT + tt] = (ct + qo) * (1.f/1024.f) + outb[tt];
    }
}

// ---------------- K_h: H GEMM via mma.sync bf16 split (256 thr) ------------
// block = (n, a, mt): C[64 i x 64 t]; 8 warps: warp = 16 i-rows x 32 t.
#define AP 72           // row pitch in bf16 (144 B)
__global__ void __launch_bounds__(256) k_h(const float* __restrict__ A)
{
    __shared__ __align__(16) __nv_bfloat16 sAhi[64*AP], sAlo[64*AP];
    __shared__ __align__(16) __nv_bfloat16 sBhi[64*AP], sBlo[64*AP];
    uint32_t bAhi = smem_u32(sAhi), bAlo = smem_u32(sAlo);
    uint32_t bBhi = smem_u32(sBhi), bBlo = smem_u32(sBlo);

    int bx = blockIdx.x;
    int n = bx >> 7, a = (bx >> 4) & 7, mt = bx & 15;
    int tid = threadIdx.x, w = tid >> 5, l = tid & 31;

    const float* Ab = A + ((size_t)((n<<3) + a) << 20) + ((size_t)(mt << 6) << 10);
    const __nv_bfloat16* Bh = g_X2tT_hi + ((size_t)n << 16);
    const __nv_bfloat16* Bl = g_X2tT_lo + ((size_t)n << 16);

    float c[4][4];
#pragma unroll
    for (int q = 0; q < 4; ++q)
#pragma unroll
        for (int d = 0; d < 4; ++d) c[q][d] = 0.f;

    int blk = l >> 3, r8 = l & 7;
    // warp w: rows [(w>>1)*16, +16), t-offset (w&1)*32
    uint32_t aoff = (uint32_t)((((w >> 1) << 4) + ((blk & 1) << 3) + r8) * (AP*2)
                               + ((blk >> 1) << 4));
    int pbase = (w & 1) << 1;        // global 16-t tile index base

#pragma unroll 1
    for (int ch = 0; ch < 16; ++ch) {
        // stage A: 64 rows x 64 j fp32 -> bf16 hi/lo (1024 float4 / 256 thr)
#pragma unroll
        for (int k = 0; k < 4; ++k) {
            int g = tid + (k << 8);
            int row = g >> 4, u = g & 15;
            float4 v = *(const float4*)(Ab + ((size_t)row << 10) + (ch << 6) + (u << 2));
            __nv_bfloat162 h0 = __floats2bfloat162_rn(v.x, v.y);
            __nv_bfloat162 h1 = __floats2bfloat162_rn(v.z, v.w);
            __nv_bfloat162 l0 = __floats2bfloat162_rn(v.x - __bfloat162float(h0.x),
                                                      v.y - __bfloat162float(h0.y));
            __nv_bfloat162 l1 = __floats2bfloat162_rn(v.z - __bfloat162float(h1.x),
                                                      v.w - __bfloat162float(h1.y));
            uint32_t off = row*AP + (u << 2);
            *(__nv_bfloat162*)(sAhi + off)     = h0;
            *(__nv_bfloat162*)(sAhi + off + 2) = h1;
            *(__nv_bfloat162*)(sAlo + off)     = l0;
            *(__nv_bfloat162*)(sAlo + off + 2) = l1;
        }
        // stage B hi/lo: 64 t-rows x 64 j bf16 (512 uint4 each / 256 thr)
#pragma unroll
        for (int k = 0; k < 2; ++k) {
            int g = tid + (k << 8);
            int trow = g >> 3, u = g & 7;
            uint32_t off = trow*AP + (u << 3);
            *(uint4*)(sBhi + off) = *(const uint4*)(Bh + ((size_t)trow << 10) + (ch << 6) + (u << 3));
            *(uint4*)(sBlo + off) = *(const uint4*)(Bl + ((size_t)trow << 10) + (ch << 6) + (u << 3));
        }
        __syncthreads();

#pragma unroll
        for (int kt = 0; kt < 4; ++kt) {
            uint32_t ah0,ah1,ah2,ah3, al0,al1,al2,al3;
            LDSM_X4(ah0,ah1,ah2,ah3, bAhi + aoff + (kt << 5));
            LDSM_X4(al0,al1,al2,al3, bAlo + aoff + (kt << 5));
#pragma unroll
            for (int p = 0; p < 2; ++p) {
                int pg = pbase + p;
                uint32_t boff = (uint32_t)(((pg << 4) + ((blk >> 1) << 3) + r8) * (AP*2)
                                           + ((blk & 1) << 4)) + (kt << 5);
                uint32_t bh0,bh1,bh2,bh3, bl0,bl1,bl2,bl3;
                LDSM_X4(bh0,bh1,bh2,bh3, bBhi + boff);
                LDSM_X4(bl0,bl1,bl2,bl3, bBlo + boff);
                int q0 = 2*p, q1 = 2*p+1;
                MMA_BF16(c[q0][0],c[q0][1],c[q0][2],c[q0][3], ah0,ah1,ah2,ah3, bh0,bh1);
                MMA_BF16(c[q0][0],c[q0][1],c[q0][2],c[q0][3], ah0,ah1,ah2,ah3, bl0,bl1);
                MMA_BF16(c[q0][0],c[q0][1],c[q0][2],c[q0][3], al0,al1,al2,al3, bh0,bh1);
                MMA_BF16(c[q1][0],c[q1][1],c[q1][2],c[q1][3], ah0,ah1,ah2,ah3, bh2,bh3);
                MMA_BF16(c[q1][0],c[q1][1],c[q1][2],c[q1][3], ah0,ah1,ah2,ah3, bl2,bl3);
                MMA_BF16(c[q1][0],c[q1][1],c[q1][2],c[q1][3], al0,al1,al2,al3, bh2,bh3);
            }
        }
        __syncthreads();
    }

    // epilogue: warp rows (w>>1)*16, t = (w&1)*32 + q*8
    {
        int row0 = (mt << 6) + ((w >> 1) << 4) + (l >> 2);
        size_t nb = ((size_t)n << 10);
        float* H0 = g_H + ((nb + row0)     << 9) + (a << 6);
        float* H1 = g_H + ((nb + row0 + 8) << 9) + (a << 6);
        int tbase = (w & 1) << 5;
        int tc = (l & 3) << 1;
#pragma unroll
        for (int q = 0; q < 4; ++q) {
            int t = tbase + (q << 3) + tc;
            *(float2*)(H0 + t) = make_float2(c[q][0], c[q][1]);
            *(float2*)(H1 + t) = make_float2(c[q][2], c[q][3]);
        }
    }
}

// ---------------- K3: main — Phase A only, destaged (no smem A) ------------
__global__ void __launch_bounds__(256) k_main(
    const float* __restrict__ A, const float* __restrict__ AW1,
    float* __restrict__ outAt)
{
    __shared__ float sW1[128];
    __shared__ float sC16[16];

    int bx = blockIdx.x;                  // n*1024 + i
    int n = bx >> 10, i = bx & 1023;
    int tid = threadIdx.x;

    if (tid < 128) sW1[tid] = AW1[tid];
    if (tid < AOUT)
        sC16[tid] = g_R[((size_t)bx << 4) + tid] + g_C[(n<<4) + tid];
    __syncthreads();

    int j0 = tid << 2;
    ULL apk[8][2];
    {
        const float* Abase = A + (((size_t)(n<<3)) << 20) + ((size_t)i << 10) + j0;
#pragma unroll
        for (int a = 0; a < AIN; ++a) {
            const ULL* rp = (const ULL*)(Abase + ((size_t)a << 20));
            apk[a][0] = rp[0]; apk[a][1] = rp[1];
        }
    }
    size_t obase = (((size_t)(n<<4)) << 20) + ((size_t)i << 10) + j0;
    const float* Rtb = g_Rt + (n << 14) + j0;
#pragma unroll
    for (int sg = 0; sg < 4; ++sg) {
        float4 c4 = *(const float4*)(sC16 + (sg<<2));
        ULL a0a,a0b,a1a,a1b,a2a,a2b,a3a,a3b;
        PACK2(a0a, c4.x); a0b = a0a;
        PACK2(a1a, c4.y); a1b = a1a;
        PACK2(a2a, c4.z); a2b = a2a;
        PACK2(a3a, c4.w); a3b = a3a;
#pragma unroll
        for (int a = 0; a < AIN; ++a) {
            float4 w4 = *(const float4*)(sW1 + (a<<4) + (sg<<2));
            ULL ws;
            PACK2(ws, w4.x); FMA2(a0a, apk[a][0], ws); FMA2(a0b, apk[a][1], ws);
            PACK2(ws, w4.y); FMA2(a1a, apk[a][0], ws); FMA2(a1b, apk[a][1], ws);
            PACK2(ws, w4.z); FMA2(a2a, apk[a][0], ws); FMA2(a2b, apk[a][1], ws);
            PACK2(ws, w4.w); FMA2(a3a, apk[a][0], ws); FMA2(a3b, apk[a][1], ws);
        }
        float4 rt0 = *(const float4*)(Rtb + (((sg<<2)+0) << 10));
        float4 rt1 = *(const float4*)(Rtb + (((sg<<2)+1) << 10));
        float4 rt2 = *(const float4*)(Rtb + (((sg<<2)+2) << 10));
        float4 rt3 = *(const float4*)(Rtb + (((sg<<2)+3) << 10));
        float v0,v1,v2,v3; float4 o;
        UNPACK2(v0,v1,a0a); UNPACK2(v2,v3,a0b);
        o.x=v0+rt0.x; o.y=v1+rt0.y; o.z=v2+rt0.z; o.w=v3+rt0.w;
        *(float4*)(outAt + obase + (((size_t)((sg<<2)+0)) << 20)) = o;
        UNPACK2(v0,v1,a1a); UNPACK2(v2,v3,a1b);
        o.x=v0+rt1.x; o.y=v1+rt1.y; o.z=v2+rt1.z; o.w=v3+rt1.w;
        *(float4*)(outAt + obase + (((size_t)((sg<<2)+1)) << 20)) = o;
        UNPACK2(v0,v1,a2a); UNPACK2(v2,v3,a2b);
        o.x=v0+rt2.x; o.y=v1+rt2.y; o.z=v2+rt2.z; o.w=v3+rt2.w;
        *(float4*)(outAt + obase + (((size_t)((sg<<2)+2)) << 20)) = o;
        UNPACK2(v0,v1,a3a); UNPACK2(v2,v3,a3b);
        o.x=v0+rt3.x; o.y=v1+rt3.y; o.z=v2+rt3.z; o.w=v3+rt3.w;
        *(float4*)(outAt + obase + (((size_t)((sg<<2)+3)) << 20)) = o;
    }
}

// ---------------- K4: out = H*OWH/n + R*T/n + K + X1t ---------------------
#define SMEM_OUT ((512*64 + 16*512) * 4)

__global__ void __launch_bounds__(256) k_out(float* __restrict__ out2)
{
    extern __shared__ float dyn[];
    float* sOWH = dyn;            // 32768 floats
    float* sH   = dyn + 32768;    // 8192 floats
    int bx = blockIdx.x;          // 256 blocks x 16 nodes
    int n = bx >> 6, tid = threadIdx.x;
    {
        const float4* s4 = (const float4*)g_OWH;
        float4* d4 = (float4*)sOWH;
#pragma unroll
        for (int k = 0; k < 32; ++k) d4[(k<<8)+tid] = s4[(k<<8)+tid];
        const float4* h4 = (const float4*)(g_H + ((size_t)bx << 13));
        float4* dh = (float4*)sH;
#pragma unroll
        for (int k = 0; k < 8; ++k) dh[(k<<8)+tid] = h4[(k<<8)+tid];
    }
    __syncthreads();
    int r = tid >> 4, q = tid & 15, t0 = q << 2;
    int node = (bx << 4) + r;
    ULL acc01 = 0ull, acc23 = 0ull;
    const float* hrow = sH + (r << 9);
#pragma unroll 4
    for (int au = 0; au < 512; ++au) {
        ULL hs; PACK2(hs, hrow[au]);
        const ULL* wr = (const ULL*)(sOWH + (au << 6) + t0);
        FMA2(acc01, hs, wr[0]); FMA2(acc23, hs, wr[1]);
    }
    float a0,a1,a2,a3;
    UNPACK2(a0,a1,acc01); UNPACK2(a2,a3,acc23);
    const float* Tn = g_T + (n << 10);
    const float* Rn = g_R + ((size_t)node << 4);
#pragma unroll
    for (int s = 0; s < AOUT; ++s) {
        float rv = Rn[s];
        float4 tv = *(const float4*)(Tn + (s << 6) + t0);
        a0 = fmaf(rv, tv.x, a0); a1 = fmaf(rv, tv.y, a1);
        a2 = fmaf(rv, tv.z, a2); a3 = fmaf(rv, tv.w, a3);
    }
    const float sc = 1.f/1024.f;
    size_t ob = ((size_t)node << 6) + t0;
    float4 kv  = *(const float4*)(g_K + (n << 6) + t0);
    float4 x1v = *(const float4*)(g_X1t + ob);
    float4 o;
    o.x = a0*sc + kv.x + x1v.x;  o.y = a1*sc + kv.y + x1v.y;
    o.z = a2*sc + kv.z + x1v.z;  o.w = a3*sc + kv.w + x1v.w;
    *(float4*)(out2 + ob) = o;
}

// ---------------- launch ---------------------------------------------------
extern "C" void kernel_launch(void* const* d_in, const int* in_sizes, int n_in,
                              void* d_out, int out_size)
{
    const float* A     = (const float*)d_in[0];
    const float* X     = (const float*)d_in[1];
    const float* AW1   = (const float*)d_in[2];
    const float* AW2   = (const float*)d_in[3];
    const float* AW3   = (const float*)d_in[4];
    const float* AW4   = (const float*)d_in[5];
    const float* AW5   = (const float*)d_in[6];
    const float* AW6   = (const float*)d_in[7];
    const float* AW7   = (const float*)d_in[8];
    const float* Abias = (const float*)d_in[9];
    const float* X1W1  = (const float*)d_in[10];
    const float* X1W2  = (const float*)d_in[11];
    const float* X1W3  = (const float*)d_in[12];
    const float* X1W4  = (const float*)d_in[13];
    const float* X1W5  = (const float*)d_in[14];
    const float* X1W6  = (const float*)d_in[15];
    const float* X1b   = (const float*)d_in[16];
    const float* X2W1  = (const float*)d_in[17];
    const float* X2W2  = (const float*)d_in[18];
    const float* X2W3  = (const float*)d_in[19];
    const float* X2W4  = (const float*)d_in[20];
    const float* X2W5  = (const float*)d_in[21];
    const float* X2W6  = (const float*)d_in[22];
    const float* X2b   = (const float*)d_in[23];
    const float* OW    = (const float*)d_in[24];
    const float* outb  = (const float*)d_in[25];

    float* outAt = (float*)d_out;
    float* out2  = outAt + (size_t)NB * AOUT * NN * NN;

    cudaFuncSetAttribute(k_out, cudaFuncAttributeMaxDynamicSharedMemorySize, SMEM_OUT);

    // ncu captures the 4th launch -> k_main (Phase A) placed 4th
    k_reduce<<<NB*NN, 256>>>(A);
    k_pre_n <<<NB, 1024>>>(X, AW2, AW4, AW7, Abias);
    k_node  <<<NB*NN/16, 256>>>(X, AW3, AW5, AW6,
                            X1W1, X1W2, X1W3, X1W4, X1W5, X1W6, X1b,
                            X2W1, X2W2, X2W3, X2W4, X2W5, X2W6, X2b);
    k_main  <<<NB*NN, 256>>>(A, AW1, outAt);
    k_h     <<<NB*AIN*16, 256>>>(A);
    k_owh   <<<AIN, 256>>>(AW1, OW);
    k_q     <<<NB*16, 1024>>>();
    k_fin   <<<NB, 1024>>>(OW, outb);
    k_out   <<<NB*NN/16, 256, SMEM_OUT>>>(out2);
}